// round 1
// baseline (speedup 1.0000x reference)
#include <cuda_runtime.h>
#include <math.h>

#define MROWS 131072        // 2048 windows * 64 tokens
#define NWIN  2048
#define D1    257
#define DIMV  256
#define SCALE 0.17677669529663687f   // 32^-0.5

// ---------------- scratch (device globals: allocation-free) ----------------
__device__ float g_qv[(size_t)MROWS * DIMV];
__device__ float g_kv[(size_t)MROWS * DIMV];
__device__ float g_vv[(size_t)MROWS * DIMV];
__device__ float g_ov[(size_t)MROWS * DIMV];
__device__ float g_qd[MROWS];
__device__ float g_kd[MROWS];
__device__ float g_vd[MROWS];
__device__ float g_od[MROWS];

// ---------------- projection GEMM: O[M,256] = X[M,257] @ W[257,256] * scale ----
__global__ void __launch_bounds__(256) proj_gemm(
    const float* __restrict__ X, const float* __restrict__ W,
    float* __restrict__ O, float scale)
{
    __shared__ __align__(16) float As[16][68];   // [k][m], padded
    __shared__ __align__(16) float Bs[16][64];   // [k][n]
    const int tid = threadIdx.x;
    const int tm = (tid >> 4) << 2;
    const int tn = (tid & 15) << 2;
    const float* Xb = X + (size_t)blockIdx.x * 64 * D1;
    const int ncol0 = blockIdx.y * 64;
    float acc[4][4] = {};

    for (int k0 = 0; k0 < D1; k0 += 16) {
        #pragma unroll
        for (int i = 0; i < 4; i++) {
            int idx = tid + i * 256;
            int r = idx >> 4, c = idx & 15;
            int k = k0 + c;
            As[c][r] = (k < D1) ? Xb[(size_t)r * D1 + k] : 0.f;
        }
        #pragma unroll
        for (int i = 0; i < 4; i++) {
            int idx = tid + i * 256;
            int r = idx >> 6, c = idx & 63;
            int k = k0 + r;
            Bs[r][c] = (k < D1) ? W[(size_t)k * DIMV + ncol0 + c] : 0.f;
        }
        __syncthreads();
        #pragma unroll
        for (int k = 0; k < 16; k++) {
            float4 a4 = *reinterpret_cast<const float4*>(&As[k][tm]);
            float4 b4 = *reinterpret_cast<const float4*>(&Bs[k][tn]);
            float a[4] = {a4.x, a4.y, a4.z, a4.w};
            float b[4] = {b4.x, b4.y, b4.z, b4.w};
            #pragma unroll
            for (int i = 0; i < 4; i++)
                #pragma unroll
                for (int j = 0; j < 4; j++)
                    acc[i][j] = fmaf(a[i], b[j], acc[i][j]);
        }
        __syncthreads();
    }
    #pragma unroll
    for (int i = 0; i < 4; i++) {
        size_t m = (size_t)blockIdx.x * 64 + tm + i;
        float4 o;
        o.x = acc[i][0] * scale;
        o.y = acc[i][1] * scale;
        o.z = acc[i][2] * scale;
        o.w = acc[i][3] * scale;
        *reinterpret_cast<float4*>(&O[m * DIMV + ncol0 + tn]) = o;
    }
}

// ---------------- depth projections: warp per row, dot over 257 --------------
__global__ void __launch_bounds__(256) dproj(
    const float* __restrict__ X,
    const float* __restrict__ Wq, const float* __restrict__ Wk,
    const float* __restrict__ Wv,
    float* __restrict__ qd, float* __restrict__ kd, float* __restrict__ vd)
{
    const int warp = threadIdx.x >> 5;
    const int lane = threadIdx.x & 31;
    const size_t row = (size_t)blockIdx.x * 8 + warp;
    const float* xr = X + row * D1;
    float sq = 0.f, sk = 0.f, sv = 0.f;
    for (int c = lane; c < D1; c += 32) {
        float xv = xr[c];
        sq = fmaf(xv, Wq[c], sq);
        sk = fmaf(xv, Wk[c], sk);
        sv = fmaf(xv, Wv[c], sv);
    }
    #pragma unroll
    for (int o = 16; o > 0; o >>= 1) {
        sq += __shfl_down_sync(0xffffffffu, sq, o);
        sk += __shfl_down_sync(0xffffffffu, sk, o);
        sv += __shfl_down_sync(0xffffffffu, sv, o);
    }
    if (lane == 0) {
        qd[row] = sq * SCALE;
        kd[row] = sk;
        vd[row] = sv;
    }
}

// ---------------- fused windowed attention: one block per window -------------
// smem layout (floats): sqT[32*65] skT[32*65] sv[64*32] gate[64*65] ssum[64*65] sc[64*65]
#define SMEM_ATTN_FLOATS (32*65 + 32*65 + 64*32 + 64*65 + 64*65 + 64*65)
__global__ void __launch_bounds__(256) attn_kernel(
    const float* __restrict__ qv, const float* __restrict__ kv,
    const float* __restrict__ vv,
    const float* __restrict__ qd, const float* __restrict__ kd,
    const float* __restrict__ vd,
    float* __restrict__ ov, float* __restrict__ od)
{
    extern __shared__ float smem[];
    float* sqT  = smem;               // [d][i] stride 65
    float* skT  = sqT + 32 * 65;      // [d][j] stride 65
    float* sv   = skT + 32 * 65;      // [j][d] stride 32
    float* gate = sv + 64 * 32;       // [i][j] stride 65
    float* ssum = gate + 64 * 65;     // [i][j] stride 65
    float* sc   = ssum + 64 * 65;     // [i][j] stride 65
    __shared__ float s_qd[64], s_kd[64], s_vd[64];

    const int tid = threadIdx.x;
    const size_t row0 = (size_t)blockIdx.x * 64;

    if (tid < 64) {
        s_qd[tid] = qd[row0 + tid];
        s_kd[tid] = kd[row0 + tid];
        s_vd[tid] = vd[row0 + tid];
    }
    __syncthreads();

    for (int idx = tid; idx < 4096; idx += 256) {
        int i = idx >> 6, j = idx & 63;
        float z = s_qd[i] * s_kd[j];
        gate[i * 65 + j] = 1.f / (1.f + __expf(-z));
        ssum[i * 65 + j] = 0.f;
    }

    const int tm = (tid >> 4) << 2;
    const int tn = (tid & 15) << 2;

    for (int h = 0; h < 8; h++) {
        __syncthreads();  // protect smem reuse across heads
        for (int idx = tid; idx < 2048; idx += 256) {
            int i = idx >> 5, d = idx & 31;
            size_t g = (row0 + i) * 256 + h * 32 + d;
            sqT[d * 65 + i] = qv[g];
            skT[d * 65 + i] = kv[g];
            sv[i * 32 + d]  = vv[g];
        }
        __syncthreads();

        // scores: 4x4 tile per thread, q already pre-scaled
        float acc[4][4] = {};
        #pragma unroll 4
        for (int d = 0; d < 32; d++) {
            float a[4], b[4];
            #pragma unroll
            for (int i = 0; i < 4; i++) a[i] = sqT[d * 65 + tm + i];
            #pragma unroll
            for (int j = 0; j < 4; j++) b[j] = skT[d * 65 + tn + j];
            #pragma unroll
            for (int i = 0; i < 4; i++)
                #pragma unroll
                for (int j = 0; j < 4; j++)
                    acc[i][j] = fmaf(a[i], b[j], acc[i][j]);
        }
        #pragma unroll
        for (int i = 0; i < 4; i++)
            #pragma unroll
            for (int j = 0; j < 4; j++) {
                int o = (tm + i) * 65 + tn + j;
                float smv = acc[i][j] * gate[o];
                sc[o] = smv;
                ssum[o] += smv;   // each (i,j) owned by exactly one thread
            }
        __syncthreads();

        // per-row softmax (stride-65 rows are bank-conflict-free across lanes)
        if (tid < 64) {
            float m = -1e30f;
            #pragma unroll 8
            for (int j = 0; j < 64; j++) m = fmaxf(m, sc[tid * 65 + j]);
            float s = 0.f;
            #pragma unroll 8
            for (int j = 0; j < 64; j++) {
                float e = __expf(sc[tid * 65 + j] - m);
                sc[tid * 65 + j] = e;
                s += e;
            }
            float inv = 1.f / s;
            #pragma unroll 8
            for (int j = 0; j < 64; j++) sc[tid * 65 + j] *= inv;
        }
        __syncthreads();

        // PV: thread -> (row i, 8 contiguous dims)
        {
            const int i  = tid >> 2;
            const int d0 = (tid & 3) << 3;
            float a8[8] = {};
            #pragma unroll 4
            for (int j = 0; j < 64; j++) {
                float p = sc[i * 65 + j];
                float4 v0 = *reinterpret_cast<const float4*>(&sv[j * 32 + d0]);
                float4 v1 = *reinterpret_cast<const float4*>(&sv[j * 32 + d0 + 4]);
                a8[0] = fmaf(p, v0.x, a8[0]); a8[1] = fmaf(p, v0.y, a8[1]);
                a8[2] = fmaf(p, v0.z, a8[2]); a8[3] = fmaf(p, v0.w, a8[3]);
                a8[4] = fmaf(p, v1.x, a8[4]); a8[5] = fmaf(p, v1.y, a8[5]);
                a8[6] = fmaf(p, v1.z, a8[6]); a8[7] = fmaf(p, v1.w, a8[7]);
            }
            size_t gb = (row0 + i) * 256 + h * 32 + d0;
            float4 w0 = {a8[0], a8[1], a8[2], a8[3]};
            float4 w1 = {a8[4], a8[5], a8[6], a8[7]};
            *reinterpret_cast<float4*>(&ov[gb])     = w0;
            *reinterpret_cast<float4*>(&ov[gb + 4]) = w1;
        }
    }

    __syncthreads();
    // depth attention: softmax of summed gated scores, dotted with vd
    if (tid < 64) {
        float m = -1e30f;
        #pragma unroll 8
        for (int j = 0; j < 64; j++) m = fmaxf(m, ssum[tid * 65 + j]);
        float s = 0.f, acc = 0.f;
        #pragma unroll 8
        for (int j = 0; j < 64; j++) {
            float e = __expf(ssum[tid * 65 + j] - m);
            s += e;
            acc = fmaf(e, s_vd[j], acc);
        }
        od[row0 + tid] = acc / s;
    }
}

// ---------------- output GEMM: out[M,257] = OV[M,256] @ Wout[0:256,:] + od⊗Wout[256,:]
__global__ void __launch_bounds__(256) out_gemm(
    const float* __restrict__ A, const float* __restrict__ Wout,
    const float* __restrict__ od, float* __restrict__ out)
{
    __shared__ __align__(16) float As[16][68];
    __shared__ __align__(16) float Bs[16][64];
    const int tid = threadIdx.x;
    const int tm = (tid >> 4) << 2;
    const int tn = (tid & 15) << 2;
    const float* Ab = A + (size_t)blockIdx.x * 64 * DIMV;
    const int ncol0 = blockIdx.y * 64;
    float acc[4][4] = {};

    for (int k0 = 0; k0 < DIMV; k0 += 16) {
        #pragma unroll
        for (int i = 0; i < 4; i++) {
            int idx = tid + i * 256;
            int r = idx >> 4, c = idx & 15;
            As[c][r] = Ab[(size_t)r * DIMV + k0 + c];
        }
        #pragma unroll
        for (int i = 0; i < 4; i++) {
            int idx = tid + i * 256;
            int r = idx >> 6, c = idx & 63;
            int n = ncol0 + c;
            Bs[r][c] = (n < D1) ? Wout[(size_t)(k0 + r) * D1 + n] : 0.f;
        }
        __syncthreads();
        #pragma unroll
        for (int k = 0; k < 16; k++) {
            float4 a4 = *reinterpret_cast<const float4*>(&As[k][tm]);
            float4 b4 = *reinterpret_cast<const float4*>(&Bs[k][tn]);
            float a[4] = {a4.x, a4.y, a4.z, a4.w};
            float b[4] = {b4.x, b4.y, b4.z, b4.w};
            #pragma unroll
            for (int i = 0; i < 4; i++)
                #pragma unroll
                for (int j = 0; j < 4; j++)
                    acc[i][j] = fmaf(a[i], b[j], acc[i][j]);
        }
        __syncthreads();
    }
    const float* wlast = Wout + (size_t)DIMV * D1;   // row 256 of Wout
    #pragma unroll
    for (int i = 0; i < 4; i++) {
        size_t m = (size_t)blockIdx.x * 64 + tm + i;
        float odv = od[m];
        #pragma unroll
        for (int j = 0; j < 4; j++) {
            int n = ncol0 + tn + j;
            if (n < D1) out[m * D1 + n] = fmaf(odv, wlast[n], acc[i][j]);
        }
    }
}

// ---------------- launch -----------------------------------------------------
extern "C" void kernel_launch(void* const* d_in, const int* in_sizes, int n_in,
                              void* d_out, int out_size)
{
    const float* x    = (const float*)d_in[0];
    const float* Wqv  = (const float*)d_in[1];
    const float* Wkv  = (const float*)d_in[2];
    const float* Wvv  = (const float*)d_in[3];
    const float* Wqd  = (const float*)d_in[4];
    const float* Wkd  = (const float*)d_in[5];
    const float* Wvd  = (const float*)d_in[6];
    const float* Wout = (const float*)d_in[7];
    float* out = (float*)d_out;

    float *qv, *kv, *vv, *ov, *qd, *kd, *vd, *od;
    cudaGetSymbolAddress((void**)&qv, g_qv);
    cudaGetSymbolAddress((void**)&kv, g_kv);
    cudaGetSymbolAddress((void**)&vv, g_vv);
    cudaGetSymbolAddress((void**)&ov, g_ov);
    cudaGetSymbolAddress((void**)&qd, g_qd);
    cudaGetSymbolAddress((void**)&kd, g_kd);
    cudaGetSymbolAddress((void**)&vd, g_vd);
    cudaGetSymbolAddress((void**)&od, g_od);

    const int attn_smem = SMEM_ATTN_FLOATS * (int)sizeof(float);
    cudaFuncSetAttribute(attn_kernel,
                         cudaFuncAttributeMaxDynamicSharedMemorySize, attn_smem);

    dim3 gproj(MROWS / 64, DIMV / 64);
    proj_gemm<<<gproj, 256>>>(x, Wqv, qv, SCALE);
    proj_gemm<<<gproj, 256>>>(x, Wkv, kv, 1.0f);
    proj_gemm<<<gproj, 256>>>(x, Wvv, vv, 1.0f);
    dproj<<<MROWS / 8, 256>>>(x, Wqd, Wkd, Wvd, qd, kd, vd);
    attn_kernel<<<NWIN, 256, attn_smem>>>(qv, kv, vv, qd, kd, vd, ov, od);
    out_gemm<<<dim3(MROWS / 64, 5), 256>>>(ov, Wout, od, out);
}

// round 3
// speedup vs baseline: 1.9647x; 1.9647x over previous
#include <cuda_runtime.h>
#include <cuda_bf16.h>
#include <cstdint>
#include <math.h>

#define MROWS 131072        // 2048 windows * 64 tokens
#define NWIN  2048
#define D1    257
#define DIMV  256
#define KPAD  288           // 257 padded to 9 chunks of 32
#define KITERS 9
#define SCALE 0.17677669529663687f   // 32^-0.5

// ======================= scratch (device globals) ===========================
__device__ __align__(256) __nv_bfloat16 g_Ah[(size_t)MROWS * KPAD];
__device__ __align__(256) __nv_bfloat16 g_Al[(size_t)MROWS * KPAD];
__device__ __align__(256) __nv_bfloat16 g_Bh[768 * KPAD];
__device__ __align__(256) __nv_bfloat16 g_Bl[768 * KPAD];
__device__ __align__(256) __nv_bfloat16 g_BoH[256 * KPAD];
__device__ __align__(256) __nv_bfloat16 g_BoL[256 * KPAD];
__device__ float g_qv[(size_t)MROWS * DIMV];
__device__ float g_kv[(size_t)MROWS * DIMV];
__device__ float g_vv[(size_t)MROWS * DIMV];
__device__ float g_ov[(size_t)MROWS * DIMV];
__device__ float g_qd[MROWS];
__device__ float g_kd[MROWS];
__device__ float g_vd[MROWS];
__device__ float g_od[MROWS];

// ======================= PTX helpers =========================================
__device__ __forceinline__ uint32_t smem_u32(const void* p) {
    uint32_t a;
    asm("{ .reg .u64 t; cvta.to.shared.u64 t, %1; cvt.u32.u64 %0, t; }"
        : "=r"(a) : "l"(p));
    return a;
}
__device__ __forceinline__ void cp16(uint32_t s, const void* g) {
    asm volatile("cp.async.ca.shared.global [%0], [%1], 16;" :: "r"(s), "l"(g));
}
#define CP_COMMIT()  asm volatile("cp.async.commit_group;" ::: "memory")
#define CP_WAIT(n)   asm volatile("cp.async.wait_group %0;" :: "n"(n) : "memory")

#define LDSM4(r, addr) \
    asm volatile("ldmatrix.sync.aligned.m8n8.x4.shared.b16 {%0,%1,%2,%3}, [%4];" \
        : "=r"((r)[0]), "=r"((r)[1]), "=r"((r)[2]), "=r"((r)[3]) : "r"(addr))

#define MMA16816(c, a, b0v, b1v) \
    asm volatile("mma.sync.aligned.m16n8k16.row.col.f32.bf16.bf16.f32 " \
        "{%0,%1,%2,%3}, {%4,%5,%6,%7}, {%8,%9}, {%0,%1,%2,%3};" \
        : "+f"((c)[0]), "+f"((c)[1]), "+f"((c)[2]), "+f"((c)[3]) \
        : "r"((a)[0]), "r"((a)[1]), "r"((a)[2]), "r"((a)[3]), "r"(b0v), "r"(b1v))

// ============ conv_x + depth projections (warp per row) =====================
__global__ void __launch_bounds__(256) conv_x_dproj(
    const float* __restrict__ X,
    const float* __restrict__ Wq, const float* __restrict__ Wk,
    const float* __restrict__ Wv,
    __nv_bfloat16* __restrict__ Ah, __nv_bfloat16* __restrict__ Al,
    float* __restrict__ qd, float* __restrict__ kd, float* __restrict__ vd)
{
    const int warp = threadIdx.x >> 5;
    const int lane = threadIdx.x & 31;
    const size_t r = (size_t)blockIdx.x * 8 + warp;
    const float* xr = X + r * D1;
    float sq = 0.f, sk = 0.f, sv = 0.f;
    #pragma unroll
    for (int i = 0; i < 9; i++) {
        int c = lane + i * 32;
        float v = (c < D1) ? xr[c] : 0.f;
        __nv_bfloat16 h = __float2bfloat16(v);
        __nv_bfloat16 l = __float2bfloat16(v - __bfloat162float(h));
        Ah[r * KPAD + c] = h;
        Al[r * KPAD + c] = l;
        if (c < D1) {
            sq = fmaf(v, Wq[c], sq);
            sk = fmaf(v, Wk[c], sk);
            sv = fmaf(v, Wv[c], sv);
        }
    }
    #pragma unroll
    for (int o = 16; o > 0; o >>= 1) {
        sq += __shfl_down_sync(0xffffffffu, sq, o);
        sk += __shfl_down_sync(0xffffffffu, sk, o);
        sv += __shfl_down_sync(0xffffffffu, sv, o);
    }
    if (lane == 0) { qd[r] = sq * SCALE; kd[r] = sk; vd[r] = sv; }
}

// ============ QKV weight transpose+split: B[n,k] = W[k, n%256] ==============
__global__ void __launch_bounds__(256) conv_w_qkv(
    const float* __restrict__ Wqv, const float* __restrict__ Wkv,
    const float* __restrict__ Wvv,
    __nv_bfloat16* __restrict__ Bh, __nv_bfloat16* __restrict__ Bl)
{
    int idx = blockIdx.x * 256 + threadIdx.x;   // 768*288 total
    int n = idx / KPAD, k = idx % KPAD;
    const float* W = (n < 256) ? Wqv : (n < 512) ? Wkv : Wvv;
    float v = (k < D1) ? W[(size_t)k * DIMV + (n & 255)] : 0.f;
    __nv_bfloat16 h = __float2bfloat16(v);
    Bh[idx] = h;
    Bl[idx] = __float2bfloat16(v - __bfloat162float(h));
}

// ============ Wout transpose+split: B[n,k] = Wout[k, n] =====================
__global__ void __launch_bounds__(256) conv_w_out(
    const float* __restrict__ Wout,
    __nv_bfloat16* __restrict__ Bh, __nv_bfloat16* __restrict__ Bl)
{
    int idx = blockIdx.x * 256 + threadIdx.x;   // 256*288 total
    int n = idx / KPAD, k = idx % KPAD;
    float v = (k < D1) ? Wout[(size_t)k * D1 + n] : 0.f;
    __nv_bfloat16 h = __float2bfloat16(v);
    Bh[idx] = h;
    Bl[idx] = __float2bfloat16(v - __bfloat162float(h));
}

// ============ ov+od -> bf16 split + out[:,256] dot ==========================
__global__ void __launch_bounds__(256) conv_ov(
    const float* __restrict__ ov, const float* __restrict__ od,
    const float* __restrict__ Wout,
    __nv_bfloat16* __restrict__ Ah, __nv_bfloat16* __restrict__ Al,
    float* __restrict__ out)
{
    const int warp = threadIdx.x >> 5;
    const int lane = threadIdx.x & 31;
    const size_t r = (size_t)blockIdx.x * 8 + warp;
    float s = 0.f;
    #pragma unroll
    for (int i = 0; i < 9; i++) {
        int c = lane + i * 32;
        float v = 0.f;
        if (c < 256)       v = ov[r * 256 + c];
        else if (c == 256) v = od[r];
        __nv_bfloat16 h = __float2bfloat16(v);
        __nv_bfloat16 l = __float2bfloat16(v - __bfloat162float(h));
        Ah[r * KPAD + c] = h;
        Al[r * KPAD + c] = l;
        if (c < D1) s = fmaf(v, Wout[(size_t)c * D1 + 256], s);
    }
    #pragma unroll
    for (int o = 16; o > 0; o >>= 1) s += __shfl_down_sync(0xffffffffu, s, o);
    if (lane == 0) out[r * D1 + 256] = s;
}

// ============ split-bf16 HMMA GEMM: BM=128 BN=128 BK=32, cp.async 2-stage ===
#define BM 128
#define BN 128
#define BK 32
#define SPITCH 40                          // bf16 per smem row (padded)
#define MAT_BYTES (BM * SPITCH * 2)        // 10240
#define STAGE_BYTES (4 * MAT_BYTES)        // 40960
#define GEMM_SMEM (2 * STAGE_BYTES)        // 81920

__global__ void __launch_bounds__(256, 1) gemm_mma(
    const __nv_bfloat16* __restrict__ Ah, const __nv_bfloat16* __restrict__ Al,
    const __nv_bfloat16* __restrict__ Bh, const __nv_bfloat16* __restrict__ Bl,
    float* __restrict__ o0, float* __restrict__ o1, float* __restrict__ o2,
    float s0, float s1, float s2, int pitch)
{
    extern __shared__ char sm[];
    const int tid  = threadIdx.x;
    const int lane = tid & 31;
    const int wid  = tid >> 5;
    const int wm   = wid >> 2;             // 0..1
    const int wn   = wid & 3;              // 0..3
    const int nblk = blockIdx.x;
    const size_t m0 = (size_t)blockIdx.y * BM;
    const int sel = nblk >> 1;
    float* o = (sel == 0) ? o0 : (sel == 1) ? o1 : o2;
    const float scale = (sel == 0) ? s0 : (sel == 1) ? s1 : s2;
    const int ncol0 = (nblk & 1) * BN;
    const uint32_t sbase = smem_u32(sm);

    const __nv_bfloat16* Bh_b = Bh + (size_t)nblk * BN * KPAD;
    const __nv_bfloat16* Bl_b = Bl + (size_t)nblk * BN * KPAD;

    // per-thread cp.async assignment (8 x 16B chunks / thread / stage)
    // id = tid + t*256 in [0,2048): mat = id>>9 (Ah,Al,Bh,Bl), i = id&511,
    // row = i>>2 (0..127), c = i&3 (16B chunk within 64B row segment)
    auto load_stage = [&](int it, int buf) {
        const int kc = it * BK;
        #pragma unroll
        for (int t = 0; t < 8; t++) {
            int id = tid + t * 256;
            int mat = id >> 9;
            int i = id & 511;
            int row = i >> 2, c = i & 3;
            const __nv_bfloat16* g;
            if      (mat == 0) g = Ah   + (m0 + row) * KPAD + kc + c * 8;
            else if (mat == 1) g = Al   + (m0 + row) * KPAD + kc + c * 8;
            else if (mat == 2) g = Bh_b + (size_t)row * KPAD + kc + c * 8;
            else               g = Bl_b + (size_t)row * KPAD + kc + c * 8;
            uint32_t s = sbase + buf * STAGE_BYTES + mat * MAT_BYTES
                       + (uint32_t)(row * SPITCH + c * 8) * 2;
            cp16(s, g);
        }
        CP_COMMIT();
    };

    float acc[4][4][4];
    #pragma unroll
    for (int a = 0; a < 4; a++)
        #pragma unroll
        for (int b = 0; b < 4; b++)
            #pragma unroll
            for (int c = 0; c < 4; c++) acc[a][b][c] = 0.f;

    // ldmatrix per-lane byte offsets (within a matrix tile)
    const uint32_t a_off = (uint32_t)((wm * 64 + (lane & 15)) * SPITCH
                                      + ((lane >> 4) << 3)) * 2;
    const uint32_t b_off = (uint32_t)((wn * 32 + ((lane >> 4) << 3) + (lane & 7)) * SPITCH
                                      + (lane & 8)) * 2;

    load_stage(0, 0);

    for (int it = 0; it < KITERS; ++it) {
        const int cur = it & 1;
        if (it + 1 < KITERS) {
            load_stage(it + 1, (it + 1) & 1);
            CP_WAIT(1);
        } else {
            CP_WAIT(0);
        }
        __syncthreads();

        const uint32_t st = sbase + cur * STAGE_BYTES;
        #pragma unroll
        for (int ks = 0; ks < 2; ks++) {
            const uint32_t ko = ks * 32;   // 16 bf16 = 32 bytes
            uint32_t ah[4][4], al[4][4], bh[2][4], bl[2][4];
            #pragma unroll
            for (int mi = 0; mi < 4; mi++) {
                uint32_t ao = a_off + (uint32_t)(mi * 16 * SPITCH) * 2 + ko;
                LDSM4(ah[mi], st + 0 * MAT_BYTES + ao);
                LDSM4(al[mi], st + 1 * MAT_BYTES + ao);
            }
            #pragma unroll
            for (int nj = 0; nj < 2; nj++) {
                uint32_t bo = b_off + (uint32_t)(nj * 16 * SPITCH) * 2 + ko;
                LDSM4(bh[nj], st + 2 * MAT_BYTES + bo);
                LDSM4(bl[nj], st + 3 * MAT_BYTES + bo);
            }
            #pragma unroll
            for (int mi = 0; mi < 4; mi++)
                #pragma unroll
                for (int ni = 0; ni < 4; ni++) {
                    uint32_t b0h = bh[ni >> 1][(ni & 1) * 2];
                    uint32_t b1h = bh[ni >> 1][(ni & 1) * 2 + 1];
                    uint32_t b0l = bl[ni >> 1][(ni & 1) * 2];
                    uint32_t b1l = bl[ni >> 1][(ni & 1) * 2 + 1];
                    MMA16816(acc[mi][ni], ah[mi], b0h, b1h);
                    MMA16816(acc[mi][ni], ah[mi], b0l, b1l);
                    MMA16816(acc[mi][ni], al[mi], b0h, b1h);
                }
        }
        __syncthreads();
    }

    // ---- epilogue ----
    const int r0 = wm * 64 + (lane >> 2);
    const int c0 = ncol0 + wn * 32 + (lane & 3) * 2;
    if (pitch == DIMV) {
        #pragma unroll
        for (int mi = 0; mi < 4; mi++)
            #pragma unroll
            for (int ni = 0; ni < 4; ni++) {
                size_t row = m0 + r0 + mi * 16;
                int col = c0 + ni * 8;
                float2 v0 = {acc[mi][ni][0] * scale, acc[mi][ni][1] * scale};
                float2 v1 = {acc[mi][ni][2] * scale, acc[mi][ni][3] * scale};
                *reinterpret_cast<float2*>(&o[row * DIMV + col]) = v0;
                *reinterpret_cast<float2*>(&o[(row + 8) * DIMV + col]) = v1;
            }
    } else {
        #pragma unroll
        for (int mi = 0; mi < 4; mi++)
            #pragma unroll
            for (int ni = 0; ni < 4; ni++) {
                size_t row = m0 + r0 + mi * 16;
                int col = c0 + ni * 8;
                o[row * (size_t)pitch + col]           = acc[mi][ni][0] * scale;
                o[row * (size_t)pitch + col + 1]       = acc[mi][ni][1] * scale;
                o[(row + 8) * (size_t)pitch + col]     = acc[mi][ni][2] * scale;
                o[(row + 8) * (size_t)pitch + col + 1] = acc[mi][ni][3] * scale;
            }
    }
}

// ---------------- fused windowed attention (unchanged) ----------------------
#define SMEM_ATTN_FLOATS (32*65 + 32*65 + 64*32 + 64*65 + 64*65 + 64*65)
__global__ void __launch_bounds__(256) attn_kernel(
    const float* __restrict__ qv, const float* __restrict__ kv,
    const float* __restrict__ vv,
    const float* __restrict__ qd, const float* __restrict__ kd,
    const float* __restrict__ vd,
    float* __restrict__ ov, float* __restrict__ od)
{
    extern __shared__ float smem[];
    float* sqT  = smem;
    float* skT  = sqT + 32 * 65;
    float* sv   = skT + 32 * 65;
    float* gate = sv + 64 * 32;
    float* ssum = gate + 64 * 65;
    float* sc   = ssum + 64 * 65;
    __shared__ float s_qd[64], s_kd[64], s_vd[64];

    const int tid = threadIdx.x;
    const size_t row0 = (size_t)blockIdx.x * 64;

    if (tid < 64) {
        s_qd[tid] = qd[row0 + tid];
        s_kd[tid] = kd[row0 + tid];
        s_vd[tid] = vd[row0 + tid];
    }
    __syncthreads();

    for (int idx = tid; idx < 4096; idx += 256) {
        int i = idx >> 6, j = idx & 63;
        float z = s_qd[i] * s_kd[j];
        gate[i * 65 + j] = 1.f / (1.f + __expf(-z));
        ssum[i * 65 + j] = 0.f;
    }

    const int tm = (tid >> 4) << 2;
    const int tn = (tid & 15) << 2;

    for (int h = 0; h < 8; h++) {
        __syncthreads();
        for (int idx = tid; idx < 2048; idx += 256) {
            int i = idx >> 5, d = idx & 31;
            size_t g = (row0 + i) * 256 + h * 32 + d;
            sqT[d * 65 + i] = qv[g];
            skT[d * 65 + i] = kv[g];
            sv[i * 32 + d]  = vv[g];
        }
        __syncthreads();

        float acc[4][4] = {};
        #pragma unroll 4
        for (int d = 0; d < 32; d++) {
            float a[4], b[4];
            #pragma unroll
            for (int i = 0; i < 4; i++) a[i] = sqT[d * 65 + tm + i];
            #pragma unroll
            for (int j = 0; j < 4; j++) b[j] = skT[d * 65 + tn + j];
            #pragma unroll
            for (int i = 0; i < 4; i++)
                #pragma unroll
                for (int j = 0; j < 4; j++)
                    acc[i][j] = fmaf(a[i], b[j], acc[i][j]);
        }
        #pragma unroll
        for (int i = 0; i < 4; i++)
            #pragma unroll
            for (int j = 0; j < 4; j++) {
                int o = (tm + i) * 65 + tn + j;
                float smv = acc[i][j] * gate[o];
                sc[o] = smv;
                ssum[o] += smv;
            }
        __syncthreads();

        if (tid < 64) {
            float m = -1e30f;
            #pragma unroll 8
            for (int j = 0; j < 64; j++) m = fmaxf(m, sc[tid * 65 + j]);
            float s = 0.f;
            #pragma unroll 8
            for (int j = 0; j < 64; j++) {
                float e = __expf(sc[tid * 65 + j] - m);
                sc[tid * 65 + j] = e;
                s += e;
            }
            float inv = 1.f / s;
            #pragma unroll 8
            for (int j = 0; j < 64; j++) sc[tid * 65 + j] *= inv;
        }
        __syncthreads();

        {
            const int i  = tid >> 2;
            const int d0 = (tid & 3) << 3;
            float a8[8] = {};
            #pragma unroll 4
            for (int j = 0; j < 64; j++) {
                float pr = sc[i * 65 + j];
                float4 v0 = *reinterpret_cast<const float4*>(&sv[j * 32 + d0]);
                float4 v1 = *reinterpret_cast<const float4*>(&sv[j * 32 + d0 + 4]);
                a8[0] = fmaf(pr, v0.x, a8[0]); a8[1] = fmaf(pr, v0.y, a8[1]);
                a8[2] = fmaf(pr, v0.z, a8[2]); a8[3] = fmaf(pr, v0.w, a8[3]);
                a8[4] = fmaf(pr, v1.x, a8[4]); a8[5] = fmaf(pr, v1.y, a8[5]);
                a8[6] = fmaf(pr, v1.z, a8[6]); a8[7] = fmaf(pr, v1.w, a8[7]);
            }
            size_t gb = (row0 + i) * 256 + h * 32 + d0;
            float4 w0 = {a8[0], a8[1], a8[2], a8[3]};
            float4 w1 = {a8[4], a8[5], a8[6], a8[7]};
            *reinterpret_cast<float4*>(&ov[gb])     = w0;
            *reinterpret_cast<float4*>(&ov[gb + 4]) = w1;
        }
    }

    __syncthreads();
    if (tid < 64) {
        float m = -1e30f;
        #pragma unroll 8
        for (int j = 0; j < 64; j++) m = fmaxf(m, ssum[tid * 65 + j]);
        float s = 0.f, acc = 0.f;
        #pragma unroll 8
        for (int j = 0; j < 64; j++) {
            float e = __expf(ssum[tid * 65 + j] - m);
            s += e;
            acc = fmaf(e, s_vd[j], acc);
        }
        od[row0 + tid] = acc / s;
    }
}

// ---------------- launch -----------------------------------------------------
extern "C" void kernel_launch(void* const* d_in, const int* in_sizes, int n_in,
                              void* d_out, int out_size)
{
    const float* x    = (const float*)d_in[0];
    const float* Wqv  = (const float*)d_in[1];
    const float* Wkv  = (const float*)d_in[2];
    const float* Wvv  = (const float*)d_in[3];
    const float* Wqd  = (const float*)d_in[4];
    const float* Wkd  = (const float*)d_in[5];
    const float* Wvd  = (const float*)d_in[6];
    const float* Wout = (const float*)d_in[7];
    float* out = (float*)d_out;

    __nv_bfloat16 *Ah, *Al, *Bh, *Bl, *BoH, *BoL;
    float *qv, *kv, *vv, *ov, *qd, *kd, *vd, *od;
    cudaGetSymbolAddress((void**)&Ah,  g_Ah);
    cudaGetSymbolAddress((void**)&Al,  g_Al);
    cudaGetSymbolAddress((void**)&Bh,  g_Bh);
    cudaGetSymbolAddress((void**)&Bl,  g_Bl);
    cudaGetSymbolAddress((void**)&BoH, g_BoH);
    cudaGetSymbolAddress((void**)&BoL, g_BoL);
    cudaGetSymbolAddress((void**)&qv,  g_qv);
    cudaGetSymbolAddress((void**)&kv,  g_kv);
    cudaGetSymbolAddress((void**)&vv,  g_vv);
    cudaGetSymbolAddress((void**)&ov,  g_ov);
    cudaGetSymbolAddress((void**)&qd,  g_qd);
    cudaGetSymbolAddress((void**)&kd,  g_kd);
    cudaGetSymbolAddress((void**)&vd,  g_vd);
    cudaGetSymbolAddress((void**)&od,  g_od);

    const int attn_smem = SMEM_ATTN_FLOATS * (int)sizeof(float);
    cudaFuncSetAttribute(attn_kernel,
                         cudaFuncAttributeMaxDynamicSharedMemorySize, attn_smem);
    cudaFuncSetAttribute(gemm_mma,
                         cudaFuncAttributeMaxDynamicSharedMemorySize, GEMM_SMEM);

    conv_w_qkv<<<768 * KPAD / 256, 256>>>(Wqv, Wkv, Wvv, Bh, Bl);
    conv_w_out<<<256 * KPAD / 256, 256>>>(Wout, BoH, BoL);
    conv_x_dproj<<<MROWS / 8, 256>>>(x, Wqd, Wkd, Wvd, Ah, Al, qd, kd, vd);

    gemm_mma<<<dim3(6, MROWS / BM), 256, GEMM_SMEM>>>(
        Ah, Al, Bh, Bl, qv, kv, vv, SCALE, 1.f, 1.f, DIMV);

    attn_kernel<<<NWIN, 256, attn_smem>>>(qv, kv, vv, qd, kd, vd, ov, od);

    conv_ov<<<MROWS / 8, 256>>>(ov, od, Wout, Ah, Al, out);

    gemm_mma<<<dim3(2, MROWS / BM), 256, GEMM_SMEM>>>(
        Ah, Al, BoH, BoL, out, out, out, 1.f, 1.f, 1.f, D1);
}

// round 4
// speedup vs baseline: 2.1500x; 1.0943x over previous
#include <cuda_runtime.h>
#include <cuda_bf16.h>
#include <cstdint>
#include <math.h>

#define MROWS 131072        // 2048 windows * 64 tokens
#define NWIN  2048
#define D1    257
#define DIMV  256
#define KPAD  288           // 257 padded to 9 chunks of 32
#define KITERS 9
#define SCALE 0.17677669529663687f   // 32^-0.5

// ======================= scratch (device globals) ===========================
__device__ __align__(256) __nv_bfloat16 g_Ah[(size_t)MROWS * KPAD];
__device__ __align__(256) __nv_bfloat16 g_Al[(size_t)MROWS * KPAD];
__device__ __align__(256) __nv_bfloat16 g_Bh[768 * KPAD];
__device__ __align__(256) __nv_bfloat16 g_Bl[768 * KPAD];
__device__ __align__(256) __nv_bfloat16 g_BoH[256 * KPAD];
__device__ __align__(256) __nv_bfloat16 g_BoL[256 * KPAD];
__device__ float g_qv[(size_t)MROWS * DIMV];
__device__ float g_kv[(size_t)MROWS * DIMV];
__device__ float g_vv[(size_t)MROWS * DIMV];
__device__ float g_ov[(size_t)MROWS * DIMV];
__device__ float g_qd[MROWS];
__device__ float g_kd[MROWS];
__device__ float g_vd[MROWS];
__device__ float g_od[MROWS];

// ======================= PTX helpers =========================================
__device__ __forceinline__ uint32_t smem_u32(const void* p) {
    uint32_t a;
    asm("{ .reg .u64 t; cvta.to.shared.u64 t, %1; cvt.u32.u64 %0, t; }"
        : "=r"(a) : "l"(p));
    return a;
}
__device__ __forceinline__ void cp16(uint32_t s, const void* g) {
    asm volatile("cp.async.ca.shared.global [%0], [%1], 16;" :: "r"(s), "l"(g));
}
#define CP_COMMIT()  asm volatile("cp.async.commit_group;" ::: "memory")
#define CP_WAIT(n)   asm volatile("cp.async.wait_group %0;" :: "n"(n) : "memory")

#define LDSM4(r, addr) \
    asm volatile("ldmatrix.sync.aligned.m8n8.x4.shared.b16 {%0,%1,%2,%3}, [%4];" \
        : "=r"((r)[0]), "=r"((r)[1]), "=r"((r)[2]), "=r"((r)[3]) : "r"(addr))

#define MMA16816(c, a, b0v, b1v) \
    asm volatile("mma.sync.aligned.m16n8k16.row.col.f32.bf16.bf16.f32 " \
        "{%0,%1,%2,%3}, {%4,%5,%6,%7}, {%8,%9}, {%0,%1,%2,%3};" \
        : "+f"((c)[0]), "+f"((c)[1]), "+f"((c)[2]), "+f"((c)[3]) \
        : "r"((a)[0]), "r"((a)[1]), "r"((a)[2]), "r"((a)[3]), "r"(b0v), "r"(b1v))

// ============ conv_x + depth projections (warp per row) =====================
__global__ void __launch_bounds__(256) conv_x_dproj(
    const float* __restrict__ X,
    const float* __restrict__ Wq, const float* __restrict__ Wk,
    const float* __restrict__ Wv,
    __nv_bfloat16* __restrict__ Ah, __nv_bfloat16* __restrict__ Al,
    float* __restrict__ qd, float* __restrict__ kd, float* __restrict__ vd)
{
    const int warp = threadIdx.x >> 5;
    const int lane = threadIdx.x & 31;
    const size_t r = (size_t)blockIdx.x * 8 + warp;
    const float* xr = X + r * D1;
    float sq = 0.f, sk = 0.f, sv = 0.f;
    #pragma unroll
    for (int i = 0; i < 9; i++) {
        int c = lane + i * 32;
        float v = (c < D1) ? xr[c] : 0.f;
        __nv_bfloat16 h = __float2bfloat16(v);
        __nv_bfloat16 l = __float2bfloat16(v - __bfloat162float(h));
        Ah[r * KPAD + c] = h;
        Al[r * KPAD + c] = l;
        if (c < D1) {
            sq = fmaf(v, Wq[c], sq);
            sk = fmaf(v, Wk[c], sk);
            sv = fmaf(v, Wv[c], sv);
        }
    }
    #pragma unroll
    for (int o = 16; o > 0; o >>= 1) {
        sq += __shfl_down_sync(0xffffffffu, sq, o);
        sk += __shfl_down_sync(0xffffffffu, sk, o);
        sv += __shfl_down_sync(0xffffffffu, sv, o);
    }
    if (lane == 0) { qd[r] = sq * SCALE; kd[r] = sk; vd[r] = sv; }
}

// ============ QKV weight transpose+split: B[n,k] = W[k, n%256] ==============
__global__ void __launch_bounds__(256) conv_w_qkv(
    const float* __restrict__ Wqv, const float* __restrict__ Wkv,
    const float* __restrict__ Wvv,
    __nv_bfloat16* __restrict__ Bh, __nv_bfloat16* __restrict__ Bl)
{
    int idx = blockIdx.x * 256 + threadIdx.x;   // 768*288 total
    int n = idx / KPAD, k = idx % KPAD;
    const float* W = (n < 256) ? Wqv : (n < 512) ? Wkv : Wvv;
    float v = (k < D1) ? W[(size_t)k * DIMV + (n & 255)] : 0.f;
    __nv_bfloat16 h = __float2bfloat16(v);
    Bh[idx] = h;
    Bl[idx] = __float2bfloat16(v - __bfloat162float(h));
}

// ============ Wout transpose+split: B[n,k] = Wout[k, n] =====================
__global__ void __launch_bounds__(256) conv_w_out(
    const float* __restrict__ Wout,
    __nv_bfloat16* __restrict__ Bh, __nv_bfloat16* __restrict__ Bl)
{
    int idx = blockIdx.x * 256 + threadIdx.x;   // 256*288 total
    int n = idx / KPAD, k = idx % KPAD;
    float v = (k < D1) ? Wout[(size_t)k * D1 + n] : 0.f;
    __nv_bfloat16 h = __float2bfloat16(v);
    Bh[idx] = h;
    Bl[idx] = __float2bfloat16(v - __bfloat162float(h));
}

// ============ ov+od -> bf16 split + out[:,256] dot ==========================
__global__ void __launch_bounds__(256) conv_ov(
    const float* __restrict__ ov, const float* __restrict__ od,
    const float* __restrict__ Wout,
    __nv_bfloat16* __restrict__ Ah, __nv_bfloat16* __restrict__ Al,
    float* __restrict__ out)
{
    const int warp = threadIdx.x >> 5;
    const int lane = threadIdx.x & 31;
    const size_t r = (size_t)blockIdx.x * 8 + warp;
    float s = 0.f;
    #pragma unroll
    for (int i = 0; i < 9; i++) {
        int c = lane + i * 32;
        float v = 0.f;
        if (c < 256)       v = ov[r * 256 + c];
        else if (c == 256) v = od[r];
        __nv_bfloat16 h = __float2bfloat16(v);
        __nv_bfloat16 l = __float2bfloat16(v - __bfloat162float(h));
        Ah[r * KPAD + c] = h;
        Al[r * KPAD + c] = l;
        if (c < D1) s = fmaf(v, Wout[(size_t)c * D1 + 256], s);
    }
    #pragma unroll
    for (int o = 16; o > 0; o >>= 1) s += __shfl_down_sync(0xffffffffu, s, o);
    if (lane == 0) out[r * D1 + 256] = s;
}

// ============ split-bf16 HMMA GEMM: BM=128 BN=128 BK=32, 3-stage cp.async ===
#define BM 128
#define BN 128
#define BK 32
#define SPITCH 40                          // bf16 per smem row (padded)
#define MAT_BYTES (BM * SPITCH * 2)        // 10240
#define STAGE_BYTES (4 * MAT_BYTES)        // 40960
#define NSTAGE 3
#define GEMM_SMEM (NSTAGE * STAGE_BYTES)   // 122880

__global__ void __launch_bounds__(256, 1) gemm_mma(
    const __nv_bfloat16* __restrict__ Ah, const __nv_bfloat16* __restrict__ Al,
    const __nv_bfloat16* __restrict__ Bh, const __nv_bfloat16* __restrict__ Bl,
    float* __restrict__ o0, float* __restrict__ o1, float* __restrict__ o2,
    float s0, float s1, float s2, int pitch)
{
    extern __shared__ char sm[];
    const int tid  = threadIdx.x;
    const int lane = tid & 31;
    const int wid  = tid >> 5;
    const int wm   = wid >> 2;             // 0..1
    const int wn   = wid & 3;              // 0..3
    const int nblk = blockIdx.x;
    const size_t m0 = (size_t)blockIdx.y * BM;
    const int sel = nblk >> 1;
    float* o = (sel == 0) ? o0 : (sel == 1) ? o1 : o2;
    const float scale = (sel == 0) ? s0 : (sel == 1) ? s1 : s2;
    const int ncol0 = (nblk & 1) * BN;
    const uint32_t sbase = smem_u32(sm);

    const __nv_bfloat16* Bh_b = Bh + (size_t)nblk * BN * KPAD;
    const __nv_bfloat16* Bl_b = Bl + (size_t)nblk * BN * KPAD;

    // per-thread cp.async assignment (8 x 16B chunks / thread / stage)
    auto load_stage = [&](int it, int buf) {
        const int kc = it * BK;
        #pragma unroll
        for (int t = 0; t < 8; t++) {
            int id = tid + t * 256;
            int mat = id >> 9;
            int i = id & 511;
            int row = i >> 2, c = i & 3;
            const __nv_bfloat16* g;
            if      (mat == 0) g = Ah   + (m0 + row) * KPAD + kc + c * 8;
            else if (mat == 1) g = Al   + (m0 + row) * KPAD + kc + c * 8;
            else if (mat == 2) g = Bh_b + (size_t)row * KPAD + kc + c * 8;
            else               g = Bl_b + (size_t)row * KPAD + kc + c * 8;
            uint32_t s = sbase + buf * STAGE_BYTES + mat * MAT_BYTES
                       + (uint32_t)(row * SPITCH + c * 8) * 2;
            cp16(s, g);
        }
        CP_COMMIT();
    };

    float acc[4][4][4];
    #pragma unroll
    for (int a = 0; a < 4; a++)
        #pragma unroll
        for (int b = 0; b < 4; b++)
            #pragma unroll
            for (int c = 0; c < 4; c++) acc[a][b][c] = 0.f;

    // ldmatrix per-lane byte offsets (within a matrix tile)
    const uint32_t a_off = (uint32_t)((wm * 64 + (lane & 15)) * SPITCH
                                      + ((lane >> 4) << 3)) * 2;
    const uint32_t b_off = (uint32_t)((wn * 32 + ((lane >> 4) << 3) + (lane & 7)) * SPITCH
                                      + (lane & 8)) * 2;

    load_stage(0, 0);
    load_stage(1, 1);

    for (int it = 0; it < KITERS; ++it) {
        CP_WAIT(1);            // stage `it` landed (stage it+1 may be in flight)
        __syncthreads();       // everyone done with buffer (it-1)%3 — safe to refill
        if (it + 2 < KITERS) load_stage(it + 2, (it + 2) % NSTAGE);
        else CP_COMMIT();      // keep group accounting exact

        const uint32_t st = sbase + (it % NSTAGE) * STAGE_BYTES;
        #pragma unroll
        for (int ks = 0; ks < 2; ks++) {
            const uint32_t ko = ks * 32;   // 16 bf16 = 32 bytes
            uint32_t ah[4][4], al[4][4], bh[2][4], bl[2][4];
            #pragma unroll
            for (int mi = 0; mi < 4; mi++) {
                uint32_t ao = a_off + (uint32_t)(mi * 16 * SPITCH) * 2 + ko;
                LDSM4(ah[mi], st + 0 * MAT_BYTES + ao);
                LDSM4(al[mi], st + 1 * MAT_BYTES + ao);
            }
            #pragma unroll
            for (int nj = 0; nj < 2; nj++) {
                uint32_t bo = b_off + (uint32_t)(nj * 16 * SPITCH) * 2 + ko;
                LDSM4(bh[nj], st + 2 * MAT_BYTES + bo);
                LDSM4(bl[nj], st + 3 * MAT_BYTES + bo);
            }
            #pragma unroll
            for (int mi = 0; mi < 4; mi++)
                #pragma unroll
                for (int ni = 0; ni < 4; ni++) {
                    uint32_t b0h = bh[ni >> 1][(ni & 1) * 2];
                    uint32_t b1h = bh[ni >> 1][(ni & 1) * 2 + 1];
                    uint32_t b0l = bl[ni >> 1][(ni & 1) * 2];
                    uint32_t b1l = bl[ni >> 1][(ni & 1) * 2 + 1];
                    MMA16816(acc[mi][ni], ah[mi], b0h, b1h);
                    MMA16816(acc[mi][ni], ah[mi], b0l, b1l);
                    MMA16816(acc[mi][ni], al[mi], b0h, b1h);
                }
        }
    }

    // ---- epilogue ----
    const int r0 = wm * 64 + (lane >> 2);
    const int c0 = ncol0 + wn * 32 + (lane & 3) * 2;
    if (pitch == DIMV) {
        #pragma unroll
        for (int mi = 0; mi < 4; mi++)
            #pragma unroll
            for (int ni = 0; ni < 4; ni++) {
                size_t row = m0 + r0 + mi * 16;
                int col = c0 + ni * 8;
                float2 v0 = {acc[mi][ni][0] * scale, acc[mi][ni][1] * scale};
                float2 v1 = {acc[mi][ni][2] * scale, acc[mi][ni][3] * scale};
                *reinterpret_cast<float2*>(&o[row * DIMV + col]) = v0;
                *reinterpret_cast<float2*>(&o[(row + 8) * DIMV + col]) = v1;
            }
    } else {
        #pragma unroll
        for (int mi = 0; mi < 4; mi++)
            #pragma unroll
            for (int ni = 0; ni < 4; ni++) {
                size_t row = m0 + r0 + mi * 16;
                int col = c0 + ni * 8;
                o[row * (size_t)pitch + col]           = acc[mi][ni][0] * scale;
                o[row * (size_t)pitch + col + 1]       = acc[mi][ni][1] * scale;
                o[(row + 8) * (size_t)pitch + col]     = acc[mi][ni][2] * scale;
                o[(row + 8) * (size_t)pitch + col + 1] = acc[mi][ni][3] * scale;
            }
    }
}

// ---------------- fused windowed attention ----------------------------------
#define SMEM_ATTN_FLOATS (32*65 + 32*65 + 64*32 + 64*65 + 64*65 + 64*65)
__global__ void __launch_bounds__(256) attn_kernel(
    const float* __restrict__ qv, const float* __restrict__ kv,
    const float* __restrict__ vv,
    const float* __restrict__ qd, const float* __restrict__ kd,
    const float* __restrict__ vd,
    float* __restrict__ ov, float* __restrict__ od)
{
    extern __shared__ float smem[];
    float* sqT  = smem;
    float* skT  = sqT + 32 * 65;
    float* sv   = skT + 32 * 65;
    float* gate = sv + 64 * 32;
    float* ssum = gate + 64 * 65;
    float* sc   = ssum + 64 * 65;
    __shared__ float s_qd[64], s_kd[64], s_vd[64];

    const int tid = threadIdx.x;
    const size_t row0 = (size_t)blockIdx.x * 64;

    if (tid < 64) {
        s_qd[tid] = qd[row0 + tid];
        s_kd[tid] = kd[row0 + tid];
        s_vd[tid] = vd[row0 + tid];
    }
    __syncthreads();

    for (int idx = tid; idx < 4096; idx += 256) {
        int i = idx >> 6, j = idx & 63;
        float z = s_qd[i] * s_kd[j];
        gate[i * 65 + j] = 1.f / (1.f + __expf(-z));
        ssum[i * 65 + j] = 0.f;
    }

    const int tm = (tid >> 4) << 2;
    const int tn = (tid & 15) << 2;
    // softmax mapping: 4 threads per row
    const int srow = tid >> 2, ssub = tid & 3;
    const int sbase_i = srow * 65 + ssub * 16;
    // PV mapping: 2 rows x 4 dims per thread
    const int pi0 = (tid >> 3) << 1;
    const int pd0 = (tid & 7) << 2;

    for (int h = 0; h < 8; h++) {
        __syncthreads();
        for (int idx = tid; idx < 2048; idx += 256) {
            int i = idx >> 5, d = idx & 31;
            size_t g = (row0 + i) * 256 + h * 32 + d;
            sqT[d * 65 + i] = qv[g];
            skT[d * 65 + i] = kv[g];
            sv[i * 32 + d]  = vv[g];
        }
        __syncthreads();

        float acc[4][4] = {};
        #pragma unroll 4
        for (int d = 0; d < 32; d++) {
            float a[4], b[4];
            #pragma unroll
            for (int i = 0; i < 4; i++) a[i] = sqT[d * 65 + tm + i];
            #pragma unroll
            for (int j = 0; j < 4; j++) b[j] = skT[d * 65 + tn + j];
            #pragma unroll
            for (int i = 0; i < 4; i++)
                #pragma unroll
                for (int j = 0; j < 4; j++)
                    acc[i][j] = fmaf(a[i], b[j], acc[i][j]);
        }
        #pragma unroll
        for (int i = 0; i < 4; i++)
            #pragma unroll
            for (int j = 0; j < 4; j++) {
                int o = (tm + i) * 65 + tn + j;
                float smv = acc[i][j] * gate[o];
                sc[o] = smv;
                ssum[o] += smv;
            }
        __syncthreads();

        // per-row softmax, 4 threads per row + quad shuffle reduce
        {
            float m = -1e30f;
            #pragma unroll
            for (int t = 0; t < 16; t++) m = fmaxf(m, sc[sbase_i + t]);
            m = fmaxf(m, __shfl_xor_sync(0xffffffffu, m, 1));
            m = fmaxf(m, __shfl_xor_sync(0xffffffffu, m, 2));
            float s = 0.f;
            float e16[16];
            #pragma unroll
            for (int t = 0; t < 16; t++) {
                float e = __expf(sc[sbase_i + t] - m);
                e16[t] = e;
                s += e;
            }
            s += __shfl_xor_sync(0xffffffffu, s, 1);
            s += __shfl_xor_sync(0xffffffffu, s, 2);
            float inv = 1.f / s;
            #pragma unroll
            for (int t = 0; t < 16; t++) sc[sbase_i + t] = e16[t] * inv;
        }
        __syncthreads();

        // PV: 2 rows x 4 dims per thread
        {
            float a0[4] = {}, a1[4] = {};
            #pragma unroll 8
            for (int j = 0; j < 64; j++) {
                float p0 = sc[pi0 * 65 + j];
                float p1 = sc[(pi0 + 1) * 65 + j];
                float4 v = *reinterpret_cast<const float4*>(&sv[j * 32 + pd0]);
                a0[0] = fmaf(p0, v.x, a0[0]); a0[1] = fmaf(p0, v.y, a0[1]);
                a0[2] = fmaf(p0, v.z, a0[2]); a0[3] = fmaf(p0, v.w, a0[3]);
                a1[0] = fmaf(p1, v.x, a1[0]); a1[1] = fmaf(p1, v.y, a1[1]);
                a1[2] = fmaf(p1, v.z, a1[2]); a1[3] = fmaf(p1, v.w, a1[3]);
            }
            size_t gb0 = (row0 + pi0) * 256 + h * 32 + pd0;
            size_t gb1 = (row0 + pi0 + 1) * 256 + h * 32 + pd0;
            float4 w0 = {a0[0], a0[1], a0[2], a0[3]};
            float4 w1 = {a1[0], a1[1], a1[2], a1[3]};
            *reinterpret_cast<float4*>(&ov[gb0]) = w0;
            *reinterpret_cast<float4*>(&ov[gb1]) = w1;
        }
    }

    __syncthreads();
    // depth attention softmax: 4 threads per row
    {
        float m = -1e30f;
        #pragma unroll
        for (int t = 0; t < 16; t++) m = fmaxf(m, ssum[sbase_i + t]);
        m = fmaxf(m, __shfl_xor_sync(0xffffffffu, m, 1));
        m = fmaxf(m, __shfl_xor_sync(0xffffffffu, m, 2));
        float s = 0.f, acc = 0.f;
        #pragma unroll
        for (int t = 0; t < 16; t++) {
            float e = __expf(ssum[sbase_i + t] - m);
            s += e;
            acc = fmaf(e, s_vd[ssub * 16 + t], acc);
        }
        s   += __shfl_xor_sync(0xffffffffu, s, 1);
        acc += __shfl_xor_sync(0xffffffffu, acc, 1);
        s   += __shfl_xor_sync(0xffffffffu, s, 2);
        acc += __shfl_xor_sync(0xffffffffu, acc, 2);
        if (ssub == 0) od[row0 + srow] = acc / s;
    }
}

// ---------------- launch -----------------------------------------------------
extern "C" void kernel_launch(void* const* d_in, const int* in_sizes, int n_in,
                              void* d_out, int out_size)
{
    const float* x    = (const float*)d_in[0];
    const float* Wqv  = (const float*)d_in[1];
    const float* Wkv  = (const float*)d_in[2];
    const float* Wvv  = (const float*)d_in[3];
    const float* Wqd  = (const float*)d_in[4];
    const float* Wkd  = (const float*)d_in[5];
    const float* Wvd  = (const float*)d_in[6];
    const float* Wout = (const float*)d_in[7];
    float* out = (float*)d_out;

    __nv_bfloat16 *Ah, *Al, *Bh, *Bl, *BoH, *BoL;
    float *qv, *kv, *vv, *ov, *qd, *kd, *vd, *od;
    cudaGetSymbolAddress((void**)&Ah,  g_Ah);
    cudaGetSymbolAddress((void**)&Al,  g_Al);
    cudaGetSymbolAddress((void**)&Bh,  g_Bh);
    cudaGetSymbolAddress((void**)&Bl,  g_Bl);
    cudaGetSymbolAddress((void**)&BoH, g_BoH);
    cudaGetSymbolAddress((void**)&BoL, g_BoL);
    cudaGetSymbolAddress((void**)&qv,  g_qv);
    cudaGetSymbolAddress((void**)&kv,  g_kv);
    cudaGetSymbolAddress((void**)&vv,  g_vv);
    cudaGetSymbolAddress((void**)&ov,  g_ov);
    cudaGetSymbolAddress((void**)&qd,  g_qd);
    cudaGetSymbolAddress((void**)&kd,  g_kd);
    cudaGetSymbolAddress((void**)&vd,  g_vd);
    cudaGetSymbolAddress((void**)&od,  g_od);

    const int attn_smem = SMEM_ATTN_FLOATS * (int)sizeof(float);
    cudaFuncSetAttribute(attn_kernel,
                         cudaFuncAttributeMaxDynamicSharedMemorySize, attn_smem);
    cudaFuncSetAttribute(gemm_mma,
                         cudaFuncAttributeMaxDynamicSharedMemorySize, GEMM_SMEM);

    conv_w_qkv<<<768 * KPAD / 256, 256>>>(Wqv, Wkv, Wvv, Bh, Bl);
    conv_w_out<<<256 * KPAD / 256, 256>>>(Wout, BoH, BoL);
    conv_x_dproj<<<MROWS / 8, 256>>>(x, Wqd, Wkd, Wvd, Ah, Al, qd, kd, vd);

    gemm_mma<<<dim3(6, MROWS / BM), 256, GEMM_SMEM>>>(
        Ah, Al, Bh, Bl, qv, kv, vv, SCALE, 1.f, 1.f, DIMV);

    attn_kernel<<<NWIN, 256, attn_smem>>>(qv, kv, vv, qd, kd, vd, ov, od);

    conv_ov<<<MROWS / 8, 256>>>(ov, od, Wout, Ah, Al, out);

    gemm_mma<<<dim3(2, MROWS / BM), 256, GEMM_SMEM>>>(
        Ah, Al, BoH, BoL, out, out, out, 1.f, 1.f, 1.f, D1);
}

// round 5
// speedup vs baseline: 2.5708x; 1.1957x over previous
#include <cuda_runtime.h>
#include <cuda_fp16.h>
#include <cstdint>
#include <math.h>

#define MROWS 131072        // 2048 windows * 64 tokens
#define NWIN  2048
#define D1    257
#define DIMV  256
#define KPAD  288           // 257 padded to 9 chunks of 32
#define KITERS 9
#define SCALE 0.17677669529663687f   // 32^-0.5

// ======================= scratch (device globals) ===========================
__device__ __align__(256) __half g_Ah[(size_t)MROWS * KPAD];
__device__ __align__(256) __half g_Al[(size_t)MROWS * KPAD];
__device__ __align__(256) __half g_Bh[768 * KPAD];
__device__ __align__(256) __half g_BoH[256 * KPAD];
__device__ float g_qv[(size_t)MROWS * DIMV];
__device__ float g_kv[(size_t)MROWS * DIMV];
__device__ float g_vv[(size_t)MROWS * DIMV];
__device__ float g_ov[(size_t)MROWS * DIMV];
__device__ float g_qd[MROWS];
__device__ float g_kd[MROWS];
__device__ float g_vd[MROWS];
__device__ float g_od[MROWS];

// ======================= PTX helpers =========================================
__device__ __forceinline__ uint32_t smem_u32(const void* p) {
    uint32_t a;
    asm("{ .reg .u64 t; cvta.to.shared.u64 t, %1; cvt.u32.u64 %0, t; }"
        : "=r"(a) : "l"(p));
    return a;
}
__device__ __forceinline__ void cp16(uint32_t s, const void* g) {
    asm volatile("cp.async.ca.shared.global [%0], [%1], 16;" :: "r"(s), "l"(g));
}
#define CP_COMMIT()  asm volatile("cp.async.commit_group;" ::: "memory")
#define CP_WAIT(n)   asm volatile("cp.async.wait_group %0;" :: "n"(n) : "memory")

#define LDSM4(r, addr) \
    asm volatile("ldmatrix.sync.aligned.m8n8.x4.shared.b16 {%0,%1,%2,%3}, [%4];" \
        : "=r"((r)[0]), "=r"((r)[1]), "=r"((r)[2]), "=r"((r)[3]) : "r"(addr))

#define MMA16816(c, a, b0v, b1v) \
    asm volatile("mma.sync.aligned.m16n8k16.row.col.f32.f16.f16.f32 " \
        "{%0,%1,%2,%3}, {%4,%5,%6,%7}, {%8,%9}, {%0,%1,%2,%3};" \
        : "+f"((c)[0]), "+f"((c)[1]), "+f"((c)[2]), "+f"((c)[3]) \
        : "r"((a)[0]), "r"((a)[1]), "r"((a)[2]), "r"((a)[3]), "r"(b0v), "r"(b1v))

// ============ conv_x + depth projections (warp per row) =====================
__global__ void __launch_bounds__(256) conv_x_dproj(
    const float* __restrict__ X,
    const float* __restrict__ Wq, const float* __restrict__ Wk,
    const float* __restrict__ Wv,
    __half* __restrict__ Ah, __half* __restrict__ Al,
    float* __restrict__ qd, float* __restrict__ kd, float* __restrict__ vd)
{
    const int warp = threadIdx.x >> 5;
    const int lane = threadIdx.x & 31;
    const size_t r = (size_t)blockIdx.x * 8 + warp;
    const float* xr = X + r * D1;
    float sq = 0.f, sk = 0.f, sv = 0.f;
    #pragma unroll
    for (int i = 0; i < 9; i++) {
        int c = lane + i * 32;
        float v = (c < D1) ? xr[c] : 0.f;
        __half h = __float2half_rn(v);
        __half l = __float2half_rn(v - __half2float(h));
        Ah[r * KPAD + c] = h;
        Al[r * KPAD + c] = l;
        if (c < D1) {
            sq = fmaf(v, Wq[c], sq);
            sk = fmaf(v, Wk[c], sk);
            sv = fmaf(v, Wv[c], sv);
        }
    }
    #pragma unroll
    for (int o = 16; o > 0; o >>= 1) {
        sq += __shfl_down_sync(0xffffffffu, sq, o);
        sk += __shfl_down_sync(0xffffffffu, sk, o);
        sv += __shfl_down_sync(0xffffffffu, sv, o);
    }
    if (lane == 0) { qd[r] = sq * SCALE; kd[r] = sk; vd[r] = sv; }
}

// ============ QKV weight transpose: B[n,k] = fp16(W[k, n%256]) ==============
__global__ void __launch_bounds__(256) conv_w_qkv(
    const float* __restrict__ Wqv, const float* __restrict__ Wkv,
    const float* __restrict__ Wvv, __half* __restrict__ Bh)
{
    int idx = blockIdx.x * 256 + threadIdx.x;   // 768*288 total
    int n = idx / KPAD, k = idx % KPAD;
    const float* W = (n < 256) ? Wqv : (n < 512) ? Wkv : Wvv;
    float v = (k < D1) ? W[(size_t)k * DIMV + (n & 255)] : 0.f;
    Bh[idx] = __float2half_rn(v);
}

// ============ Wout transpose: B[n,k] = fp16(Wout[k, n]) =====================
__global__ void __launch_bounds__(256) conv_w_out(
    const float* __restrict__ Wout, __half* __restrict__ Bh)
{
    int idx = blockIdx.x * 256 + threadIdx.x;   // 256*288 total
    int n = idx / KPAD, k = idx % KPAD;
    float v = (k < D1) ? Wout[(size_t)k * D1 + n] : 0.f;
    Bh[idx] = __float2half_rn(v);
}

// ============ ov+od -> fp16 split + out[:,256] dot ==========================
__global__ void __launch_bounds__(256) conv_ov(
    const float* __restrict__ ov, const float* __restrict__ od,
    const float* __restrict__ Wout,
    __half* __restrict__ Ah, __half* __restrict__ Al,
    float* __restrict__ out)
{
    const int warp = threadIdx.x >> 5;
    const int lane = threadIdx.x & 31;
    const size_t r = (size_t)blockIdx.x * 8 + warp;
    float s = 0.f;
    #pragma unroll
    for (int i = 0; i < 9; i++) {
        int c = lane + i * 32;
        float v = 0.f;
        if (c < 256)       v = ov[r * 256 + c];
        else if (c == 256) v = od[r];
        __half h = __float2half_rn(v);
        __half l = __float2half_rn(v - __half2float(h));
        Ah[r * KPAD + c] = h;
        Al[r * KPAD + c] = l;
        if (c < D1) s = fmaf(v, Wout[(size_t)c * D1 + 256], s);
    }
    #pragma unroll
    for (int o = 16; o > 0; o >>= 1) s += __shfl_down_sync(0xffffffffu, s, o);
    if (lane == 0) out[r * D1 + 256] = s;
}

// ============ split-fp16 HMMA GEMM: BM=128 BN=128 BK=32, 3-stage, 2 CTA/SM ==
#define BM 128
#define BN 128
#define BK 32
#define SPITCH 40                          // fp16 per smem row (padded)
#define MAT_BYTES (BM * SPITCH * 2)        // 10240
#define STAGE_BYTES (3 * MAT_BYTES)        // 30720 (Ah, Al, Bh)
#define NSTAGE 3
#define GEMM_SMEM (NSTAGE * STAGE_BYTES)   // 92160

__global__ void __launch_bounds__(256, 2) gemm_mma(
    const __half* __restrict__ Ah, const __half* __restrict__ Al,
    const __half* __restrict__ Bh,
    float* __restrict__ o0, float* __restrict__ o1, float* __restrict__ o2,
    float s0, float s1, float s2, int pitch)
{
    extern __shared__ char sm[];
    const int tid  = threadIdx.x;
    const int lane = tid & 31;
    const int wid  = tid >> 5;
    const int wm   = wid >> 2;             // 0..1
    const int wn   = wid & 3;              // 0..3
    const int nblk = blockIdx.x;
    const size_t m0 = (size_t)blockIdx.y * BM;
    const int sel = nblk >> 1;
    float* o = (sel == 0) ? o0 : (sel == 1) ? o1 : o2;
    const float scale = (sel == 0) ? s0 : (sel == 1) ? s1 : s2;
    const int ncol0 = (nblk & 1) * BN;
    const uint32_t sbase = smem_u32(sm);

    const __half* Bh_b = Bh + (size_t)nblk * BN * KPAD;

    // per-thread cp.async assignment (6 x 16B chunks / thread / stage)
    // id in [0,1536): mat = id>>9 (Ah,Al,Bh), i = id&511, row = i>>2, c = i&3
    auto load_stage = [&](int it, int buf) {
        const int kc = it * BK;
        #pragma unroll
        for (int t = 0; t < 6; t++) {
            int id = tid + t * 256;
            int mat = id >> 9;
            int i = id & 511;
            int row = i >> 2, c = i & 3;
            const __half* g;
            if      (mat == 0) g = Ah   + (m0 + row) * KPAD + kc + c * 8;
            else if (mat == 1) g = Al   + (m0 + row) * KPAD + kc + c * 8;
            else               g = Bh_b + (size_t)row * KPAD + kc + c * 8;
            uint32_t s = sbase + buf * STAGE_BYTES + mat * MAT_BYTES
                       + (uint32_t)(row * SPITCH + c * 8) * 2;
            cp16(s, g);
        }
        CP_COMMIT();
    };

    float acc[4][4][4];
    #pragma unroll
    for (int a = 0; a < 4; a++)
        #pragma unroll
        for (int b = 0; b < 4; b++)
            #pragma unroll
            for (int c = 0; c < 4; c++) acc[a][b][c] = 0.f;

    // ldmatrix per-lane byte offsets (within a matrix tile)
    const uint32_t a_off = (uint32_t)((wm * 64 + (lane & 15)) * SPITCH
                                      + ((lane >> 4) << 3)) * 2;
    const uint32_t b_off = (uint32_t)((wn * 32 + ((lane >> 4) << 3) + (lane & 7)) * SPITCH
                                      + (lane & 8)) * 2;

    load_stage(0, 0);
    load_stage(1, 1);

    for (int it = 0; it < KITERS; ++it) {
        CP_WAIT(1);            // stage `it` landed (stage it+1 may be in flight)
        __syncthreads();       // buffer (it-1)%3 free — safe to refill
        if (it + 2 < KITERS) load_stage(it + 2, (it + 2) % NSTAGE);
        else CP_COMMIT();      // keep group accounting exact

        const uint32_t st = sbase + (it % NSTAGE) * STAGE_BYTES;
        #pragma unroll
        for (int ks = 0; ks < 2; ks++) {
            const uint32_t ko = ks * 32;   // 16 fp16 = 32 bytes
            uint32_t ah[4][4], al[4][4], bh[2][4];
            #pragma unroll
            for (int mi = 0; mi < 4; mi++) {
                uint32_t ao = a_off + (uint32_t)(mi * 16 * SPITCH) * 2 + ko;
                LDSM4(ah[mi], st + 0 * MAT_BYTES + ao);
                LDSM4(al[mi], st + 1 * MAT_BYTES + ao);
            }
            #pragma unroll
            for (int nj = 0; nj < 2; nj++) {
                uint32_t bo = b_off + (uint32_t)(nj * 16 * SPITCH) * 2 + ko;
                LDSM4(bh[nj], st + 2 * MAT_BYTES + bo);
            }
            #pragma unroll
            for (int mi = 0; mi < 4; mi++)
                #pragma unroll
                for (int ni = 0; ni < 4; ni++) {
                    uint32_t b0 = bh[ni >> 1][(ni & 1) * 2];
                    uint32_t b1 = bh[ni >> 1][(ni & 1) * 2 + 1];
                    MMA16816(acc[mi][ni], ah[mi], b0, b1);
                    MMA16816(acc[mi][ni], al[mi], b0, b1);
                }
        }
    }

    // ---- epilogue ----
    const int r0 = wm * 64 + (lane >> 2);
    const int c0 = ncol0 + wn * 32 + (lane & 3) * 2;
    if (pitch == DIMV) {
        #pragma unroll
        for (int mi = 0; mi < 4; mi++)
            #pragma unroll
            for (int ni = 0; ni < 4; ni++) {
                size_t row = m0 + r0 + mi * 16;
                int col = c0 + ni * 8;
                float2 v0 = {acc[mi][ni][0] * scale, acc[mi][ni][1] * scale};
                float2 v1 = {acc[mi][ni][2] * scale, acc[mi][ni][3] * scale};
                *reinterpret_cast<float2*>(&o[row * DIMV + col]) = v0;
                *reinterpret_cast<float2*>(&o[(row + 8) * DIMV + col]) = v1;
            }
    } else {
        #pragma unroll
        for (int mi = 0; mi < 4; mi++)
            #pragma unroll
            for (int ni = 0; ni < 4; ni++) {
                size_t row = m0 + r0 + mi * 16;
                int col = c0 + ni * 8;
                o[row * (size_t)pitch + col]           = acc[mi][ni][0] * scale;
                o[row * (size_t)pitch + col + 1]       = acc[mi][ni][1] * scale;
                o[(row + 8) * (size_t)pitch + col]     = acc[mi][ni][2] * scale;
                o[(row + 8) * (size_t)pitch + col + 1] = acc[mi][ni][3] * scale;
            }
    }
}

// ---------------- fused windowed attention ----------------------------------
#define SMEM_ATTN_FLOATS (32*65 + 32*65 + 64*32 + 64*65 + 64*65 + 64*65)
__global__ void __launch_bounds__(256) attn_kernel(
    const float* __restrict__ qv, const float* __restrict__ kv,
    const float* __restrict__ vv,
    const float* __restrict__ qd, const float* __restrict__ kd,
    const float* __restrict__ vd,
    float* __restrict__ ov, float* __restrict__ od)
{
    extern __shared__ float smem[];
    float* sqT  = smem;
    float* skT  = sqT + 32 * 65;
    float* sv   = skT + 32 * 65;
    float* gate = sv + 64 * 32;
    float* ssum = gate + 64 * 65;
    float* sc   = ssum + 64 * 65;
    __shared__ float s_qd[64], s_kd[64], s_vd[64];

    const int tid = threadIdx.x;
    const size_t row0 = (size_t)blockIdx.x * 64;

    if (tid < 64) {
        s_qd[tid] = qd[row0 + tid];
        s_kd[tid] = kd[row0 + tid];
        s_vd[tid] = vd[row0 + tid];
    }
    __syncthreads();

    for (int idx = tid; idx < 4096; idx += 256) {
        int i = idx >> 6, j = idx & 63;
        float z = s_qd[i] * s_kd[j];
        gate[i * 65 + j] = 1.f / (1.f + __expf(-z));
        ssum[i * 65 + j] = 0.f;
    }

    const int tm = (tid >> 4) << 2;
    const int tn = (tid & 15) << 2;
    const int srow = tid >> 2, ssub = tid & 3;
    const int sbase_i = srow * 65 + ssub * 16;
    const int pi0 = (tid >> 3) << 1;
    const int pd0 = (tid & 7) << 2;

    for (int h = 0; h < 8; h++) {
        __syncthreads();
        for (int idx = tid; idx < 2048; idx += 256) {
            int i = idx >> 5, d = idx & 31;
            size_t g = (row0 + i) * 256 + h * 32 + d;
            sqT[d * 65 + i] = qv[g];
            skT[d * 65 + i] = kv[g];
            sv[i * 32 + d]  = vv[g];
        }
        __syncthreads();

        float acc[4][4] = {};
        #pragma unroll 4
        for (int d = 0; d < 32; d++) {
            float a[4], b[4];
            #pragma unroll
            for (int i = 0; i < 4; i++) a[i] = sqT[d * 65 + tm + i];
            #pragma unroll
            for (int j = 0; j < 4; j++) b[j] = skT[d * 65 + tn + j];
            #pragma unroll
            for (int i = 0; i < 4; i++)
                #pragma unroll
                for (int j = 0; j < 4; j++)
                    acc[i][j] = fmaf(a[i], b[j], acc[i][j]);
        }
        #pragma unroll
        for (int i = 0; i < 4; i++)
            #pragma unroll
            for (int j = 0; j < 4; j++) {
                int o = (tm + i) * 65 + tn + j;
                float smv = acc[i][j] * gate[o];
                sc[o] = smv;
                ssum[o] += smv;
            }
        __syncthreads();

        // per-row softmax, 4 threads per row + quad shuffle reduce
        {
            float m = -1e30f;
            #pragma unroll
            for (int t = 0; t < 16; t++) m = fmaxf(m, sc[sbase_i + t]);
            m = fmaxf(m, __shfl_xor_sync(0xffffffffu, m, 1));
            m = fmaxf(m, __shfl_xor_sync(0xffffffffu, m, 2));
            float s = 0.f;
            float e16[16];
            #pragma unroll
            for (int t = 0; t < 16; t++) {
                float e = __expf(sc[sbase_i + t] - m);
                e16[t] = e;
                s += e;
            }
            s += __shfl_xor_sync(0xffffffffu, s, 1);
            s += __shfl_xor_sync(0xffffffffu, s, 2);
            float inv = 1.f / s;
            #pragma unroll
            for (int t = 0; t < 16; t++) sc[sbase_i + t] = e16[t] * inv;
        }
        __syncthreads();

        // PV: 2 rows x 4 dims per thread
        {
            float a0[4] = {}, a1[4] = {};
            #pragma unroll 8
            for (int j = 0; j < 64; j++) {
                float p0 = sc[pi0 * 65 + j];
                float p1 = sc[(pi0 + 1) * 65 + j];
                float4 v = *reinterpret_cast<const float4*>(&sv[j * 32 + pd0]);
                a0[0] = fmaf(p0, v.x, a0[0]); a0[1] = fmaf(p0, v.y, a0[1]);
                a0[2] = fmaf(p0, v.z, a0[2]); a0[3] = fmaf(p0, v.w, a0[3]);
                a1[0] = fmaf(p1, v.x, a1[0]); a1[1] = fmaf(p1, v.y, a1[1]);
                a1[2] = fmaf(p1, v.z, a1[2]); a1[3] = fmaf(p1, v.w, a1[3]);
            }
            size_t gb0 = (row0 + pi0) * 256 + h * 32 + pd0;
            size_t gb1 = (row0 + pi0 + 1) * 256 + h * 32 + pd0;
            float4 w0 = {a0[0], a0[1], a0[2], a0[3]};
            float4 w1 = {a1[0], a1[1], a1[2], a1[3]};
            *reinterpret_cast<float4*>(&ov[gb0]) = w0;
            *reinterpret_cast<float4*>(&ov[gb1]) = w1;
        }
    }

    __syncthreads();
    // depth attention softmax: 4 threads per row
    {
        float m = -1e30f;
        #pragma unroll
        for (int t = 0; t < 16; t++) m = fmaxf(m, ssum[sbase_i + t]);
        m = fmaxf(m, __shfl_xor_sync(0xffffffffu, m, 1));
        m = fmaxf(m, __shfl_xor_sync(0xffffffffu, m, 2));
        float s = 0.f, acc = 0.f;
        #pragma unroll
        for (int t = 0; t < 16; t++) {
            float e = __expf(ssum[sbase_i + t] - m);
            s += e;
            acc = fmaf(e, s_vd[ssub * 16 + t], acc);
        }
        s   += __shfl_xor_sync(0xffffffffu, s, 1);
        acc += __shfl_xor_sync(0xffffffffu, acc, 1);
        s   += __shfl_xor_sync(0xffffffffu, s, 2);
        acc += __shfl_xor_sync(0xffffffffu, acc, 2);
        if (ssub == 0) od[row0 + srow] = acc / s;
    }
}

// ---------------- launch -----------------------------------------------------
extern "C" void kernel_launch(void* const* d_in, const int* in_sizes, int n_in,
                              void* d_out, int out_size)
{
    const float* x    = (const float*)d_in[0];
    const float* Wqv  = (const float*)d_in[1];
    const float* Wkv  = (const float*)d_in[2];
    const float* Wvv  = (const float*)d_in[3];
    const float* Wqd  = (const float*)d_in[4];
    const float* Wkd  = (const float*)d_in[5];
    const float* Wvd  = (const float*)d_in[6];
    const float* Wout = (const float*)d_in[7];
    float* out = (float*)d_out;

    __half *Ah, *Al, *Bh, *BoH;
    float *qv, *kv, *vv, *ov, *qd, *kd, *vd, *od;
    cudaGetSymbolAddress((void**)&Ah,  g_Ah);
    cudaGetSymbolAddress((void**)&Al,  g_Al);
    cudaGetSymbolAddress((void**)&Bh,  g_Bh);
    cudaGetSymbolAddress((void**)&BoH, g_BoH);
    cudaGetSymbolAddress((void**)&qv,  g_qv);
    cudaGetSymbolAddress((void**)&kv,  g_kv);
    cudaGetSymbolAddress((void**)&vv,  g_vv);
    cudaGetSymbolAddress((void**)&ov,  g_ov);
    cudaGetSymbolAddress((void**)&qd,  g_qd);
    cudaGetSymbolAddress((void**)&kd,  g_kd);
    cudaGetSymbolAddress((void**)&vd,  g_vd);
    cudaGetSymbolAddress((void**)&od,  g_od);

    const int attn_smem = SMEM_ATTN_FLOATS * (int)sizeof(float);
    cudaFuncSetAttribute(attn_kernel,
                         cudaFuncAttributeMaxDynamicSharedMemorySize, attn_smem);
    cudaFuncSetAttribute(gemm_mma,
                         cudaFuncAttributeMaxDynamicSharedMemorySize, GEMM_SMEM);

    conv_w_qkv<<<768 * KPAD / 256, 256>>>(Wqv, Wkv, Wvv, Bh);
    conv_w_out<<<256 * KPAD / 256, 256>>>(Wout, BoH);
    conv_x_dproj<<<MROWS / 8, 256>>>(x, Wqd, Wkd, Wvd, Ah, Al, qd, kd, vd);

    gemm_mma<<<dim3(6, MROWS / BM), 256, GEMM_SMEM>>>(
        Ah, Al, Bh, qv, kv, vv, SCALE, 1.f, 1.f, DIMV);

    attn_kernel<<<NWIN, 256, attn_smem>>>(qv, kv, vv, qd, kd, vd, ov, od);

    conv_ov<<<MROWS / 8, 256>>>(ov, od, Wout, Ah, Al, out);

    gemm_mma<<<dim3(2, MROWS / BM), 256, GEMM_SMEM>>>(
        Ah, Al, BoH, out, out, out, 1.f, 1.f, 1.f, D1);
}

// round 6
// speedup vs baseline: 2.6351x; 1.0250x over previous
#include <cuda_runtime.h>
#include <cuda_fp16.h>
#include <cstdint>
#include <math.h>

#define MROWS 131072        // 2048 windows * 64 tokens
#define NWIN  2048
#define D1    257
#define DIMV  256
#define KPAD  288           // 257 padded to 9 chunks of 32
#define KITERS 9
#define SCALE 0.17677669529663687f   // 32^-0.5

// ======================= scratch (device globals) ===========================
__device__ __align__(256) __half g_Ah[(size_t)MROWS * KPAD];
__device__ __align__(256) __half g_Al[(size_t)MROWS * KPAD];
__device__ __align__(256) __half g_Bh[768 * KPAD];
__device__ __align__(256) __half g_BoH[256 * KPAD];
__device__ float g_qv[(size_t)MROWS * DIMV];
__device__ float g_kv[(size_t)MROWS * DIMV];
__device__ float g_vv[(size_t)MROWS * DIMV];
__device__ float g_ov[(size_t)MROWS * DIMV];
__device__ float g_qd[MROWS];
__device__ float g_kd[MROWS];
__device__ float g_vd[MROWS];
__device__ float g_od[MROWS];

// ======================= PTX helpers =========================================
__device__ __forceinline__ uint32_t smem_u32(const void* p) {
    uint32_t a;
    asm("{ .reg .u64 t; cvta.to.shared.u64 t, %1; cvt.u32.u64 %0, t; }"
        : "=r"(a) : "l"(p));
    return a;
}
__device__ __forceinline__ void cp16(uint32_t s, const void* g) {
    asm volatile("cp.async.ca.shared.global [%0], [%1], 16;" :: "r"(s), "l"(g));
}
#define CP_COMMIT()  asm volatile("cp.async.commit_group;" ::: "memory")
#define CP_WAIT(n)   asm volatile("cp.async.wait_group %0;" :: "n"(n) : "memory")

#define LDSM4(r, addr) \
    asm volatile("ldmatrix.sync.aligned.m8n8.x4.shared.b16 {%0,%1,%2,%3}, [%4];" \
        : "=r"((r)[0]), "=r"((r)[1]), "=r"((r)[2]), "=r"((r)[3]) : "r"(addr))

#define MMA16816(c, a, b0v, b1v) \
    asm volatile("mma.sync.aligned.m16n8k16.row.col.f32.f16.f16.f32 " \
        "{%0,%1,%2,%3}, {%4,%5,%6,%7}, {%8,%9}, {%0,%1,%2,%3};" \
        : "+f"((c)[0]), "+f"((c)[1]), "+f"((c)[2]), "+f"((c)[3]) \
        : "r"((a)[0]), "r"((a)[1]), "r"((a)[2]), "r"((a)[3]), "r"(b0v), "r"(b1v))

// ============ conv_x + depth projections (warp per row) =====================
__global__ void __launch_bounds__(256) conv_x_dproj(
    const float* __restrict__ X,
    const float* __restrict__ Wq, const float* __restrict__ Wk,
    const float* __restrict__ Wv,
    __half* __restrict__ Ah, __half* __restrict__ Al,
    float* __restrict__ qd, float* __restrict__ kd, float* __restrict__ vd)
{
    const int warp = threadIdx.x >> 5;
    const int lane = threadIdx.x & 31;
    const size_t r = (size_t)blockIdx.x * 8 + warp;
    const float* xr = X + r * D1;
    float sq = 0.f, sk = 0.f, sv = 0.f;
    #pragma unroll
    for (int i = 0; i < 9; i++) {
        int c = lane + i * 32;
        float v = (c < D1) ? xr[c] : 0.f;
        __half h = __float2half_rn(v);
        __half l = __float2half_rn(v - __half2float(h));
        Ah[r * KPAD + c] = h;
        Al[r * KPAD + c] = l;
        if (c < D1) {
            sq = fmaf(v, Wq[c], sq);
            sk = fmaf(v, Wk[c], sk);
            sv = fmaf(v, Wv[c], sv);
        }
    }
    #pragma unroll
    for (int o = 16; o > 0; o >>= 1) {
        sq += __shfl_down_sync(0xffffffffu, sq, o);
        sk += __shfl_down_sync(0xffffffffu, sk, o);
        sv += __shfl_down_sync(0xffffffffu, sv, o);
    }
    if (lane == 0) { qd[r] = sq * SCALE; kd[r] = sk; vd[r] = sv; }
}

// ============ QKV weight transpose: B[n,k] = fp16(W[k, n%256]) ==============
__global__ void __launch_bounds__(256) conv_w_qkv(
    const float* __restrict__ Wqv, const float* __restrict__ Wkv,
    const float* __restrict__ Wvv, __half* __restrict__ Bh)
{
    int idx = blockIdx.x * 256 + threadIdx.x;   // 768*288 total
    int n = idx / KPAD, k = idx % KPAD;
    const float* W = (n < 256) ? Wqv : (n < 512) ? Wkv : Wvv;
    float v = (k < D1) ? W[(size_t)k * DIMV + (n & 255)] : 0.f;
    Bh[idx] = __float2half_rn(v);
}

// ============ Wout transpose: B[n,k] = fp16(Wout[k, n]) =====================
__global__ void __launch_bounds__(256) conv_w_out(
    const float* __restrict__ Wout, __half* __restrict__ Bh)
{
    int idx = blockIdx.x * 256 + threadIdx.x;   // 256*288 total
    int n = idx / KPAD, k = idx % KPAD;
    float v = (k < D1) ? Wout[(size_t)k * D1 + n] : 0.f;
    Bh[idx] = __float2half_rn(v);
}

// ============ ov+od -> fp16 split + out[:,256] dot ==========================
__global__ void __launch_bounds__(256) conv_ov(
    const float* __restrict__ ov, const float* __restrict__ od,
    const float* __restrict__ Wout,
    __half* __restrict__ Ah, __half* __restrict__ Al,
    float* __restrict__ out)
{
    const int warp = threadIdx.x >> 5;
    const int lane = threadIdx.x & 31;
    const size_t r = (size_t)blockIdx.x * 8 + warp;
    float s = 0.f;
    #pragma unroll
    for (int i = 0; i < 9; i++) {
        int c = lane + i * 32;
        float v = 0.f;
        if (c < 256)       v = ov[r * 256 + c];
        else if (c == 256) v = od[r];
        __half h = __float2half_rn(v);
        __half l = __float2half_rn(v - __half2float(h));
        Ah[r * KPAD + c] = h;
        Al[r * KPAD + c] = l;
        if (c < D1) s = fmaf(v, Wout[(size_t)c * D1 + 256], s);
    }
    #pragma unroll
    for (int o = 16; o > 0; o >>= 1) s += __shfl_down_sync(0xffffffffu, s, o);
    if (lane == 0) out[r * D1 + 256] = s;
}

// ============ split-fp16 HMMA GEMM: BM=128 BN=128 BK=32, 3-stage =============
// 128 threads, 2x2 warps, 64x64 per warp — halves LDSM traffic per MMA.
#define BM 128
#define BN 128
#define BK 32
#define SPITCH 40                          // fp16 per smem row (padded)
#define MAT_BYTES (BM * SPITCH * 2)        // 10240
#define STAGE_BYTES (3 * MAT_BYTES)        // 30720 (Ah, Al, Bh)
#define NSTAGE 3
#define GEMM_SMEM (NSTAGE * STAGE_BYTES)   // 92160

__global__ void __launch_bounds__(128, 2) gemm_mma(
    const __half* __restrict__ Ah, const __half* __restrict__ Al,
    const __half* __restrict__ Bh,
    float* __restrict__ o0, float* __restrict__ o1, float* __restrict__ o2,
    float s0, float s1, float s2, int pitch)
{
    extern __shared__ char sm[];
    const int tid  = threadIdx.x;
    const int lane = tid & 31;
    const int wid  = tid >> 5;
    const int wm   = wid >> 1;             // 0..1
    const int wn   = wid & 1;              // 0..1
    const int nblk = blockIdx.x;
    const size_t m0 = (size_t)blockIdx.y * BM;
    const int sel = nblk >> 1;
    float* o = (sel == 0) ? o0 : (sel == 1) ? o1 : o2;
    const float scale = (sel == 0) ? s0 : (sel == 1) ? s1 : s2;
    const int ncol0 = (nblk & 1) * BN;
    const uint32_t sbase = smem_u32(sm);

    const __half* Bh_b = Bh + (size_t)nblk * BN * KPAD;

    // per-thread cp.async assignment (12 x 16B chunks / thread / stage)
    // id in [0,1536): mat = id>>9 (Ah,Al,Bh), i = id&511, row = i>>2, c = i&3
    auto load_stage = [&](int it, int buf) {
        const int kc = it * BK;
        #pragma unroll
        for (int t = 0; t < 12; t++) {
            int id = tid + t * 128;
            int mat = id >> 9;
            int i = id & 511;
            int row = i >> 2, c = i & 3;
            const __half* g;
            if      (mat == 0) g = Ah   + (m0 + row) * KPAD + kc + c * 8;
            else if (mat == 1) g = Al   + (m0 + row) * KPAD + kc + c * 8;
            else               g = Bh_b + (size_t)row * KPAD + kc + c * 8;
            uint32_t s = sbase + buf * STAGE_BYTES + mat * MAT_BYTES
                       + (uint32_t)(row * SPITCH + c * 8) * 2;
            cp16(s, g);
        }
        CP_COMMIT();
    };

    float acc[4][8][4];
    #pragma unroll
    for (int a = 0; a < 4; a++)
        #pragma unroll
        for (int b = 0; b < 8; b++)
            #pragma unroll
            for (int c = 0; c < 4; c++) acc[a][b][c] = 0.f;

    // ldmatrix per-lane byte offsets (within a matrix tile)
    const uint32_t a_off = (uint32_t)((wm * 64 + (lane & 15)) * SPITCH
                                      + ((lane >> 4) << 3)) * 2;
    const uint32_t b_off = (uint32_t)((wn * 64 + ((lane >> 4) << 3) + (lane & 7)) * SPITCH
                                      + (lane & 8)) * 2;

    load_stage(0, 0);
    load_stage(1, 1);

    for (int it = 0; it < KITERS; ++it) {
        CP_WAIT(1);            // stage `it` landed (stage it+1 may be in flight)
        __syncthreads();       // buffer (it-1)%3 free — safe to refill
        if (it + 2 < KITERS) load_stage(it + 2, (it + 2) % NSTAGE);
        else CP_COMMIT();      // keep group accounting exact

        const uint32_t st = sbase + (it % NSTAGE) * STAGE_BYTES;
        // last chunk: only k=256..271 carries data (272..287 are zero pad)
        const int nks = (it == KITERS - 1) ? 1 : 2;
        for (int ks = 0; ks < nks; ks++) {
            const uint32_t ko = ks * 32;   // 16 fp16 = 32 bytes
            uint32_t ah[4][4], al[4][4], bh[4][4];
            #pragma unroll
            for (int mi = 0; mi < 4; mi++) {
                uint32_t ao = a_off + (uint32_t)(mi * 16 * SPITCH) * 2 + ko;
                LDSM4(ah[mi], st + 0 * MAT_BYTES + ao);
                LDSM4(al[mi], st + 1 * MAT_BYTES + ao);
            }
            #pragma unroll
            for (int nj = 0; nj < 4; nj++) {
                uint32_t bo = b_off + (uint32_t)(nj * 16 * SPITCH) * 2 + ko;
                LDSM4(bh[nj], st + 2 * MAT_BYTES + bo);
            }
            #pragma unroll
            for (int mi = 0; mi < 4; mi++)
                #pragma unroll
                for (int ni = 0; ni < 8; ni++) {
                    uint32_t b0 = bh[ni >> 1][(ni & 1) * 2];
                    uint32_t b1 = bh[ni >> 1][(ni & 1) * 2 + 1];
                    MMA16816(acc[mi][ni], ah[mi], b0, b1);
                    MMA16816(acc[mi][ni], al[mi], b0, b1);
                }
        }
    }

    // ---- epilogue: warp tile 64x64 ----
    const int r0 = wm * 64 + (lane >> 2);
    const int c0 = ncol0 + wn * 64 + (lane & 3) * 2;
    if (pitch == DIMV) {
        #pragma unroll
        for (int mi = 0; mi < 4; mi++)
            #pragma unroll
            for (int ni = 0; ni < 8; ni++) {
                size_t row = m0 + r0 + mi * 16;
                int col = c0 + ni * 8;
                float2 v0 = {acc[mi][ni][0] * scale, acc[mi][ni][1] * scale};
                float2 v1 = {acc[mi][ni][2] * scale, acc[mi][ni][3] * scale};
                *reinterpret_cast<float2*>(&o[row * DIMV + col]) = v0;
                *reinterpret_cast<float2*>(&o[(row + 8) * DIMV + col]) = v1;
            }
    } else {
        #pragma unroll
        for (int mi = 0; mi < 4; mi++)
            #pragma unroll
            for (int ni = 0; ni < 8; ni++) {
                size_t row = m0 + r0 + mi * 16;
                int col = c0 + ni * 8;
                o[row * (size_t)pitch + col]           = acc[mi][ni][0] * scale;
                o[row * (size_t)pitch + col + 1]       = acc[mi][ni][1] * scale;
                o[(row + 8) * (size_t)pitch + col]     = acc[mi][ni][2] * scale;
                o[(row + 8) * (size_t)pitch + col + 1] = acc[mi][ni][3] * scale;
            }
    }
}

// ---------------- fused windowed attention ----------------------------------
#define SMEM_ATTN_FLOATS (32*65 + 32*65 + 64*32 + 64*65 + 64*65 + 64*65)
__global__ void __launch_bounds__(256) attn_kernel(
    const float* __restrict__ qv, const float* __restrict__ kv,
    const float* __restrict__ vv,
    const float* __restrict__ qd, const float* __restrict__ kd,
    const float* __restrict__ vd,
    float* __restrict__ ov, float* __restrict__ od)
{
    extern __shared__ float smem[];
    float* sqT  = smem;
    float* skT  = sqT + 32 * 65;
    float* sv   = skT + 32 * 65;
    float* gate = sv + 64 * 32;
    float* ssum = gate + 64 * 65;
    float* sc   = ssum + 64 * 65;
    __shared__ float s_qd[64], s_kd[64], s_vd[64];

    const int tid = threadIdx.x;
    const size_t row0 = (size_t)blockIdx.x * 64;

    if (tid < 64) {
        s_qd[tid] = qd[row0 + tid];
        s_kd[tid] = kd[row0 + tid];
        s_vd[tid] = vd[row0 + tid];
    }
    __syncthreads();

    for (int idx = tid; idx < 4096; idx += 256) {
        int i = idx >> 6, j = idx & 63;
        float z = s_qd[i] * s_kd[j];
        gate[i * 65 + j] = 1.f / (1.f + __expf(-z));
        ssum[i * 65 + j] = 0.f;
    }

    const int tm = (tid >> 4) << 2;
    const int tn = (tid & 15) << 2;
    const int srow = tid >> 2, ssub = tid & 3;
    const int sbase_i = srow * 65 + ssub * 16;
    const int pi0 = (tid >> 3) << 1;
    const int pd0 = (tid & 7) << 2;

    for (int h = 0; h < 8; h++) {
        __syncthreads();
        for (int idx = tid; idx < 2048; idx += 256) {
            int i = idx >> 5, d = idx & 31;
            size_t g = (row0 + i) * 256 + h * 32 + d;
            sqT[d * 65 + i] = qv[g];
            skT[d * 65 + i] = kv[g];
            sv[i * 32 + d]  = vv[g];
        }
        __syncthreads();

        float acc[4][4] = {};
        #pragma unroll 4
        for (int d = 0; d < 32; d++) {
            float a[4], b[4];
            #pragma unroll
            for (int i = 0; i < 4; i++) a[i] = sqT[d * 65 + tm + i];
            #pragma unroll
            for (int j = 0; j < 4; j++) b[j] = skT[d * 65 + tn + j];
            #pragma unroll
            for (int i = 0; i < 4; i++)
                #pragma unroll
                for (int j = 0; j < 4; j++)
                    acc[i][j] = fmaf(a[i], b[j], acc[i][j]);
        }
        #pragma unroll
        for (int i = 0; i < 4; i++)
            #pragma unroll
            for (int j = 0; j < 4; j++) {
                int o = (tm + i) * 65 + tn + j;
                float smv = acc[i][j] * gate[o];
                sc[o] = smv;
                ssum[o] += smv;
            }
        __syncthreads();

        // per-row softmax, 4 threads per row + quad shuffle reduce
        {
            float m = -1e30f;
            #pragma unroll
            for (int t = 0; t < 16; t++) m = fmaxf(m, sc[sbase_i + t]);
            m = fmaxf(m, __shfl_xor_sync(0xffffffffu, m, 1));
            m = fmaxf(m, __shfl_xor_sync(0xffffffffu, m, 2));
            float s = 0.f;
            float e16[16];
            #pragma unroll
            for (int t = 0; t < 16; t++) {
                float e = __expf(sc[sbase_i + t] - m);
                e16[t] = e;
                s += e;
            }
            s += __shfl_xor_sync(0xffffffffu, s, 1);
            s += __shfl_xor_sync(0xffffffffu, s, 2);
            float inv = 1.f / s;
            #pragma unroll
            for (int t = 0; t < 16; t++) sc[sbase_i + t] = e16[t] * inv;
        }
        __syncthreads();

        // PV: 2 rows x 4 dims per thread
        {
            float a0[4] = {}, a1[4] = {};
            #pragma unroll 8
            for (int j = 0; j < 64; j++) {
                float p0 = sc[pi0 * 65 + j];
                float p1 = sc[(pi0 + 1) * 65 + j];
                float4 v = *reinterpret_cast<const float4*>(&sv[j * 32 + pd0]);
                a0[0] = fmaf(p0, v.x, a0[0]); a0[1] = fmaf(p0, v.y, a0[1]);
                a0[2] = fmaf(p0, v.z, a0[2]); a0[3] = fmaf(p0, v.w, a0[3]);
                a1[0] = fmaf(p1, v.x, a1[0]); a1[1] = fmaf(p1, v.y, a1[1]);
                a1[2] = fmaf(p1, v.z, a1[2]); a1[3] = fmaf(p1, v.w, a1[3]);
            }
            size_t gb0 = (row0 + pi0) * 256 + h * 32 + pd0;
            size_t gb1 = (row0 + pi0 + 1) * 256 + h * 32 + pd0;
            float4 w0 = {a0[0], a0[1], a0[2], a0[3]};
            float4 w1 = {a1[0], a1[1], a1[2], a1[3]};
            *reinterpret_cast<float4*>(&ov[gb0]) = w0;
            *reinterpret_cast<float4*>(&ov[gb1]) = w1;
        }
    }

    __syncthreads();
    // depth attention softmax: 4 threads per row
    {
        float m = -1e30f;
        #pragma unroll
        for (int t = 0; t < 16; t++) m = fmaxf(m, ssum[sbase_i + t]);
        m = fmaxf(m, __shfl_xor_sync(0xffffffffu, m, 1));
        m = fmaxf(m, __shfl_xor_sync(0xffffffffu, m, 2));
        float s = 0.f, acc = 0.f;
        #pragma unroll
        for (int t = 0; t < 16; t++) {
            float e = __expf(ssum[sbase_i + t] - m);
            s += e;
            acc = fmaf(e, s_vd[ssub * 16 + t], acc);
        }
        s   += __shfl_xor_sync(0xffffffffu, s, 1);
        acc += __shfl_xor_sync(0xffffffffu, acc, 1);
        s   += __shfl_xor_sync(0xffffffffu, s, 2);
        acc += __shfl_xor_sync(0xffffffffu, acc, 2);
        if (ssub == 0) od[row0 + srow] = acc / s;
    }
}

// ---------------- launch -----------------------------------------------------
extern "C" void kernel_launch(void* const* d_in, const int* in_sizes, int n_in,
                              void* d_out, int out_size)
{
    const float* x    = (const float*)d_in[0];
    const float* Wqv  = (const float*)d_in[1];
    const float* Wkv  = (const float*)d_in[2];
    const float* Wvv  = (const float*)d_in[3];
    const float* Wqd  = (const float*)d_in[4];
    const float* Wkd  = (const float*)d_in[5];
    const float* Wvd  = (const float*)d_in[6];
    const float* Wout = (const float*)d_in[7];
    float* out = (float*)d_out;

    __half *Ah, *Al, *Bh, *BoH;
    float *qv, *kv, *vv, *ov, *qd, *kd, *vd, *od;
    cudaGetSymbolAddress((void**)&Ah,  g_Ah);
    cudaGetSymbolAddress((void**)&Al,  g_Al);
    cudaGetSymbolAddress((void**)&Bh,  g_Bh);
    cudaGetSymbolAddress((void**)&BoH, g_BoH);
    cudaGetSymbolAddress((void**)&qv,  g_qv);
    cudaGetSymbolAddress((void**)&kv,  g_kv);
    cudaGetSymbolAddress((void**)&vv,  g_vv);
    cudaGetSymbolAddress((void**)&ov,  g_ov);
    cudaGetSymbolAddress((void**)&qd,  g_qd);
    cudaGetSymbolAddress((void**)&kd,  g_kd);
    cudaGetSymbolAddress((void**)&vd,  g_vd);
    cudaGetSymbolAddress((void**)&od,  g_od);

    const int attn_smem = SMEM_ATTN_FLOATS * (int)sizeof(float);
    cudaFuncSetAttribute(attn_kernel,
                         cudaFuncAttributeMaxDynamicSharedMemorySize, attn_smem);
    cudaFuncSetAttribute(gemm_mma,
                         cudaFuncAttributeMaxDynamicSharedMemorySize, GEMM_SMEM);

    conv_w_qkv<<<768 * KPAD / 256, 256>>>(Wqv, Wkv, Wvv, Bh);
    conv_w_out<<<256 * KPAD / 256, 256>>>(Wout, BoH);
    conv_x_dproj<<<MROWS / 8, 256>>>(x, Wqd, Wkd, Wvd, Ah, Al, qd, kd, vd);

    gemm_mma<<<dim3(6, MROWS / BM), 128, GEMM_SMEM>>>(
        Ah, Al, Bh, qv, kv, vv, SCALE, 1.f, 1.f, DIMV);

    attn_kernel<<<NWIN, 256, attn_smem>>>(qv, kv, vv, qd, kd, vd, ov, od);

    conv_ov<<<MROWS / 8, 256>>>(ov, od, Wout, Ah, Al, out);

    gemm_mma<<<dim3(2, MROWS / BM), 128, GEMM_SMEM>>>(
        Ah, Al, BoH, out, out, out, 1.f, 1.f, 1.f, D1);
}

// round 7
// speedup vs baseline: 3.1769x; 1.2056x over previous
#include <cuda_runtime.h>
#include <cuda_fp16.h>
#include <cstdint>
#include <math.h>

#define MROWS 131072        // 2048 windows * 64 tokens
#define NWIN  2048
#define D1    257
#define DIMV  256
#define KPAD  288           // 257 padded to 9 chunks of 32
#define KITERS 9
#define SCALE 0.17677669529663687f   // 32^-0.5

// ======================= scratch (device globals) ===========================
__device__ __align__(256) __half g_Ah[(size_t)MROWS * KPAD];
__device__ __align__(256) __half g_Bh[768 * KPAD];
__device__ __align__(256) __half g_BoH[256 * KPAD];
__device__ float g_qv[(size_t)MROWS * DIMV];
__device__ float g_kv[(size_t)MROWS * DIMV];
__device__ float g_vv[(size_t)MROWS * DIMV];
__device__ float g_ov[(size_t)MROWS * DIMV];
__device__ float g_qd[MROWS];
__device__ float g_kd[MROWS];
__device__ float g_vd[MROWS];
__device__ float g_od[MROWS];

// ======================= PTX helpers =========================================
__device__ __forceinline__ uint32_t smem_u32(const void* p) {
    uint32_t a;
    asm("{ .reg .u64 t; cvta.to.shared.u64 t, %1; cvt.u32.u64 %0, t; }"
        : "=r"(a) : "l"(p));
    return a;
}
__device__ __forceinline__ void cp16(uint32_t s, const void* g) {
    asm volatile("cp.async.ca.shared.global [%0], [%1], 16;" :: "r"(s), "l"(g));
}
#define CP_COMMIT()  asm volatile("cp.async.commit_group;" ::: "memory")
#define CP_WAIT(n)   asm volatile("cp.async.wait_group %0;" :: "n"(n) : "memory")

#define LDSM4(r, addr) \
    asm volatile("ldmatrix.sync.aligned.m8n8.x4.shared.b16 {%0,%1,%2,%3}, [%4];" \
        : "=r"((r)[0]), "=r"((r)[1]), "=r"((r)[2]), "=r"((r)[3]) : "r"(addr))

#define MMA16816(c, a, b0v, b1v) \
    asm volatile("mma.sync.aligned.m16n8k16.row.col.f32.f16.f16.f32 " \
        "{%0,%1,%2,%3}, {%4,%5,%6,%7}, {%8,%9}, {%0,%1,%2,%3};" \
        : "+f"((c)[0]), "+f"((c)[1]), "+f"((c)[2]), "+f"((c)[3]) \
        : "r"((a)[0]), "r"((a)[1]), "r"((a)[2]), "r"((a)[3]), "r"(b0v), "r"(b1v))

// ============ conv_x + depth projections (warp per row) =====================
__global__ void __launch_bounds__(256) conv_x_dproj(
    const float* __restrict__ X,
    const float* __restrict__ Wq, const float* __restrict__ Wk,
    const float* __restrict__ Wv,
    __half* __restrict__ Ah,
    float* __restrict__ qd, float* __restrict__ kd, float* __restrict__ vd)
{
    const int warp = threadIdx.x >> 5;
    const int lane = threadIdx.x & 31;
    const size_t r = (size_t)blockIdx.x * 8 + warp;
    const float* xr = X + r * D1;
    float sq = 0.f, sk = 0.f, sv = 0.f;
    #pragma unroll
    for (int i = 0; i < 9; i++) {
        int c = lane + i * 32;
        float v = (c < D1) ? xr[c] : 0.f;
        Ah[r * KPAD + c] = __float2half_rn(v);
        if (c < D1) {
            sq = fmaf(v, Wq[c], sq);
            sk = fmaf(v, Wk[c], sk);
            sv = fmaf(v, Wv[c], sv);
        }
    }
    #pragma unroll
    for (int o = 16; o > 0; o >>= 1) {
        sq += __shfl_down_sync(0xffffffffu, sq, o);
        sk += __shfl_down_sync(0xffffffffu, sk, o);
        sv += __shfl_down_sync(0xffffffffu, sv, o);
    }
    if (lane == 0) { qd[r] = sq * SCALE; kd[r] = sk; vd[r] = sv; }
}

// ============ QKV weight transpose: B[n,k] = fp16(W[k, n%256]) ==============
__global__ void __launch_bounds__(256) conv_w_qkv(
    const float* __restrict__ Wqv, const float* __restrict__ Wkv,
    const float* __restrict__ Wvv, __half* __restrict__ Bh)
{
    int idx = blockIdx.x * 256 + threadIdx.x;   // 768*288 total
    int n = idx / KPAD, k = idx % KPAD;
    const float* W = (n < 256) ? Wqv : (n < 512) ? Wkv : Wvv;
    float v = (k < D1) ? W[(size_t)k * DIMV + (n & 255)] : 0.f;
    Bh[idx] = __float2half_rn(v);
}

// ============ Wout transpose: B[n,k] = fp16(Wout[k, n]) =====================
__global__ void __launch_bounds__(256) conv_w_out(
    const float* __restrict__ Wout, __half* __restrict__ Bh)
{
    int idx = blockIdx.x * 256 + threadIdx.x;   // 256*288 total
    int n = idx / KPAD, k = idx % KPAD;
    float v = (k < D1) ? Wout[(size_t)k * D1 + n] : 0.f;
    Bh[idx] = __float2half_rn(v);
}

// ============ ov+od -> fp16 + out[:,256] dot ================================
__global__ void __launch_bounds__(256) conv_ov(
    const float* __restrict__ ov, const float* __restrict__ od,
    const float* __restrict__ Wout,
    __half* __restrict__ Ah, float* __restrict__ out)
{
    const int warp = threadIdx.x >> 5;
    const int lane = threadIdx.x & 31;
    const size_t r = (size_t)blockIdx.x * 8 + warp;
    float s = 0.f;
    #pragma unroll
    for (int i = 0; i < 9; i++) {
        int c = lane + i * 32;
        float v = 0.f;
        if (c < 256)       v = ov[r * 256 + c];
        else if (c == 256) v = od[r];
        Ah[r * KPAD + c] = __float2half_rn(v);
        if (c < D1) s = fmaf(v, Wout[(size_t)c * D1 + 256], s);
    }
    #pragma unroll
    for (int o = 16; o > 0; o >>= 1) s += __shfl_down_sync(0xffffffffu, s, o);
    if (lane == 0) out[r * D1 + 256] = s;
}

// ============ fp16 HMMA GEMM: BM=128 BN=128 BK=32, 3-stage, 2 CTA/SM ========
#define BM 128
#define BN 128
#define BK 32
#define SPITCH 40                          // fp16 per smem row (padded)
#define MAT_BYTES (BM * SPITCH * 2)        // 10240
#define STAGE_BYTES (2 * MAT_BYTES)        // 20480 (Ah, Bh)
#define NSTAGE 3
#define GEMM_SMEM (NSTAGE * STAGE_BYTES)   // 61440

__global__ void __launch_bounds__(256, 2) gemm_mma(
    const __half* __restrict__ Ah, const __half* __restrict__ Bh,
    float* __restrict__ o0, float* __restrict__ o1, float* __restrict__ o2,
    float s0, float s1, float s2, int pitch)
{
    extern __shared__ char sm[];
    const int tid  = threadIdx.x;
    const int lane = tid & 31;
    const int wid  = tid >> 5;
    const int wm   = wid >> 2;             // 0..1
    const int wn   = wid & 3;              // 0..3
    const int nblk = blockIdx.x;
    const size_t m0 = (size_t)blockIdx.y * BM;
    const int sel = nblk >> 1;
    float* o = (sel == 0) ? o0 : (sel == 1) ? o1 : o2;
    const float scale = (sel == 0) ? s0 : (sel == 1) ? s1 : s2;
    const int ncol0 = (nblk & 1) * BN;
    const uint32_t sbase = smem_u32(sm);

    const __half* Bh_b = Bh + (size_t)nblk * BN * KPAD;

    // per-thread cp.async assignment (4 x 16B chunks / thread / stage)
    // id in [0,1024): mat = id>>9 (Ah,Bh), i = id&511, row = i>>2, c = i&3
    auto load_stage = [&](int it, int buf) {
        const int kc = it * BK;
        #pragma unroll
        for (int t = 0; t < 4; t++) {
            int id = tid + t * 256;
            int mat = id >> 9;
            int i = id & 511;
            int row = i >> 2, c = i & 3;
            const __half* g;
            if (mat == 0) g = Ah   + (m0 + row) * KPAD + kc + c * 8;
            else          g = Bh_b + (size_t)row * KPAD + kc + c * 8;
            uint32_t s = sbase + buf * STAGE_BYTES + mat * MAT_BYTES
                       + (uint32_t)(row * SPITCH + c * 8) * 2;
            cp16(s, g);
        }
        CP_COMMIT();
    };

    float acc[4][4][4];
    #pragma unroll
    for (int a = 0; a < 4; a++)
        #pragma unroll
        for (int b = 0; b < 4; b++)
            #pragma unroll
            for (int c = 0; c < 4; c++) acc[a][b][c] = 0.f;

    // ldmatrix per-lane byte offsets (within a matrix tile)
    const uint32_t a_off = (uint32_t)((wm * 64 + (lane & 15)) * SPITCH
                                      + ((lane >> 4) << 3)) * 2;
    const uint32_t b_off = (uint32_t)((wn * 32 + ((lane >> 4) << 3) + (lane & 7)) * SPITCH
                                      + (lane & 8)) * 2;

    load_stage(0, 0);
    load_stage(1, 1);

    for (int it = 0; it < KITERS; ++it) {
        CP_WAIT(1);            // stage `it` landed (stage it+1 may be in flight)
        __syncthreads();       // buffer (it-1)%3 free — safe to refill
        if (it + 2 < KITERS) load_stage(it + 2, (it + 2) % NSTAGE);
        else CP_COMMIT();      // keep group accounting exact

        const uint32_t st = sbase + (it % NSTAGE) * STAGE_BYTES;
        // last chunk: only k=256..271 carries data (272..287 are zero pad)
        const int nks = (it == KITERS - 1) ? 1 : 2;
        for (int ks = 0; ks < nks; ks++) {
            const uint32_t ko = ks * 32;   // 16 fp16 = 32 bytes
            uint32_t ah[4][4], bh[2][4];
            #pragma unroll
            for (int mi = 0; mi < 4; mi++) {
                uint32_t ao = a_off + (uint32_t)(mi * 16 * SPITCH) * 2 + ko;
                LDSM4(ah[mi], st + 0 * MAT_BYTES + ao);
            }
            #pragma unroll
            for (int nj = 0; nj < 2; nj++) {
                uint32_t bo = b_off + (uint32_t)(nj * 16 * SPITCH) * 2 + ko;
                LDSM4(bh[nj], st + 1 * MAT_BYTES + bo);
            }
            #pragma unroll
            for (int mi = 0; mi < 4; mi++)
                #pragma unroll
                for (int ni = 0; ni < 4; ni++) {
                    uint32_t b0 = bh[ni >> 1][(ni & 1) * 2];
                    uint32_t b1 = bh[ni >> 1][(ni & 1) * 2 + 1];
                    MMA16816(acc[mi][ni], ah[mi], b0, b1);
                }
        }
    }

    // ---- epilogue: warp tile 64x32 ----
    const int r0 = wm * 64 + (lane >> 2);
    const int c0 = ncol0 + wn * 32 + (lane & 3) * 2;
    if (pitch == DIMV) {
        #pragma unroll
        for (int mi = 0; mi < 4; mi++)
            #pragma unroll
            for (int ni = 0; ni < 4; ni++) {
                size_t row = m0 + r0 + mi * 16;
                int col = c0 + ni * 8;
                float2 v0 = {acc[mi][ni][0] * scale, acc[mi][ni][1] * scale};
                float2 v1 = {acc[mi][ni][2] * scale, acc[mi][ni][3] * scale};
                *reinterpret_cast<float2*>(&o[row * DIMV + col]) = v0;
                *reinterpret_cast<float2*>(&o[(row + 8) * DIMV + col]) = v1;
            }
    } else {
        #pragma unroll
        for (int mi = 0; mi < 4; mi++)
            #pragma unroll
            for (int ni = 0; ni < 4; ni++) {
                size_t row = m0 + r0 + mi * 16;
                int col = c0 + ni * 8;
                o[row * (size_t)pitch + col]           = acc[mi][ni][0] * scale;
                o[row * (size_t)pitch + col + 1]       = acc[mi][ni][1] * scale;
                o[(row + 8) * (size_t)pitch + col]     = acc[mi][ni][2] * scale;
                o[(row + 8) * (size_t)pitch + col + 1] = acc[mi][ni][3] * scale;
            }
    }
}

// ---------------- fused windowed attention ----------------------------------
#define SMEM_ATTN_FLOATS (32*65 + 32*65 + 64*32 + 64*65 + 64*65 + 64*65)
__global__ void __launch_bounds__(256) attn_kernel(
    const float* __restrict__ qv, const float* __restrict__ kv,
    const float* __restrict__ vv,
    const float* __restrict__ qd, const float* __restrict__ kd,
    const float* __restrict__ vd,
    float* __restrict__ ov, float* __restrict__ od)
{
    extern __shared__ float smem[];
    float* sqT  = smem;
    float* skT  = sqT + 32 * 65;
    float* sv   = skT + 32 * 65;
    float* gate = sv + 64 * 32;
    float* ssum = gate + 64 * 65;
    float* sc   = ssum + 64 * 65;
    __shared__ float s_qd[64], s_kd[64], s_vd[64];

    const int tid = threadIdx.x;
    const size_t row0 = (size_t)blockIdx.x * 64;

    if (tid < 64) {
        s_qd[tid] = qd[row0 + tid];
        s_kd[tid] = kd[row0 + tid];
        s_vd[tid] = vd[row0 + tid];
    }
    __syncthreads();

    for (int idx = tid; idx < 4096; idx += 256) {
        int i = idx >> 6, j = idx & 63;
        float z = s_qd[i] * s_kd[j];
        gate[i * 65 + j] = 1.f / (1.f + __expf(-z));
        ssum[i * 65 + j] = 0.f;
    }

    const int tm = (tid >> 4) << 2;
    const int tn = (tid & 15) << 2;
    const int srow = tid >> 2, ssub = tid & 3;
    const int sbase_i = srow * 65 + ssub * 16;
    const int pi0 = (tid >> 3) << 1;
    const int pd0 = (tid & 7) << 2;

    for (int h = 0; h < 8; h++) {
        __syncthreads();
        for (int idx = tid; idx < 2048; idx += 256) {
            int i = idx >> 5, d = idx & 31;
            size_t g = (row0 + i) * 256 + h * 32 + d;
            sqT[d * 65 + i] = qv[g];
            skT[d * 65 + i] = kv[g];
            sv[i * 32 + d]  = vv[g];
        }
        __syncthreads();

        float acc[4][4] = {};
        #pragma unroll 4
        for (int d = 0; d < 32; d++) {
            float a[4], b[4];
            #pragma unroll
            for (int i = 0; i < 4; i++) a[i] = sqT[d * 65 + tm + i];
            #pragma unroll
            for (int j = 0; j < 4; j++) b[j] = skT[d * 65 + tn + j];
            #pragma unroll
            for (int i = 0; i < 4; i++)
                #pragma unroll
                for (int j = 0; j < 4; j++)
                    acc[i][j] = fmaf(a[i], b[j], acc[i][j]);
        }
        #pragma unroll
        for (int i = 0; i < 4; i++)
            #pragma unroll
            for (int j = 0; j < 4; j++) {
                int o = (tm + i) * 65 + tn + j;
                float smv = acc[i][j] * gate[o];
                sc[o] = smv;
                ssum[o] += smv;
            }
        __syncthreads();

        // per-row softmax, 4 threads per row + quad shuffle reduce
        {
            float m = -1e30f;
            #pragma unroll
            for (int t = 0; t < 16; t++) m = fmaxf(m, sc[sbase_i + t]);
            m = fmaxf(m, __shfl_xor_sync(0xffffffffu, m, 1));
            m = fmaxf(m, __shfl_xor_sync(0xffffffffu, m, 2));
            float s = 0.f;
            float e16[16];
            #pragma unroll
            for (int t = 0; t < 16; t++) {
                float e = __expf(sc[sbase_i + t] - m);
                e16[t] = e;
                s += e;
            }
            s += __shfl_xor_sync(0xffffffffu, s, 1);
            s += __shfl_xor_sync(0xffffffffu, s, 2);
            float inv = 1.f / s;
            #pragma unroll
            for (int t = 0; t < 16; t++) sc[sbase_i + t] = e16[t] * inv;
        }
        __syncthreads();

        // PV: 2 rows x 4 dims per thread
        {
            float a0[4] = {}, a1[4] = {};
            #pragma unroll 8
            for (int j = 0; j < 64; j++) {
                float p0 = sc[pi0 * 65 + j];
                float p1 = sc[(pi0 + 1) * 65 + j];
                float4 v = *reinterpret_cast<const float4*>(&sv[j * 32 + pd0]);
                a0[0] = fmaf(p0, v.x, a0[0]); a0[1] = fmaf(p0, v.y, a0[1]);
                a0[2] = fmaf(p0, v.z, a0[2]); a0[3] = fmaf(p0, v.w, a0[3]);
                a1[0] = fmaf(p1, v.x, a1[0]); a1[1] = fmaf(p1, v.y, a1[1]);
                a1[2] = fmaf(p1, v.z, a1[2]); a1[3] = fmaf(p1, v.w, a1[3]);
            }
            size_t gb0 = (row0 + pi0) * 256 + h * 32 + pd0;
            size_t gb1 = (row0 + pi0 + 1) * 256 + h * 32 + pd0;
            float4 w0 = {a0[0], a0[1], a0[2], a0[3]};
            float4 w1 = {a1[0], a1[1], a1[2], a1[3]};
            *reinterpret_cast<float4*>(&ov[gb0]) = w0;
            *reinterpret_cast<float4*>(&ov[gb1]) = w1;
        }
    }

    __syncthreads();
    // depth attention softmax: 4 threads per row
    {
        float m = -1e30f;
        #pragma unroll
        for (int t = 0; t < 16; t++) m = fmaxf(m, ssum[sbase_i + t]);
        m = fmaxf(m, __shfl_xor_sync(0xffffffffu, m, 1));
        m = fmaxf(m, __shfl_xor_sync(0xffffffffu, m, 2));
        float s = 0.f, acc = 0.f;
        #pragma unroll
        for (int t = 0; t < 16; t++) {
            float e = __expf(ssum[sbase_i + t] - m);
            s += e;
            acc = fmaf(e, s_vd[ssub * 16 + t], acc);
        }
        s   += __shfl_xor_sync(0xffffffffu, s, 1);
        acc += __shfl_xor_sync(0xffffffffu, acc, 1);
        s   += __shfl_xor_sync(0xffffffffu, s, 2);
        acc += __shfl_xor_sync(0xffffffffu, acc, 2);
        if (ssub == 0) od[row0 + srow] = acc / s;
    }
}

// ---------------- launch -----------------------------------------------------
extern "C" void kernel_launch(void* const* d_in, const int* in_sizes, int n_in,
                              void* d_out, int out_size)
{
    const float* x    = (const float*)d_in[0];
    const float* Wqv  = (const float*)d_in[1];
    const float* Wkv  = (const float*)d_in[2];
    const float* Wvv  = (const float*)d_in[3];
    const float* Wqd  = (const float*)d_in[4];
    const float* Wkd  = (const float*)d_in[5];
    const float* Wvd  = (const float*)d_in[6];
    const float* Wout = (const float*)d_in[7];
    float* out = (float*)d_out;

    __half *Ah, *Bh, *BoH;
    float *qv, *kv, *vv, *ov, *qd, *kd, *vd, *od;
    cudaGetSymbolAddress((void**)&Ah,  g_Ah);
    cudaGetSymbolAddress((void**)&Bh,  g_Bh);
    cudaGetSymbolAddress((void**)&BoH, g_BoH);
    cudaGetSymbolAddress((void**)&qv,  g_qv);
    cudaGetSymbolAddress((void**)&kv,  g_kv);
    cudaGetSymbolAddress((void**)&vv,  g_vv);
    cudaGetSymbolAddress((void**)&ov,  g_ov);
    cudaGetSymbolAddress((void**)&qd,  g_qd);
    cudaGetSymbolAddress((void**)&kd,  g_kd);
    cudaGetSymbolAddress((void**)&vd,  g_vd);
    cudaGetSymbolAddress((void**)&od,  g_od);

    const int attn_smem = SMEM_ATTN_FLOATS * (int)sizeof(float);
    cudaFuncSetAttribute(attn_kernel,
                         cudaFuncAttributeMaxDynamicSharedMemorySize, attn_smem);
    cudaFuncSetAttribute(gemm_mma,
                         cudaFuncAttributeMaxDynamicSharedMemorySize, GEMM_SMEM);

    conv_w_qkv<<<768 * KPAD / 256, 256>>>(Wqv, Wkv, Wvv, Bh);
    conv_w_out<<<256 * KPAD / 256, 256>>>(Wout, BoH);
    conv_x_dproj<<<MROWS / 8, 256>>>(x, Wqd, Wkd, Wvd, Ah, qd, kd, vd);

    gemm_mma<<<dim3(6, MROWS / BM), 256, GEMM_SMEM>>>(
        Ah, Bh, qv, kv, vv, SCALE, 1.f, 1.f, DIMV);

    attn_kernel<<<NWIN, 256, attn_smem>>>(qv, kv, vv, qd, kd, vd, ov, od);

    conv_ov<<<MROWS / 8, 256>>>(ov, od, Wout, Ah, out);

    gemm_mma<<<dim3(2, MROWS / BM), 256, GEMM_SMEM>>>(
        Ah, BoH, out, out, out, 1.f, 1.f, 1.f, D1);
}

// round 9
// speedup vs baseline: 5.1461x; 1.6199x over previous
#include <cuda_runtime.h>
#include <cuda_fp16.h>
#include <cstdint>
#include <math.h>

#define MROWS 131072        // 2048 windows * 64 tokens
#define NWIN  2048
#define D1    257
#define DIMV  256
#define KPAD  288           // 257 padded to 9 chunks of 32
#define KITERS 9
#define SCALE 0.17677669529663687f   // 32^-0.5

// ======================= scratch (device globals) ===========================
__device__ __align__(256) __half g_Ah[(size_t)MROWS * KPAD];
__device__ __align__(256) __half g_Bh[768 * KPAD];
__device__ __align__(256) __half g_BoH[256 * KPAD];
__device__ __align__(256) __half g_qvh[(size_t)MROWS * DIMV];
__device__ __align__(256) __half g_kvh[(size_t)MROWS * DIMV];
__device__ __align__(256) __half g_vvh[(size_t)MROWS * DIMV];
__device__ float g_qd[MROWS];
__device__ float g_kd[MROWS];
__device__ float g_vd[MROWS];

// ======================= PTX helpers =========================================
__device__ __forceinline__ uint32_t smem_u32(const void* p) {
    uint32_t a;
    asm("{ .reg .u64 t; cvta.to.shared.u64 t, %1; cvt.u32.u64 %0, t; }"
        : "=r"(a) : "l"(p));
    return a;
}
__device__ __forceinline__ void cp16(uint32_t s, const void* g) {
    asm volatile("cp.async.ca.shared.global [%0], [%1], 16;" :: "r"(s), "l"(g));
}
#define CP_COMMIT()  asm volatile("cp.async.commit_group;" ::: "memory")
#define CP_WAIT(n)   asm volatile("cp.async.wait_group %0;" :: "n"(n) : "memory")

#define LDSM4(r, addr) \
    asm volatile("ldmatrix.sync.aligned.m8n8.x4.shared.b16 {%0,%1,%2,%3}, [%4];" \
        : "=r"((r)[0]), "=r"((r)[1]), "=r"((r)[2]), "=r"((r)[3]) : "r"(addr))

#define LDSM2T(r, addr) \
    asm volatile("ldmatrix.sync.aligned.m8n8.x2.trans.shared.b16 {%0,%1}, [%2];" \
        : "=r"((r)[0]), "=r"((r)[1]) : "r"(addr))

#define MMA16816(c, a, b0v, b1v) \
    asm volatile("mma.sync.aligned.m16n8k16.row.col.f32.f16.f16.f32 " \
        "{%0,%1,%2,%3}, {%4,%5,%6,%7}, {%8,%9}, {%0,%1,%2,%3};" \
        : "+f"((c)[0]), "+f"((c)[1]), "+f"((c)[2]), "+f"((c)[3]) \
        : "r"((a)[0]), "r"((a)[1]), "r"((a)[2]), "r"((a)[3]), "r"(b0v), "r"(b1v))

__device__ __forceinline__ uint32_t packh2(float a, float b) {
    __half2 h = __floats2half2_rn(a, b);
    return *reinterpret_cast<uint32_t*>(&h);
}

// ============ conv_x + depth projections (warp per row) =====================
__global__ void __launch_bounds__(256) conv_x_dproj(
    const float* __restrict__ X,
    const float* __restrict__ Wq, const float* __restrict__ Wk,
    const float* __restrict__ Wv,
    __half* __restrict__ Ah,
    float* __restrict__ qd, float* __restrict__ kd, float* __restrict__ vd)
{
    const int warp = threadIdx.x >> 5;
    const int lane = threadIdx.x & 31;
    const size_t r = (size_t)blockIdx.x * 8 + warp;
    const float* xr = X + r * D1;
    float sq = 0.f, sk = 0.f, sv = 0.f;
    #pragma unroll
    for (int i = 0; i < 9; i++) {
        int c = lane + i * 32;
        float v = (c < D1) ? xr[c] : 0.f;
        Ah[r * KPAD + c] = __float2half_rn(v);
        if (c < D1) {
            sq = fmaf(v, Wq[c], sq);
            sk = fmaf(v, Wk[c], sk);
            sv = fmaf(v, Wv[c], sv);
        }
    }
    #pragma unroll
    for (int o = 16; o > 0; o >>= 1) {
        sq += __shfl_down_sync(0xffffffffu, sq, o);
        sk += __shfl_down_sync(0xffffffffu, sk, o);
        sv += __shfl_down_sync(0xffffffffu, sv, o);
    }
    if (lane == 0) { qd[r] = sq * SCALE; kd[r] = sk; vd[r] = sv; }
}

// ============ QKV weight transpose: B[n,k] = fp16(W[k, n%256]) ==============
__global__ void __launch_bounds__(256) conv_w_qkv(
    const float* __restrict__ Wqv, const float* __restrict__ Wkv,
    const float* __restrict__ Wvv, __half* __restrict__ Bh)
{
    int idx = blockIdx.x * 256 + threadIdx.x;   // 768*288 total
    int n = idx / KPAD, k = idx % KPAD;
    const float* W = (n < 256) ? Wqv : (n < 512) ? Wkv : Wvv;
    float v = (k < D1) ? W[(size_t)k * DIMV + (n & 255)] : 0.f;
    Bh[idx] = __float2half_rn(v);
}

// ============ Wout transpose: B[n,k] = fp16(Wout[k, n]) =====================
__global__ void __launch_bounds__(256) conv_w_out(
    const float* __restrict__ Wout, __half* __restrict__ Bh)
{
    int idx = blockIdx.x * 256 + threadIdx.x;   // 256*288 total
    int n = idx / KPAD, k = idx % KPAD;
    float v = (k < D1) ? Wout[(size_t)k * D1 + n] : 0.f;
    Bh[idx] = __float2half_rn(v);
}

// ============ fp16 HMMA GEMM: BM=128 BN=128 BK=32, 3-stage, 2 CTA/SM ========
#define BM 128
#define BN 128
#define BK 32
#define SPITCH 40
#define MAT_BYTES (BM * SPITCH * 2)        // 10240
#define STAGE_BYTES (2 * MAT_BYTES)        // 20480
#define NSTAGE 3
#define GEMM_SMEM (NSTAGE * STAGE_BYTES)   // 61440

__global__ void __launch_bounds__(256, 2) gemm_mma(
    const __half* __restrict__ A, const __half* __restrict__ B,
    void* __restrict__ o0, void* __restrict__ o1, void* __restrict__ o2,
    float s0, float s1, float s2, int pitch, int half_out)
{
    extern __shared__ char sm[];
    const int tid  = threadIdx.x;
    const int lane = tid & 31;
    const int wid  = tid >> 5;
    const int wm   = wid >> 2;
    const int wn   = wid & 3;
    const int nblk = blockIdx.x;
    const size_t m0 = (size_t)blockIdx.y * BM;
    const int sel = nblk >> 1;
    void* ov = (sel == 0) ? o0 : (sel == 1) ? o1 : o2;
    const float scale = (sel == 0) ? s0 : (sel == 1) ? s1 : s2;
    const int ncol0 = (nblk & 1) * BN;
    const uint32_t sbase = smem_u32(sm);

    const __half* B_b = B + (size_t)nblk * BN * KPAD;

    auto load_stage = [&](int it, int buf) {
        const int kc = it * BK;
        #pragma unroll
        for (int t = 0; t < 4; t++) {
            int id = tid + t * 256;
            int mat = id >> 9;
            int i = id & 511;
            int row = i >> 2, c = i & 3;
            const __half* g;
            if (mat == 0) g = A   + (m0 + row) * KPAD + kc + c * 8;
            else          g = B_b + (size_t)row * KPAD + kc + c * 8;
            uint32_t s = sbase + buf * STAGE_BYTES + mat * MAT_BYTES
                       + (uint32_t)(row * SPITCH + c * 8) * 2;
            cp16(s, g);
        }
        CP_COMMIT();
    };

    float acc[4][4][4];
    #pragma unroll
    for (int a = 0; a < 4; a++)
        #pragma unroll
        for (int b = 0; b < 4; b++)
            #pragma unroll
            for (int c = 0; c < 4; c++) acc[a][b][c] = 0.f;

    const uint32_t a_off = (uint32_t)((wm * 64 + (lane & 15)) * SPITCH
                                      + ((lane >> 4) << 3)) * 2;
    const uint32_t b_off = (uint32_t)((wn * 32 + ((lane >> 4) << 3) + (lane & 7)) * SPITCH
                                      + (lane & 8)) * 2;

    load_stage(0, 0);
    load_stage(1, 1);

    for (int it = 0; it < KITERS; ++it) {
        CP_WAIT(1);
        __syncthreads();
        if (it + 2 < KITERS) load_stage(it + 2, (it + 2) % NSTAGE);
        else CP_COMMIT();

        const uint32_t st = sbase + (it % NSTAGE) * STAGE_BYTES;
        const int nks = (it == KITERS - 1) ? 1 : 2;
        for (int ks = 0; ks < nks; ks++) {
            const uint32_t ko = ks * 32;
            uint32_t ah[4][4], bh[2][4];
            #pragma unroll
            for (int mi = 0; mi < 4; mi++) {
                uint32_t ao = a_off + (uint32_t)(mi * 16 * SPITCH) * 2 + ko;
                LDSM4(ah[mi], st + 0 * MAT_BYTES + ao);
            }
            #pragma unroll
            for (int nj = 0; nj < 2; nj++) {
                uint32_t bo = b_off + (uint32_t)(nj * 16 * SPITCH) * 2 + ko;
                LDSM4(bh[nj], st + 1 * MAT_BYTES + bo);
            }
            #pragma unroll
            for (int mi = 0; mi < 4; mi++)
                #pragma unroll
                for (int ni = 0; ni < 4; ni++) {
                    uint32_t b0 = bh[ni >> 1][(ni & 1) * 2];
                    uint32_t b1 = bh[ni >> 1][(ni & 1) * 2 + 1];
                    MMA16816(acc[mi][ni], ah[mi], b0, b1);
                }
        }
    }

    const int r0 = wm * 64 + (lane >> 2);
    const int c0 = ncol0 + wn * 32 + (lane & 3) * 2;
    if (half_out) {
        __half* o = (__half*)ov;
        #pragma unroll
        for (int mi = 0; mi < 4; mi++)
            #pragma unroll
            for (int ni = 0; ni < 4; ni++) {
                size_t row = m0 + r0 + mi * 16;
                int col = c0 + ni * 8;
                *(uint32_t*)&o[row * DIMV + col] =
                    packh2(acc[mi][ni][0] * scale, acc[mi][ni][1] * scale);
                *(uint32_t*)&o[(row + 8) * DIMV + col] =
                    packh2(acc[mi][ni][2] * scale, acc[mi][ni][3] * scale);
            }
    } else {
        float* o = (float*)ov;
        #pragma unroll
        for (int mi = 0; mi < 4; mi++)
            #pragma unroll
            for (int ni = 0; ni < 4; ni++) {
                size_t row = m0 + r0 + mi * 16;
                int col = c0 + ni * 8;
                o[row * (size_t)pitch + col]           = acc[mi][ni][0] * scale;
                o[row * (size_t)pitch + col + 1]       = acc[mi][ni][1] * scale;
                o[(row + 8) * (size_t)pitch + col]     = acc[mi][ni][2] * scale;
                o[(row + 8) * (size_t)pitch + col + 1] = acc[mi][ni][3] * scale;
            }
    }
}

// ============ fused MMA attention: 1 window/CTA, 128 thr, warp = 16 rows ====
#define APITCH 264     // halves per row (256 + 8 pad): conflict-free LDSM
#define ATTN_HALVES (3 * 64 * APITCH + 64 * 66)
#define ATTN_SMEM   (ATTN_HALVES * 2 + (64 * 3 + 260) * 4)

__global__ void __launch_bounds__(128, 2) attn_mma(
    const __half* __restrict__ qv, const __half* __restrict__ kv,
    const __half* __restrict__ vv,
    const float* __restrict__ qd, const float* __restrict__ kd,
    const float* __restrict__ vd, const float* __restrict__ Wout,
    __half* __restrict__ Ah, float* __restrict__ out)
{
    extern __shared__ char sm[];
    __half* sq    = (__half*)sm;                 // [64][APITCH]
    __half* sk    = sq + 64 * APITCH;
    __half* sv    = sk + 64 * APITCH;
    __half* sgate = sv + 64 * APITCH;            // [64][66]
    float*  s_qd  = (float*)(sm + ATTN_HALVES * 2);
    float*  s_kd  = s_qd + 64;
    float*  s_vd  = s_kd + 64;
    float*  s_w   = s_vd + 64;                   // Wout[:,256], 257 floats

    const int tid  = threadIdx.x;
    const int lane = tid & 31;
    const int wid  = tid >> 5;
    const int g    = lane >> 2;
    const int tig  = lane & 3;
    const size_t r0 = (size_t)blockIdx.x * 64;

    // ---- cooperative load: q/k/v (fp16, 64 rows x 256 halves = 2048 uint4) ----
    {
        const uint4* gq = (const uint4*)(qv + r0 * DIMV);
        const uint4* gk = (const uint4*)(kv + r0 * DIMV);
        const uint4* gv = (const uint4*)(vv + r0 * DIMV);
        for (int i = tid; i < 2048; i += 128) {
            int row = i >> 5, c = i & 31;            // 32 x 8 halves = 256/row
            uint32_t off = (uint32_t)(row * APITCH * 2 + c * 16);
            *(uint4*)((char*)sq + off) = gq[i];
            *(uint4*)((char*)sk + off) = gk[i];
            *(uint4*)((char*)sv + off) = gv[i];
        }
        if (tid < 64) {
            s_qd[tid] = qd[r0 + tid];
            s_kd[tid] = kd[r0 + tid];
            s_vd[tid] = vd[r0 + tid];
        }
        for (int i = tid; i < 257; i += 128)
            s_w[i] = Wout[(size_t)i * D1 + 256];
    }
    __syncthreads();

    // ---- gate table (head-invariant): sigmoid(qd_i * kd_j), fp16 ----
    for (int i = tid; i < 4096; i += 128) {
        int ii = i >> 6, jj = i & 63;
        float z = s_qd[ii] * s_kd[jj];
        sgate[ii * 66 + jj] = __float2half_rn(1.f / (1.f + __expf(-z)));
    }
    __syncthreads();

    const uint32_t sq_u = smem_u32(sq);
    const uint32_t sk_u = smem_u32(sk);
    const uint32_t sv_u = smem_u32(sv);
    const int mrow = wid * 16;

    float ssum[8][4];
    #pragma unroll
    for (int ni = 0; ni < 8; ni++)
        #pragma unroll
        for (int k = 0; k < 4; k++) ssum[ni][k] = 0.f;
    float ds0 = 0.f, ds1 = 0.f;

    const uint32_t a_base = sq_u + (uint32_t)((mrow + (lane & 15)) * APITCH
                                              + ((lane >> 4) << 3)) * 2;
    const uint32_t b_rowoff = (uint32_t)((((lane >> 4) << 3) + (lane & 7)) * APITCH
                                         + (lane & 8)) * 2;
    const uint32_t v_base = sv_u + (uint32_t)((lane & 15) * APITCH) * 2;

    for (int h = 0; h < 8; h++) {
        const int kb = h * 32;
        // ---- S = Q K^T (64 cols, k=32) ----
        float acc[8][4];
        #pragma unroll
        for (int ni = 0; ni < 8; ni++)
            #pragma unroll
            for (int k = 0; k < 4; k++) acc[ni][k] = 0.f;
        #pragma unroll
        for (int ks = 0; ks < 2; ks++) {
            uint32_t a[4];
            LDSM4(a, a_base + (uint32_t)(kb + ks * 16) * 2);
            #pragma unroll
            for (int nt = 0; nt < 4; nt++) {
                uint32_t b[4];
                uint32_t baddr = sk_u + b_rowoff
                               + (uint32_t)(nt * 16 * APITCH + kb + ks * 16) * 2;
                LDSM4(b, baddr);
                MMA16816(acc[nt * 2],     a, b[0], b[1]);
                MMA16816(acc[nt * 2 + 1], a, b[2], b[3]);
            }
        }
        // ---- gate + ssum + row max ----
        float m0 = -1e30f, m1 = -1e30f;
        #pragma unroll
        for (int ni = 0; ni < 8; ni++) {
            int j0 = ni * 8 + tig * 2;
            __half2 gA = *(__half2*)&sgate[(mrow + g) * 66 + j0];
            __half2 gB = *(__half2*)&sgate[(mrow + g + 8) * 66 + j0];
            float2 fA = __half22float2(gA);
            float2 fB = __half22float2(gB);
            acc[ni][0] *= fA.x;  acc[ni][1] *= fA.y;
            acc[ni][2] *= fB.x;  acc[ni][3] *= fB.y;
            ssum[ni][0] += acc[ni][0]; ssum[ni][1] += acc[ni][1];
            ssum[ni][2] += acc[ni][2]; ssum[ni][3] += acc[ni][3];
            m0 = fmaxf(m0, fmaxf(acc[ni][0], acc[ni][1]));
            m1 = fmaxf(m1, fmaxf(acc[ni][2], acc[ni][3]));
        }
        m0 = fmaxf(m0, __shfl_xor_sync(0xffffffffu, m0, 1));
        m0 = fmaxf(m0, __shfl_xor_sync(0xffffffffu, m0, 2));
        m1 = fmaxf(m1, __shfl_xor_sync(0xffffffffu, m1, 1));
        m1 = fmaxf(m1, __shfl_xor_sync(0xffffffffu, m1, 2));
        // ---- exp + row sums ----
        float sum0 = 0.f, sum1 = 0.f;
        #pragma unroll
        for (int ni = 0; ni < 8; ni++) {
            acc[ni][0] = __expf(acc[ni][0] - m0);
            acc[ni][1] = __expf(acc[ni][1] - m0);
            acc[ni][2] = __expf(acc[ni][2] - m1);
            acc[ni][3] = __expf(acc[ni][3] - m1);
            sum0 += acc[ni][0] + acc[ni][1];
            sum1 += acc[ni][2] + acc[ni][3];
        }
        sum0 += __shfl_xor_sync(0xffffffffu, sum0, 1);
        sum0 += __shfl_xor_sync(0xffffffffu, sum0, 2);
        sum1 += __shfl_xor_sync(0xffffffffu, sum1, 1);
        sum1 += __shfl_xor_sync(0xffffffffu, sum1, 2);
        const float inv0 = 1.f / sum0, inv1 = 1.f / sum1;
        // ---- P fragments directly from accumulators (FA2 identity) ----
        uint32_t pa[4][4];
        #pragma unroll
        for (int t = 0; t < 4; t++) {
            pa[t][0] = packh2(acc[2*t][0]   * inv0, acc[2*t][1]   * inv0);
            pa[t][1] = packh2(acc[2*t][2]   * inv1, acc[2*t][3]   * inv1);
            pa[t][2] = packh2(acc[2*t+1][0] * inv0, acc[2*t+1][1] * inv0);
            pa[t][3] = packh2(acc[2*t+1][2] * inv1, acc[2*t+1][3] * inv1);
        }
        // ---- out = P @ V (k=64 tokens, n=32 dims) ----
        float oacc[4][4];
        #pragma unroll
        for (int nb = 0; nb < 4; nb++)
            #pragma unroll
            for (int k = 0; k < 4; k++) oacc[nb][k] = 0.f;
        #pragma unroll
        for (int t = 0; t < 4; t++) {
            #pragma unroll
            for (int nb = 0; nb < 4; nb++) {
                uint32_t b2[2];
                uint32_t vaddr = v_base
                               + (uint32_t)(t * 16 * APITCH + kb + nb * 8) * 2;
                LDSM2T(b2, vaddr);
                MMA16816(oacc[nb], pa[t], b2[0], b2[1]);
            }
        }
        // ---- write ov (fp16 into A matrix) + out[:,256] dot partials ----
        #pragma unroll
        for (int nb = 0; nb < 4; nb++) {
            int c0 = kb + nb * 8 + tig * 2;
            float w0 = s_w[c0], w1 = s_w[c0 + 1];
            ds0 += oacc[nb][0] * w0 + oacc[nb][1] * w1;
            ds1 += oacc[nb][2] * w0 + oacc[nb][3] * w1;
            *(uint32_t*)&Ah[(r0 + mrow + g) * KPAD + c0] =
                packh2(oacc[nb][0], oacc[nb][1]);
            *(uint32_t*)&Ah[(r0 + mrow + g + 8) * KPAD + c0] =
                packh2(oacc[nb][2], oacc[nb][3]);
        }
    }

    // ---- depth attention: softmax(ssum) . vd  (all in registers) ----
    float m0 = -1e30f, m1 = -1e30f;
    #pragma unroll
    for (int ni = 0; ni < 8; ni++) {
        m0 = fmaxf(m0, fmaxf(ssum[ni][0], ssum[ni][1]));
        m1 = fmaxf(m1, fmaxf(ssum[ni][2], ssum[ni][3]));
    }
    m0 = fmaxf(m0, __shfl_xor_sync(0xffffffffu, m0, 1));
    m0 = fmaxf(m0, __shfl_xor_sync(0xffffffffu, m0, 2));
    m1 = fmaxf(m1, __shfl_xor_sync(0xffffffffu, m1, 1));
    m1 = fmaxf(m1, __shfl_xor_sync(0xffffffffu, m1, 2));
    float se0 = 0.f, se1 = 0.f, av0 = 0.f, av1 = 0.f;
    #pragma unroll
    for (int ni = 0; ni < 8; ni++) {
        int j0 = ni * 8 + tig * 2;
        float v0 = s_vd[j0], v1 = s_vd[j0 + 1];
        float e0 = __expf(ssum[ni][0] - m0);
        float e1 = __expf(ssum[ni][1] - m0);
        float e2 = __expf(ssum[ni][2] - m1);
        float e3 = __expf(ssum[ni][3] - m1);
        se0 += e0 + e1;  av0 += e0 * v0 + e1 * v1;
        se1 += e2 + e3;  av1 += e2 * v0 + e3 * v1;
    }
    se0 += __shfl_xor_sync(0xffffffffu, se0, 1);
    se0 += __shfl_xor_sync(0xffffffffu, se0, 2);
    av0 += __shfl_xor_sync(0xffffffffu, av0, 1);
    av0 += __shfl_xor_sync(0xffffffffu, av0, 2);
    se1 += __shfl_xor_sync(0xffffffffu, se1, 1);
    se1 += __shfl_xor_sync(0xffffffffu, se1, 2);
    av1 += __shfl_xor_sync(0xffffffffu, av1, 1);
    av1 += __shfl_xor_sync(0xffffffffu, av1, 2);
    ds0 += __shfl_xor_sync(0xffffffffu, ds0, 1);
    ds0 += __shfl_xor_sync(0xffffffffu, ds0, 2);
    ds1 += __shfl_xor_sync(0xffffffffu, ds1, 1);
    ds1 += __shfl_xor_sync(0xffffffffu, ds1, 2);

    if (tig == 0) {
        float od0 = av0 / se0, od1 = av1 / se1;
        size_t ra = r0 + mrow + g, rb = ra + 8;
        Ah[ra * KPAD + 256] = __float2half_rn(od0);
        Ah[rb * KPAD + 256] = __float2half_rn(od1);
        out[ra * D1 + 256] = ds0 + od0 * s_w[256];
        out[rb * D1 + 256] = ds1 + od1 * s_w[256];
    }
}

// ---------------- launch -----------------------------------------------------
extern "C" void kernel_launch(void* const* d_in, const int* in_sizes, int n_in,
                              void* d_out, int out_size)
{
    const float* x    = (const float*)d_in[0];
    const float* Wqv  = (const float*)d_in[1];
    const float* Wkv  = (const float*)d_in[2];
    const float* Wvv  = (const float*)d_in[3];
    const float* Wqd  = (const float*)d_in[4];
    const float* Wkd  = (const float*)d_in[5];
    const float* Wvd  = (const float*)d_in[6];
    const float* Wout = (const float*)d_in[7];
    float* out = (float*)d_out;

    __half *Ah, *Bh, *BoH, *qvh, *kvh, *vvh;
    float *qd, *kd, *vd;
    cudaGetSymbolAddress((void**)&Ah,  g_Ah);
    cudaGetSymbolAddress((void**)&Bh,  g_Bh);
    cudaGetSymbolAddress((void**)&BoH, g_BoH);
    cudaGetSymbolAddress((void**)&qvh, g_qvh);
    cudaGetSymbolAddress((void**)&kvh, g_kvh);
    cudaGetSymbolAddress((void**)&vvh, g_vvh);
    cudaGetSymbolAddress((void**)&qd,  g_qd);
    cudaGetSymbolAddress((void**)&kd,  g_kd);
    cudaGetSymbolAddress((void**)&vd,  g_vd);

    cudaFuncSetAttribute(gemm_mma,
                         cudaFuncAttributeMaxDynamicSharedMemorySize, GEMM_SMEM);
    cudaFuncSetAttribute(attn_mma,
                         cudaFuncAttributeMaxDynamicSharedMemorySize, ATTN_SMEM);

    conv_w_qkv<<<768 * KPAD / 256, 256>>>(Wqv, Wkv, Wvv, Bh);
    conv_w_out<<<256 * KPAD / 256, 256>>>(Wout, BoH);
    conv_x_dproj<<<MROWS / 8, 256>>>(x, Wqd, Wkd, Wvd, Ah, qd, kd, vd);

    gemm_mma<<<dim3(6, MROWS / BM), 256, GEMM_SMEM>>>(
        Ah, Bh, qvh, kvh, vvh, SCALE, 1.f, 1.f, DIMV, 1);

    attn_mma<<<NWIN, 128, ATTN_SMEM>>>(qvh, kvh, vvh, qd, kd, vd, Wout, Ah, out);

    gemm_mma<<<dim3(2, MROWS / BM), 256, GEMM_SMEM>>>(
        Ah, BoH, out, out, out, 1.f, 1.f, 1.f, D1, 0);
}

// round 10
// speedup vs baseline: 5.6366x; 1.0953x over previous
#include <cuda_runtime.h>
#include <cuda_fp16.h>
#include <cstdint>
#include <math.h>

#define MROWS 131072        // 2048 windows * 64 tokens
#define NWIN  2048
#define D1    257
#define DIMV  256
#define KPAD  288           // 257 padded to 9 chunks of 32
#define KITERS 9
#define SCALE 0.17677669529663687f   // 32^-0.5

// ======================= scratch (device globals) ===========================
__device__ __align__(256) __half g_Ah[(size_t)MROWS * KPAD];
__device__ __align__(256) __half g_Bh[768 * KPAD];
__device__ __align__(256) __half g_BoH[256 * KPAD];
__device__ __align__(256) __half g_qvh[(size_t)MROWS * DIMV];
__device__ __align__(256) __half g_kvh[(size_t)MROWS * DIMV];
__device__ __align__(256) __half g_vvh[(size_t)MROWS * DIMV];
__device__ float g_qd[MROWS];
__device__ float g_kd[MROWS];
__device__ float g_vd[MROWS];

// ======================= PTX helpers =========================================
__device__ __forceinline__ uint32_t smem_u32(const void* p) {
    uint32_t a;
    asm("{ .reg .u64 t; cvta.to.shared.u64 t, %1; cvt.u32.u64 %0, t; }"
        : "=r"(a) : "l"(p));
    return a;
}
__device__ __forceinline__ void cp16(uint32_t s, const void* g) {
    asm volatile("cp.async.ca.shared.global [%0], [%1], 16;" :: "r"(s), "l"(g));
}
#define CP_COMMIT()  asm volatile("cp.async.commit_group;" ::: "memory")
#define CP_WAIT(n)   asm volatile("cp.async.wait_group %0;" :: "n"(n) : "memory")

#define LDSM4(r, addr) \
    asm volatile("ldmatrix.sync.aligned.m8n8.x4.shared.b16 {%0,%1,%2,%3}, [%4];" \
        : "=r"((r)[0]), "=r"((r)[1]), "=r"((r)[2]), "=r"((r)[3]) : "r"(addr))

#define LDSM2T(r, addr) \
    asm volatile("ldmatrix.sync.aligned.m8n8.x2.trans.shared.b16 {%0,%1}, [%2];" \
        : "=r"((r)[0]), "=r"((r)[1]) : "r"(addr))

#define MMA16816(c, a, b0v, b1v) \
    asm volatile("mma.sync.aligned.m16n8k16.row.col.f32.f16.f16.f32 " \
        "{%0,%1,%2,%3}, {%4,%5,%6,%7}, {%8,%9}, {%0,%1,%2,%3};" \
        : "+f"((c)[0]), "+f"((c)[1]), "+f"((c)[2]), "+f"((c)[3]) \
        : "r"((a)[0]), "r"((a)[1]), "r"((a)[2]), "r"((a)[3]), "r"(b0v), "r"(b1v))

__device__ __forceinline__ uint32_t packh2(float a, float b) {
    __half2 h = __floats2half2_rn(a, b);
    return *reinterpret_cast<uint32_t*>(&h);
}

// ============ conv_x + depth projections (warp per row) =====================
__global__ void __launch_bounds__(256) conv_x_dproj(
    const float* __restrict__ X,
    const float* __restrict__ Wq, const float* __restrict__ Wk,
    const float* __restrict__ Wv,
    __half* __restrict__ Ah,
    float* __restrict__ qd, float* __restrict__ kd, float* __restrict__ vd)
{
    const int warp = threadIdx.x >> 5;
    const int lane = threadIdx.x & 31;
    const size_t r = (size_t)blockIdx.x * 8 + warp;
    const float* xr = X + r * D1;
    float sq = 0.f, sk = 0.f, sv = 0.f;
    #pragma unroll
    for (int i = 0; i < 9; i++) {
        int c = lane + i * 32;
        float v = (c < D1) ? xr[c] : 0.f;
        Ah[r * KPAD + c] = __float2half_rn(v);
        if (c < D1) {
            sq = fmaf(v, Wq[c], sq);
            sk = fmaf(v, Wk[c], sk);
            sv = fmaf(v, Wv[c], sv);
        }
    }
    #pragma unroll
    for (int o = 16; o > 0; o >>= 1) {
        sq += __shfl_down_sync(0xffffffffu, sq, o);
        sk += __shfl_down_sync(0xffffffffu, sk, o);
        sv += __shfl_down_sync(0xffffffffu, sv, o);
    }
    if (lane == 0) { qd[r] = sq * SCALE; kd[r] = sk; vd[r] = sv; }
}

// ============ QKV weight transpose: B[n,k] = fp16(W[k, n%256]) ==============
__global__ void __launch_bounds__(256) conv_w_qkv(
    const float* __restrict__ Wqv, const float* __restrict__ Wkv,
    const float* __restrict__ Wvv, __half* __restrict__ Bh)
{
    int idx = blockIdx.x * 256 + threadIdx.x;   // 768*288 total
    int n = idx / KPAD, k = idx % KPAD;
    const float* W = (n < 256) ? Wqv : (n < 512) ? Wkv : Wvv;
    float v = (k < D1) ? W[(size_t)k * DIMV + (n & 255)] : 0.f;
    Bh[idx] = __float2half_rn(v);
}

// ============ Wout transpose: B[n,k] = fp16(Wout[k, n]) =====================
__global__ void __launch_bounds__(256) conv_w_out(
    const float* __restrict__ Wout, __half* __restrict__ Bh)
{
    int idx = blockIdx.x * 256 + threadIdx.x;   // 256*288 total
    int n = idx / KPAD, k = idx % KPAD;
    float v = (k < D1) ? Wout[(size_t)k * D1 + n] : 0.f;
    Bh[idx] = __float2half_rn(v);
}

// ============ fp16 HMMA GEMM: BM=BN=128 BK=32, 3-stage, 2x2 warps ===========
// 128 threads, 64x64 per warp: 8 LDSM4 per 32 MMAs (was 6 per 16) -> -33% LDS.
#define BM 128
#define BN 128
#define BK 32
#define SPITCH 40
#define MAT_BYTES (BM * SPITCH * 2)        // 10240
#define STAGE_BYTES (2 * MAT_BYTES)        // 20480
#define NSTAGE 3
#define GEMM_SMEM (NSTAGE * STAGE_BYTES)   // 61440

__global__ void __launch_bounds__(128, 2) gemm_mma(
    const __half* __restrict__ A, const __half* __restrict__ B,
    void* __restrict__ o0, void* __restrict__ o1, void* __restrict__ o2,
    float s0, float s1, float s2, int pitch, int half_out)
{
    extern __shared__ char sm[];
    const int tid  = threadIdx.x;
    const int lane = tid & 31;
    const int wid  = tid >> 5;
    const int wm   = wid >> 1;             // 0..1
    const int wn   = wid & 1;              // 0..1
    const int nblk = blockIdx.x;
    const size_t m0 = (size_t)blockIdx.y * BM;
    const int sel = nblk >> 1;
    void* ov = (sel == 0) ? o0 : (sel == 1) ? o1 : o2;
    const float scale = (sel == 0) ? s0 : (sel == 1) ? s1 : s2;
    const int ncol0 = (nblk & 1) * BN;
    const uint32_t sbase = smem_u32(sm);

    const __half* B_b = B + (size_t)nblk * BN * KPAD;

    // per-thread cp.async assignment (8 x 16B chunks / thread / stage)
    auto load_stage = [&](int it, int buf) {
        const int kc = it * BK;
        #pragma unroll
        for (int t = 0; t < 8; t++) {
            int id = tid + t * 128;
            int mat = id >> 9;
            int i = id & 511;
            int row = i >> 2, c = i & 3;
            const __half* g;
            if (mat == 0) g = A   + (m0 + row) * KPAD + kc + c * 8;
            else          g = B_b + (size_t)row * KPAD + kc + c * 8;
            uint32_t s = sbase + buf * STAGE_BYTES + mat * MAT_BYTES
                       + (uint32_t)(row * SPITCH + c * 8) * 2;
            cp16(s, g);
        }
        CP_COMMIT();
    };

    float acc[4][8][4];
    #pragma unroll
    for (int a = 0; a < 4; a++)
        #pragma unroll
        for (int b = 0; b < 8; b++)
            #pragma unroll
            for (int c = 0; c < 4; c++) acc[a][b][c] = 0.f;

    const uint32_t a_off = (uint32_t)((wm * 64 + (lane & 15)) * SPITCH
                                      + ((lane >> 4) << 3)) * 2;
    const uint32_t b_off = (uint32_t)((wn * 64 + ((lane >> 4) << 3) + (lane & 7)) * SPITCH
                                      + (lane & 8)) * 2;

    load_stage(0, 0);
    load_stage(1, 1);

    for (int it = 0; it < KITERS; ++it) {
        CP_WAIT(1);
        __syncthreads();
        if (it + 2 < KITERS) load_stage(it + 2, (it + 2) % NSTAGE);
        else CP_COMMIT();

        const uint32_t st = sbase + (it % NSTAGE) * STAGE_BYTES;
        const int nks = (it == KITERS - 1) ? 1 : 2;
        for (int ks = 0; ks < nks; ks++) {
            const uint32_t ko = ks * 32;
            uint32_t ah[4][4], bh[4][4];
            #pragma unroll
            for (int mi = 0; mi < 4; mi++) {
                uint32_t ao = a_off + (uint32_t)(mi * 16 * SPITCH) * 2 + ko;
                LDSM4(ah[mi], st + 0 * MAT_BYTES + ao);
            }
            #pragma unroll
            for (int nj = 0; nj < 4; nj++) {
                uint32_t bo = b_off + (uint32_t)(nj * 16 * SPITCH) * 2 + ko;
                LDSM4(bh[nj], st + 1 * MAT_BYTES + bo);
            }
            #pragma unroll
            for (int mi = 0; mi < 4; mi++)
                #pragma unroll
                for (int ni = 0; ni < 8; ni++) {
                    uint32_t b0 = bh[ni >> 1][(ni & 1) * 2];
                    uint32_t b1 = bh[ni >> 1][(ni & 1) * 2 + 1];
                    MMA16816(acc[mi][ni], ah[mi], b0, b1);
                }
        }
    }

    // ---- epilogue: warp tile 64x64 ----
    const int r0 = wm * 64 + (lane >> 2);
    const int c0 = ncol0 + wn * 64 + (lane & 3) * 2;
    if (half_out) {
        __half* o = (__half*)ov;
        #pragma unroll
        for (int mi = 0; mi < 4; mi++)
            #pragma unroll
            for (int ni = 0; ni < 8; ni++) {
                size_t row = m0 + r0 + mi * 16;
                int col = c0 + ni * 8;
                *(uint32_t*)&o[row * DIMV + col] =
                    packh2(acc[mi][ni][0] * scale, acc[mi][ni][1] * scale);
                *(uint32_t*)&o[(row + 8) * DIMV + col] =
                    packh2(acc[mi][ni][2] * scale, acc[mi][ni][3] * scale);
            }
    } else {
        float* o = (float*)ov;
        #pragma unroll
        for (int mi = 0; mi < 4; mi++)
            #pragma unroll
            for (int ni = 0; ni < 8; ni++) {
                size_t row = m0 + r0 + mi * 16;
                int col = c0 + ni * 8;
                o[row * (size_t)pitch + col]           = acc[mi][ni][0] * scale;
                o[row * (size_t)pitch + col + 1]       = acc[mi][ni][1] * scale;
                o[(row + 8) * (size_t)pitch + col]     = acc[mi][ni][2] * scale;
                o[(row + 8) * (size_t)pitch + col + 1] = acc[mi][ni][3] * scale;
            }
    }
}

// ============ fused MMA attention: 1 window/CTA, 128 thr, warp = 16 rows ====
#define APITCH 264     // halves per row (256 + 8 pad): conflict-free LDSM
#define ATTN_HALVES (3 * 64 * APITCH + 64 * 66)
#define ATTN_SMEM   (ATTN_HALVES * 2 + (64 * 3 + 260) * 4)

__global__ void __launch_bounds__(128, 2) attn_mma(
    const __half* __restrict__ qv, const __half* __restrict__ kv,
    const __half* __restrict__ vv,
    const float* __restrict__ qd, const float* __restrict__ kd,
    const float* __restrict__ vd, const float* __restrict__ Wout,
    __half* __restrict__ Ah, float* __restrict__ out)
{
    extern __shared__ char sm[];
    __half* sq    = (__half*)sm;                 // [64][APITCH]
    __half* sk    = sq + 64 * APITCH;
    __half* sv    = sk + 64 * APITCH;
    __half* sgate = sv + 64 * APITCH;            // [64][66]
    float*  s_qd  = (float*)(sm + ATTN_HALVES * 2);
    float*  s_kd  = s_qd + 64;
    float*  s_vd  = s_kd + 64;
    float*  s_w   = s_vd + 64;                   // Wout[:,256], 257 floats

    const int tid  = threadIdx.x;
    const int lane = tid & 31;
    const int wid  = tid >> 5;
    const int g    = lane >> 2;
    const int tig  = lane & 3;
    const size_t r0 = (size_t)blockIdx.x * 64;

    const uint32_t sq_u = smem_u32(sq);
    const uint32_t sk_u = smem_u32(sk);
    const uint32_t sv_u = smem_u32(sv);

    // ---- cooperative load via cp.async (fire-and-forget, one wait) ----
    {
        const uint4* gq = (const uint4*)(qv + r0 * DIMV);
        const uint4* gk = (const uint4*)(kv + r0 * DIMV);
        const uint4* gv = (const uint4*)(vv + r0 * DIMV);
        for (int i = tid; i < 2048; i += 128) {
            int row = i >> 5, c = i & 31;            // 32 x 8 halves = 256/row
            uint32_t off = (uint32_t)(row * APITCH * 2 + c * 16);
            cp16(sq_u + off, gq + i);
            cp16(sk_u + off, gk + i);
            cp16(sv_u + off, gv + i);
        }
        CP_COMMIT();
        if (tid < 64) {
            s_qd[tid] = qd[r0 + tid];
            s_kd[tid] = kd[r0 + tid];
            s_vd[tid] = vd[r0 + tid];
        }
        for (int i = tid; i < 257; i += 128)
            s_w[i] = Wout[(size_t)i * D1 + 256];
        CP_WAIT(0);
    }
    __syncthreads();

    // ---- gate table (head-invariant): sigmoid(qd_i * kd_j), fp16 ----
    for (int i = tid; i < 4096; i += 128) {
        int ii = i >> 6, jj = i & 63;
        float z = s_qd[ii] * s_kd[jj];
        sgate[ii * 66 + jj] = __float2half_rn(1.f / (1.f + __expf(-z)));
    }
    __syncthreads();

    const int mrow = wid * 16;

    float ssum[8][4];
    #pragma unroll
    for (int ni = 0; ni < 8; ni++)
        #pragma unroll
        for (int k = 0; k < 4; k++) ssum[ni][k] = 0.f;
    float ds0 = 0.f, ds1 = 0.f;

    const uint32_t a_base = sq_u + (uint32_t)((mrow + (lane & 15)) * APITCH
                                              + ((lane >> 4) << 3)) * 2;
    const uint32_t b_rowoff = (uint32_t)((((lane >> 4) << 3) + (lane & 7)) * APITCH
                                         + (lane & 8)) * 2;
    const uint32_t v_base = sv_u + (uint32_t)((lane & 15) * APITCH) * 2;

    for (int h = 0; h < 8; h++) {
        const int kb = h * 32;
        // ---- S = Q K^T (64 cols, k=32) ----
        float acc[8][4];
        #pragma unroll
        for (int ni = 0; ni < 8; ni++)
            #pragma unroll
            for (int k = 0; k < 4; k++) acc[ni][k] = 0.f;
        #pragma unroll
        for (int ks = 0; ks < 2; ks++) {
            uint32_t a[4];
            LDSM4(a, a_base + (uint32_t)(kb + ks * 16) * 2);
            #pragma unroll
            for (int nt = 0; nt < 4; nt++) {
                uint32_t b[4];
                uint32_t baddr = sk_u + b_rowoff
                               + (uint32_t)(nt * 16 * APITCH + kb + ks * 16) * 2;
                LDSM4(b, baddr);
                MMA16816(acc[nt * 2],     a, b[0], b[1]);
                MMA16816(acc[nt * 2 + 1], a, b[2], b[3]);
            }
        }
        // ---- gate + ssum + row max ----
        float m0 = -1e30f, m1 = -1e30f;
        #pragma unroll
        for (int ni = 0; ni < 8; ni++) {
            int j0 = ni * 8 + tig * 2;
            __half2 gA = *(__half2*)&sgate[(mrow + g) * 66 + j0];
            __half2 gB = *(__half2*)&sgate[(mrow + g + 8) * 66 + j0];
            float2 fA = __half22float2(gA);
            float2 fB = __half22float2(gB);
            acc[ni][0] *= fA.x;  acc[ni][1] *= fA.y;
            acc[ni][2] *= fB.x;  acc[ni][3] *= fB.y;
            ssum[ni][0] += acc[ni][0]; ssum[ni][1] += acc[ni][1];
            ssum[ni][2] += acc[ni][2]; ssum[ni][3] += acc[ni][3];
            m0 = fmaxf(m0, fmaxf(acc[ni][0], acc[ni][1]));
            m1 = fmaxf(m1, fmaxf(acc[ni][2], acc[ni][3]));
        }
        m0 = fmaxf(m0, __shfl_xor_sync(0xffffffffu, m0, 1));
        m0 = fmaxf(m0, __shfl_xor_sync(0xffffffffu, m0, 2));
        m1 = fmaxf(m1, __shfl_xor_sync(0xffffffffu, m1, 1));
        m1 = fmaxf(m1, __shfl_xor_sync(0xffffffffu, m1, 2));
        // ---- exp + row sums ----
        float sum0 = 0.f, sum1 = 0.f;
        #pragma unroll
        for (int ni = 0; ni < 8; ni++) {
            acc[ni][0] = __expf(acc[ni][0] - m0);
            acc[ni][1] = __expf(acc[ni][1] - m0);
            acc[ni][2] = __expf(acc[ni][2] - m1);
            acc[ni][3] = __expf(acc[ni][3] - m1);
            sum0 += acc[ni][0] + acc[ni][1];
            sum1 += acc[ni][2] + acc[ni][3];
        }
        sum0 += __shfl_xor_sync(0xffffffffu, sum0, 1);
        sum0 += __shfl_xor_sync(0xffffffffu, sum0, 2);
        sum1 += __shfl_xor_sync(0xffffffffu, sum1, 1);
        sum1 += __shfl_xor_sync(0xffffffffu, sum1, 2);
        const float inv0 = 1.f / sum0, inv1 = 1.f / sum1;
        // ---- P fragments directly from accumulators (FA2 identity) ----
        uint32_t pa[4][4];
        #pragma unroll
        for (int t = 0; t < 4; t++) {
            pa[t][0] = packh2(acc[2*t][0]   * inv0, acc[2*t][1]   * inv0);
            pa[t][1] = packh2(acc[2*t][2]   * inv1, acc[2*t][3]   * inv1);
            pa[t][2] = packh2(acc[2*t+1][0] * inv0, acc[2*t+1][1] * inv0);
            pa[t][3] = packh2(acc[2*t+1][2] * inv1, acc[2*t+1][3] * inv1);
        }
        // ---- out = P @ V (k=64 tokens, n=32 dims) ----
        float oacc[4][4];
        #pragma unroll
        for (int nb = 0; nb < 4; nb++)
            #pragma unroll
            for (int k = 0; k < 4; k++) oacc[nb][k] = 0.f;
        #pragma unroll
        for (int t = 0; t < 4; t++) {
            #pragma unroll
            for (int nb = 0; nb < 4; nb++) {
                uint32_t b2[2];
                uint32_t vaddr = v_base
                               + (uint32_t)(t * 16 * APITCH + kb + nb * 8) * 2;
                LDSM2T(b2, vaddr);
                MMA16816(oacc[nb], pa[t], b2[0], b2[1]);
            }
        }
        // ---- write ov (fp16 into A matrix) + out[:,256] dot partials ----
        #pragma unroll
        for (int nb = 0; nb < 4; nb++) {
            int c0 = kb + nb * 8 + tig * 2;
            float w0 = s_w[c0], w1 = s_w[c0 + 1];
            ds0 += oacc[nb][0] * w0 + oacc[nb][1] * w1;
            ds1 += oacc[nb][2] * w0 + oacc[nb][3] * w1;
            *(uint32_t*)&Ah[(r0 + mrow + g) * KPAD + c0] =
                packh2(oacc[nb][0], oacc[nb][1]);
            *(uint32_t*)&Ah[(r0 + mrow + g + 8) * KPAD + c0] =
                packh2(oacc[nb][2], oacc[nb][3]);
        }
    }

    // ---- depth attention: softmax(ssum) . vd  (all in registers) ----
    float m0 = -1e30f, m1 = -1e30f;
    #pragma unroll
    for (int ni = 0; ni < 8; ni++) {
        m0 = fmaxf(m0, fmaxf(ssum[ni][0], ssum[ni][1]));
        m1 = fmaxf(m1, fmaxf(ssum[ni][2], ssum[ni][3]));
    }
    m0 = fmaxf(m0, __shfl_xor_sync(0xffffffffu, m0, 1));
    m0 = fmaxf(m0, __shfl_xor_sync(0xffffffffu, m0, 2));
    m1 = fmaxf(m1, __shfl_xor_sync(0xffffffffu, m1, 1));
    m1 = fmaxf(m1, __shfl_xor_sync(0xffffffffu, m1, 2));
    float se0 = 0.f, se1 = 0.f, av0 = 0.f, av1 = 0.f;
    #pragma unroll
    for (int ni = 0; ni < 8; ni++) {
        int j0 = ni * 8 + tig * 2;
        float v0 = s_vd[j0], v1 = s_vd[j0 + 1];
        float e0 = __expf(ssum[ni][0] - m0);
        float e1 = __expf(ssum[ni][1] - m0);
        float e2 = __expf(ssum[ni][2] - m1);
        float e3 = __expf(ssum[ni][3] - m1);
        se0 += e0 + e1;  av0 += e0 * v0 + e1 * v1;
        se1 += e2 + e3;  av1 += e2 * v0 + e3 * v1;
    }
    se0 += __shfl_xor_sync(0xffffffffu, se0, 1);
    se0 += __shfl_xor_sync(0xffffffffu, se0, 2);
    av0 += __shfl_xor_sync(0xffffffffu, av0, 1);
    av0 += __shfl_xor_sync(0xffffffffu, av0, 2);
    se1 += __shfl_xor_sync(0xffffffffu, se1, 1);
    se1 += __shfl_xor_sync(0xffffffffu, se1, 2);
    av1 += __shfl_xor_sync(0xffffffffu, av1, 1);
    av1 += __shfl_xor_sync(0xffffffffu, av1, 2);
    ds0 += __shfl_xor_sync(0xffffffffu, ds0, 1);
    ds0 += __shfl_xor_sync(0xffffffffu, ds0, 2);
    ds1 += __shfl_xor_sync(0xffffffffu, ds1, 1);
    ds1 += __shfl_xor_sync(0xffffffffu, ds1, 2);

    if (tig == 0) {
        float od0 = av0 / se0, od1 = av1 / se1;
        size_t ra = r0 + mrow + g, rb = ra + 8;
        Ah[ra * KPAD + 256] = __float2half_rn(od0);
        Ah[rb * KPAD + 256] = __float2half_rn(od1);
        out[ra * D1 + 256] = ds0 + od0 * s_w[256];
        out[rb * D1 + 256] = ds1 + od1 * s_w[256];
    }
}

// ---------------- launch -----------------------------------------------------
extern "C" void kernel_launch(void* const* d_in, const int* in_sizes, int n_in,
                              void* d_out, int out_size)
{
    const float* x    = (const float*)d_in[0];
    const float* Wqv  = (const float*)d_in[1];
    const float* Wkv  = (const float*)d_in[2];
    const float* Wvv  = (const float*)d_in[3];
    const float* Wqd  = (const float*)d_in[4];
    const float* Wkd  = (const float*)d_in[5];
    const float* Wvd  = (const float*)d_in[6];
    const float* Wout = (const float*)d_in[7];
    float* out = (float*)d_out;

    __half *Ah, *Bh, *BoH, *qvh, *kvh, *vvh;
    float *qd, *kd, *vd;
    cudaGetSymbolAddress((void**)&Ah,  g_Ah);
    cudaGetSymbolAddress((void**)&Bh,  g_Bh);
    cudaGetSymbolAddress((void**)&BoH, g_BoH);
    cudaGetSymbolAddress((void**)&qvh, g_qvh);
    cudaGetSymbolAddress((void**)&kvh, g_kvh);
    cudaGetSymbolAddress((void**)&vvh, g_vvh);
    cudaGetSymbolAddress((void**)&qd,  g_qd);
    cudaGetSymbolAddress((void**)&kd,  g_kd);
    cudaGetSymbolAddress((void**)&vd,  g_vd);

    cudaFuncSetAttribute(gemm_mma,
                         cudaFuncAttributeMaxDynamicSharedMemorySize, GEMM_SMEM);
    cudaFuncSetAttribute(attn_mma,
                         cudaFuncAttributeMaxDynamicSharedMemorySize, ATTN_SMEM);

    conv_w_qkv<<<768 * KPAD / 256, 256>>>(Wqv, Wkv, Wvv, Bh);
    conv_w_out<<<256 * KPAD / 256, 256>>>(Wout, BoH);
    conv_x_dproj<<<MROWS / 8, 256>>>(x, Wqd, Wkd, Wvd, Ah, qd, kd, vd);

    gemm_mma<<<dim3(6, MROWS / BM), 128, GEMM_SMEM>>>(
        Ah, Bh, qvh, kvh, vvh, SCALE, 1.f, 1.f, DIMV, 1);

    attn_mma<<<NWIN, 128, ATTN_SMEM>>>(qvh, kvh, vvh, qd, kd, vd, Wout, Ah, out);

    gemm_mma<<<dim3(2, MROWS / BM), 128, GEMM_SMEM>>>(
        Ah, BoH, out, out, out, 1.f, 1.f, 1.f, D1, 0);
}

// round 11
// speedup vs baseline: 5.6424x; 1.0010x over previous
#include <cuda_runtime.h>
#include <cuda_fp16.h>
#include <cstdint>
#include <math.h>

#define MROWS 131072        // 2048 windows * 64 tokens
#define NWIN  2048
#define D1    257
#define DIMV  256
#define KPAD  288           // 257 padded to 9 chunks of 32
#define KITERS 9
#define SCALE 0.17677669529663687f   // 32^-0.5

// ======================= scratch (device globals) ===========================
__device__ __align__(256) __half g_Ah[(size_t)MROWS * KPAD];
__device__ __align__(256) __half g_Bh[768 * KPAD];
__device__ __align__(256) __half g_BoH[256 * KPAD];
__device__ __align__(256) __half g_qvh[(size_t)MROWS * DIMV];
__device__ __align__(256) __half g_kvh[(size_t)MROWS * DIMV];
__device__ __align__(256) __half g_vvh[(size_t)MROWS * DIMV];
__device__ float g_qd[MROWS];
__device__ float g_kd[MROWS];
__device__ float g_vd[MROWS];

// ======================= PTX helpers =========================================
__device__ __forceinline__ uint32_t smem_u32(const void* p) {
    uint32_t a;
    asm("{ .reg .u64 t; cvta.to.shared.u64 t, %1; cvt.u32.u64 %0, t; }"
        : "=r"(a) : "l"(p));
    return a;
}
__device__ __forceinline__ void cp16(uint32_t s, const void* g) {
    asm volatile("cp.async.ca.shared.global [%0], [%1], 16;" :: "r"(s), "l"(g));
}
#define CP_COMMIT()  asm volatile("cp.async.commit_group;" ::: "memory")
#define CP_WAIT(n)   asm volatile("cp.async.wait_group %0;" :: "n"(n) : "memory")

#define LDSM4(r, addr) \
    asm volatile("ldmatrix.sync.aligned.m8n8.x4.shared.b16 {%0,%1,%2,%3}, [%4];" \
        : "=r"((r)[0]), "=r"((r)[1]), "=r"((r)[2]), "=r"((r)[3]) : "r"(addr))

#define LDSM2T(r, addr) \
    asm volatile("ldmatrix.sync.aligned.m8n8.x2.trans.shared.b16 {%0,%1}, [%2];" \
        : "=r"((r)[0]), "=r"((r)[1]) : "r"(addr))

#define MMA16816(c, a, b0v, b1v) \
    asm volatile("mma.sync.aligned.m16n8k16.row.col.f32.f16.f16.f32 " \
        "{%0,%1,%2,%3}, {%4,%5,%6,%7}, {%8,%9}, {%0,%1,%2,%3};" \
        : "+f"((c)[0]), "+f"((c)[1]), "+f"((c)[2]), "+f"((c)[3]) \
        : "r"((a)[0]), "r"((a)[1]), "r"((a)[2]), "r"((a)[3]), "r"(b0v), "r"(b1v))

__device__ __forceinline__ uint32_t packh2(float a, float b) {
    __half2 h = __floats2half2_rn(a, b);
    return *reinterpret_cast<uint32_t*>(&h);
}

// ============ conv_x + depth projections (warp per row) =====================
__global__ void __launch_bounds__(256) conv_x_dproj(
    const float* __restrict__ X,
    const float* __restrict__ Wq, const float* __restrict__ Wk,
    const float* __restrict__ Wv,
    __half* __restrict__ Ah,
    float* __restrict__ qd, float* __restrict__ kd, float* __restrict__ vd)
{
    const int warp = threadIdx.x >> 5;
    const int lane = threadIdx.x & 31;
    const size_t r = (size_t)blockIdx.x * 8 + warp;
    const float* xr = X + r * D1;
    float sq = 0.f, sk = 0.f, sv = 0.f;
    #pragma unroll
    for (int i = 0; i < 9; i++) {
        int c = lane + i * 32;
        float v = (c < D1) ? xr[c] : 0.f;
        Ah[r * KPAD + c] = __float2half_rn(v);
        if (c < D1) {
            sq = fmaf(v, Wq[c], sq);
            sk = fmaf(v, Wk[c], sk);
            sv = fmaf(v, Wv[c], sv);
        }
    }
    #pragma unroll
    for (int o = 16; o > 0; o >>= 1) {
        sq += __shfl_down_sync(0xffffffffu, sq, o);
        sk += __shfl_down_sync(0xffffffffu, sk, o);
        sv += __shfl_down_sync(0xffffffffu, sv, o);
    }
    if (lane == 0) { qd[r] = sq * SCALE; kd[r] = sk; vd[r] = sv; }
}

// ============ QKV weight transpose: B[n,k] = fp16(W[k, n%256]) ==============
__global__ void __launch_bounds__(256) conv_w_qkv(
    const float* __restrict__ Wqv, const float* __restrict__ Wkv,
    const float* __restrict__ Wvv, __half* __restrict__ Bh)
{
    int idx = blockIdx.x * 256 + threadIdx.x;   // 768*288 total
    int n = idx / KPAD, k = idx % KPAD;
    const float* W = (n < 256) ? Wqv : (n < 512) ? Wkv : Wvv;
    float v = (k < D1) ? W[(size_t)k * DIMV + (n & 255)] : 0.f;
    Bh[idx] = __float2half_rn(v);
}

// ============ Wout transpose: B[n,k] = fp16(Wout[k, n]) =====================
__global__ void __launch_bounds__(256) conv_w_out(
    const float* __restrict__ Wout, __half* __restrict__ Bh)
{
    int idx = blockIdx.x * 256 + threadIdx.x;   // 256*288 total
    int n = idx / KPAD, k = idx % KPAD;
    float v = (k < D1) ? Wout[(size_t)k * D1 + n] : 0.f;
    Bh[idx] = __float2half_rn(v);
}

// ============ fp16 HMMA GEMM: BM=BN=128 BK=32, 3-stage, 2x2 warps ===========
// 128 threads, 64x64 per warp: 8 LDSM4 per 32 MMAs (was 6 per 16) -> -33% LDS.
#define BM 128
#define BN 128
#define BK 32
#define SPITCH 40
#define MAT_BYTES (BM * SPITCH * 2)        // 10240
#define STAGE_BYTES (2 * MAT_BYTES)        // 20480
#define NSTAGE 3
#define GEMM_SMEM (NSTAGE * STAGE_BYTES)   // 61440

__global__ void __launch_bounds__(128, 2) gemm_mma(
    const __half* __restrict__ A, const __half* __restrict__ B,
    void* __restrict__ o0, void* __restrict__ o1, void* __restrict__ o2,
    float s0, float s1, float s2, int pitch, int half_out)
{
    extern __shared__ char sm[];
    const int tid  = threadIdx.x;
    const int lane = tid & 31;
    const int wid  = tid >> 5;
    const int wm   = wid >> 1;             // 0..1
    const int wn   = wid & 1;              // 0..1
    const int nblk = blockIdx.x;
    const size_t m0 = (size_t)blockIdx.y * BM;
    const int sel = nblk >> 1;
    void* ov = (sel == 0) ? o0 : (sel == 1) ? o1 : o2;
    const float scale = (sel == 0) ? s0 : (sel == 1) ? s1 : s2;
    const int ncol0 = (nblk & 1) * BN;
    const uint32_t sbase = smem_u32(sm);

    const __half* B_b = B + (size_t)nblk * BN * KPAD;

    // per-thread cp.async assignment (8 x 16B chunks / thread / stage)
    auto load_stage = [&](int it, int buf) {
        const int kc = it * BK;
        #pragma unroll
        for (int t = 0; t < 8; t++) {
            int id = tid + t * 128;
            int mat = id >> 9;
            int i = id & 511;
            int row = i >> 2, c = i & 3;
            const __half* g;
            if (mat == 0) g = A   + (m0 + row) * KPAD + kc + c * 8;
            else          g = B_b + (size_t)row * KPAD + kc + c * 8;
            uint32_t s = sbase + buf * STAGE_BYTES + mat * MAT_BYTES
                       + (uint32_t)(row * SPITCH + c * 8) * 2;
            cp16(s, g);
        }
        CP_COMMIT();
    };

    float acc[4][8][4];
    #pragma unroll
    for (int a = 0; a < 4; a++)
        #pragma unroll
        for (int b = 0; b < 8; b++)
            #pragma unroll
            for (int c = 0; c < 4; c++) acc[a][b][c] = 0.f;

    const uint32_t a_off = (uint32_t)((wm * 64 + (lane & 15)) * SPITCH
                                      + ((lane >> 4) << 3)) * 2;
    const uint32_t b_off = (uint32_t)((wn * 64 + ((lane >> 4) << 3) + (lane & 7)) * SPITCH
                                      + (lane & 8)) * 2;

    load_stage(0, 0);
    load_stage(1, 1);

    for (int it = 0; it < KITERS; ++it) {
        CP_WAIT(1);
        __syncthreads();
        if (it + 2 < KITERS) load_stage(it + 2, (it + 2) % NSTAGE);
        else CP_COMMIT();

        const uint32_t st = sbase + (it % NSTAGE) * STAGE_BYTES;
        const int nks = (it == KITERS - 1) ? 1 : 2;
        for (int ks = 0; ks < nks; ks++) {
            const uint32_t ko = ks * 32;
            uint32_t ah[4][4], bh[4][4];
            #pragma unroll
            for (int mi = 0; mi < 4; mi++) {
                uint32_t ao = a_off + (uint32_t)(mi * 16 * SPITCH) * 2 + ko;
                LDSM4(ah[mi], st + 0 * MAT_BYTES + ao);
            }
            #pragma unroll
            for (int nj = 0; nj < 4; nj++) {
                uint32_t bo = b_off + (uint32_t)(nj * 16 * SPITCH) * 2 + ko;
                LDSM4(bh[nj], st + 1 * MAT_BYTES + bo);
            }
            #pragma unroll
            for (int mi = 0; mi < 4; mi++)
                #pragma unroll
                for (int ni = 0; ni < 8; ni++) {
                    uint32_t b0 = bh[ni >> 1][(ni & 1) * 2];
                    uint32_t b1 = bh[ni >> 1][(ni & 1) * 2 + 1];
                    MMA16816(acc[mi][ni], ah[mi], b0, b1);
                }
        }
    }

    // ---- epilogue: warp tile 64x64 ----
    const int r0 = wm * 64 + (lane >> 2);
    const int c0 = ncol0 + wn * 64 + (lane & 3) * 2;
    if (half_out) {
        __half* o = (__half*)ov;
        #pragma unroll
        for (int mi = 0; mi < 4; mi++)
            #pragma unroll
            for (int ni = 0; ni < 8; ni++) {
                size_t row = m0 + r0 + mi * 16;
                int col = c0 + ni * 8;
                *(uint32_t*)&o[row * DIMV + col] =
                    packh2(acc[mi][ni][0] * scale, acc[mi][ni][1] * scale);
                *(uint32_t*)&o[(row + 8) * DIMV + col] =
                    packh2(acc[mi][ni][2] * scale, acc[mi][ni][3] * scale);
            }
    } else {
        float* o = (float*)ov;
        #pragma unroll
        for (int mi = 0; mi < 4; mi++)
            #pragma unroll
            for (int ni = 0; ni < 8; ni++) {
                size_t row = m0 + r0 + mi * 16;
                int col = c0 + ni * 8;
                o[row * (size_t)pitch + col]           = acc[mi][ni][0] * scale;
                o[row * (size_t)pitch + col + 1]       = acc[mi][ni][1] * scale;
                o[(row + 8) * (size_t)pitch + col]     = acc[mi][ni][2] * scale;
                o[(row + 8) * (size_t)pitch + col + 1] = acc[mi][ni][3] * scale;
            }
    }
}

// ============ fused MMA attention: 1 window/CTA, 128 thr, warp = 16 rows ====
#define APITCH 264     // halves per row (256 + 8 pad): conflict-free LDSM
#define ATTN_HALVES (3 * 64 * APITCH + 64 * 66)
#define ATTN_SMEM   (ATTN_HALVES * 2 + (64 * 3 + 260) * 4)

__global__ void __launch_bounds__(128, 2) attn_mma(
    const __half* __restrict__ qv, const __half* __restrict__ kv,
    const __half* __restrict__ vv,
    const float* __restrict__ qd, const float* __restrict__ kd,
    const float* __restrict__ vd, const float* __restrict__ Wout,
    __half* __restrict__ Ah, float* __restrict__ out)
{
    extern __shared__ char sm[];
    __half* sq    = (__half*)sm;                 // [64][APITCH]
    __half* sk    = sq + 64 * APITCH;
    __half* sv    = sk + 64 * APITCH;
    __half* sgate = sv + 64 * APITCH;            // [64][66]
    float*  s_qd  = (float*)(sm + ATTN_HALVES * 2);
    float*  s_kd  = s_qd + 64;
    float*  s_vd  = s_kd + 64;
    float*  s_w   = s_vd + 64;                   // Wout[:,256], 257 floats

    const int tid  = threadIdx.x;
    const int lane = tid & 31;
    const int wid  = tid >> 5;
    const int g    = lane >> 2;
    const int tig  = lane & 3;
    const size_t r0 = (size_t)blockIdx.x * 64;

    const uint32_t sq_u = smem_u32(sq);
    const uint32_t sk_u = smem_u32(sk);
    const uint32_t sv_u = smem_u32(sv);

    // ---- cooperative load via cp.async (fire-and-forget, one wait) ----
    {
        const uint4* gq = (const uint4*)(qv + r0 * DIMV);
        const uint4* gk = (const uint4*)(kv + r0 * DIMV);
        const uint4* gv = (const uint4*)(vv + r0 * DIMV);
        for (int i = tid; i < 2048; i += 128) {
            int row = i >> 5, c = i & 31;            // 32 x 8 halves = 256/row
            uint32_t off = (uint32_t)(row * APITCH * 2 + c * 16);
            cp16(sq_u + off, gq + i);
            cp16(sk_u + off, gk + i);
            cp16(sv_u + off, gv + i);
        }
        CP_COMMIT();
        if (tid < 64) {
            s_qd[tid] = qd[r0 + tid];
            s_kd[tid] = kd[r0 + tid];
            s_vd[tid] = vd[r0 + tid];
        }
        for (int i = tid; i < 257; i += 128)
            s_w[i] = Wout[(size_t)i * D1 + 256];
        CP_WAIT(0);
    }
    __syncthreads();

    // ---- gate table (head-invariant): sigmoid(qd_i * kd_j), fp16 ----
    for (int i = tid; i < 4096; i += 128) {
        int ii = i >> 6, jj = i & 63;
        float z = s_qd[ii] * s_kd[jj];
        sgate[ii * 66 + jj] = __float2half_rn(1.f / (1.f + __expf(-z)));
    }
    __syncthreads();

    const int mrow = wid * 16;

    float ssum[8][4];
    #pragma unroll
    for (int ni = 0; ni < 8; ni++)
        #pragma unroll
        for (int k = 0; k < 4; k++) ssum[ni][k] = 0.f;
    float ds0 = 0.f, ds1 = 0.f;

    const uint32_t a_base = sq_u + (uint32_t)((mrow + (lane & 15)) * APITCH
                                              + ((lane >> 4) << 3)) * 2;
    const uint32_t b_rowoff = (uint32_t)((((lane >> 4) << 3) + (lane & 7)) * APITCH
                                         + (lane & 8)) * 2;
    const uint32_t v_base = sv_u + (uint32_t)((lane & 15) * APITCH) * 2;

    for (int h = 0; h < 8; h++) {
        const int kb = h * 32;
        // ---- S = Q K^T (64 cols, k=32) ----
        float acc[8][4];
        #pragma unroll
        for (int ni = 0; ni < 8; ni++)
            #pragma unroll
            for (int k = 0; k < 4; k++) acc[ni][k] = 0.f;
        #pragma unroll
        for (int ks = 0; ks < 2; ks++) {
            uint32_t a[4];
            LDSM4(a, a_base + (uint32_t)(kb + ks * 16) * 2);
            #pragma unroll
            for (int nt = 0; nt < 4; nt++) {
                uint32_t b[4];
                uint32_t baddr = sk_u + b_rowoff
                               + (uint32_t)(nt * 16 * APITCH + kb + ks * 16) * 2;
                LDSM4(b, baddr);
                MMA16816(acc[nt * 2],     a, b[0], b[1]);
                MMA16816(acc[nt * 2 + 1], a, b[2], b[3]);
            }
        }
        // ---- gate + ssum + row max ----
        float m0 = -1e30f, m1 = -1e30f;
        #pragma unroll
        for (int ni = 0; ni < 8; ni++) {
            int j0 = ni * 8 + tig * 2;
            __half2 gA = *(__half2*)&sgate[(mrow + g) * 66 + j0];
            __half2 gB = *(__half2*)&sgate[(mrow + g + 8) * 66 + j0];
            float2 fA = __half22float2(gA);
            float2 fB = __half22float2(gB);
            acc[ni][0] *= fA.x;  acc[ni][1] *= fA.y;
            acc[ni][2] *= fB.x;  acc[ni][3] *= fB.y;
            ssum[ni][0] += acc[ni][0]; ssum[ni][1] += acc[ni][1];
            ssum[ni][2] += acc[ni][2]; ssum[ni][3] += acc[ni][3];
            m0 = fmaxf(m0, fmaxf(acc[ni][0], acc[ni][1]));
            m1 = fmaxf(m1, fmaxf(acc[ni][2], acc[ni][3]));
        }
        m0 = fmaxf(m0, __shfl_xor_sync(0xffffffffu, m0, 1));
        m0 = fmaxf(m0, __shfl_xor_sync(0xffffffffu, m0, 2));
        m1 = fmaxf(m1, __shfl_xor_sync(0xffffffffu, m1, 1));
        m1 = fmaxf(m1, __shfl_xor_sync(0xffffffffu, m1, 2));
        // ---- exp + row sums ----
        float sum0 = 0.f, sum1 = 0.f;
        #pragma unroll
        for (int ni = 0; ni < 8; ni++) {
            acc[ni][0] = __expf(acc[ni][0] - m0);
            acc[ni][1] = __expf(acc[ni][1] - m0);
            acc[ni][2] = __expf(acc[ni][2] - m1);
            acc[ni][3] = __expf(acc[ni][3] - m1);
            sum0 += acc[ni][0] + acc[ni][1];
            sum1 += acc[ni][2] + acc[ni][3];
        }
        sum0 += __shfl_xor_sync(0xffffffffu, sum0, 1);
        sum0 += __shfl_xor_sync(0xffffffffu, sum0, 2);
        sum1 += __shfl_xor_sync(0xffffffffu, sum1, 1);
        sum1 += __shfl_xor_sync(0xffffffffu, sum1, 2);
        const float inv0 = 1.f / sum0, inv1 = 1.f / sum1;
        // ---- P fragments directly from accumulators (FA2 identity) ----
        uint32_t pa[4][4];
        #pragma unroll
        for (int t = 0; t < 4; t++) {
            pa[t][0] = packh2(acc[2*t][0]   * inv0, acc[2*t][1]   * inv0);
            pa[t][1] = packh2(acc[2*t][2]   * inv1, acc[2*t][3]   * inv1);
            pa[t][2] = packh2(acc[2*t+1][0] * inv0, acc[2*t+1][1] * inv0);
            pa[t][3] = packh2(acc[2*t+1][2] * inv1, acc[2*t+1][3] * inv1);
        }
        // ---- out = P @ V (k=64 tokens, n=32 dims) ----
        float oacc[4][4];
        #pragma unroll
        for (int nb = 0; nb < 4; nb++)
            #pragma unroll
            for (int k = 0; k < 4; k++) oacc[nb][k] = 0.f;
        #pragma unroll
        for (int t = 0; t < 4; t++) {
            #pragma unroll
            for (int nb = 0; nb < 4; nb++) {
                uint32_t b2[2];
                uint32_t vaddr = v_base
                               + (uint32_t)(t * 16 * APITCH + kb + nb * 8) * 2;
                LDSM2T(b2, vaddr);
                MMA16816(oacc[nb], pa[t], b2[0], b2[1]);
            }
        }
        // ---- write ov (fp16 into A matrix) + out[:,256] dot partials ----
        #pragma unroll
        for (int nb = 0; nb < 4; nb++) {
            int c0 = kb + nb * 8 + tig * 2;
            float w0 = s_w[c0], w1 = s_w[c0 + 1];
            ds0 += oacc[nb][0] * w0 + oacc[nb][1] * w1;
            ds1 += oacc[nb][2] * w0 + oacc[nb][3] * w1;
            *(uint32_t*)&Ah[(r0 + mrow + g) * KPAD + c0] =
                packh2(oacc[nb][0], oacc[nb][1]);
            *(uint32_t*)&Ah[(r0 + mrow + g + 8) * KPAD + c0] =
                packh2(oacc[nb][2], oacc[nb][3]);
        }
    }

    // ---- depth attention: softmax(ssum) . vd  (all in registers) ----
    float m0 = -1e30f, m1 = -1e30f;
    #pragma unroll
    for (int ni = 0; ni < 8; ni++) {
        m0 = fmaxf(m0, fmaxf(ssum[ni][0], ssum[ni][1]));
        m1 = fmaxf(m1, fmaxf(ssum[ni][2], ssum[ni][3]));
    }
    m0 = fmaxf(m0, __shfl_xor_sync(0xffffffffu, m0, 1));
    m0 = fmaxf(m0, __shfl_xor_sync(0xffffffffu, m0, 2));
    m1 = fmaxf(m1, __shfl_xor_sync(0xffffffffu, m1, 1));
    m1 = fmaxf(m1, __shfl_xor_sync(0xffffffffu, m1, 2));
    float se0 = 0.f, se1 = 0.f, av0 = 0.f, av1 = 0.f;
    #pragma unroll
    for (int ni = 0; ni < 8; ni++) {
        int j0 = ni * 8 + tig * 2;
        float v0 = s_vd[j0], v1 = s_vd[j0 + 1];
        float e0 = __expf(ssum[ni][0] - m0);
        float e1 = __expf(ssum[ni][1] - m0);
        float e2 = __expf(ssum[ni][2] - m1);
        float e3 = __expf(ssum[ni][3] - m1);
        se0 += e0 + e1;  av0 += e0 * v0 + e1 * v1;
        se1 += e2 + e3;  av1 += e2 * v0 + e3 * v1;
    }
    se0 += __shfl_xor_sync(0xffffffffu, se0, 1);
    se0 += __shfl_xor_sync(0xffffffffu, se0, 2);
    av0 += __shfl_xor_sync(0xffffffffu, av0, 1);
    av0 += __shfl_xor_sync(0xffffffffu, av0, 2);
    se1 += __shfl_xor_sync(0xffffffffu, se1, 1);
    se1 += __shfl_xor_sync(0xffffffffu, se1, 2);
    av1 += __shfl_xor_sync(0xffffffffu, av1, 1);
    av1 += __shfl_xor_sync(0xffffffffu, av1, 2);
    ds0 += __shfl_xor_sync(0xffffffffu, ds0, 1);
    ds0 += __shfl_xor_sync(0xffffffffu, ds0, 2);
    ds1 += __shfl_xor_sync(0xffffffffu, ds1, 1);
    ds1 += __shfl_xor_sync(0xffffffffu, ds1, 2);

    if (tig == 0) {
        float od0 = av0 / se0, od1 = av1 / se1;
        size_t ra = r0 + mrow + g, rb = ra + 8;
        Ah[ra * KPAD + 256] = __float2half_rn(od0);
        Ah[rb * KPAD + 256] = __float2half_rn(od1);
        out[ra * D1 + 256] = ds0 + od0 * s_w[256];
        out[rb * D1 + 256] = ds1 + od1 * s_w[256];
    }
}

// ---------------- launch -----------------------------------------------------
extern "C" void kernel_launch(void* const* d_in, const int* in_sizes, int n_in,
                              void* d_out, int out_size)
{
    const float* x    = (const float*)d_in[0];
    const float* Wqv  = (const float*)d_in[1];
    const float* Wkv  = (const float*)d_in[2];
    const float* Wvv  = (const float*)d_in[3];
    const float* Wqd  = (const float*)d_in[4];
    const float* Wkd  = (const float*)d_in[5];
    const float* Wvd  = (const float*)d_in[6];
    const float* Wout = (const float*)d_in[7];
    float* out = (float*)d_out;

    __half *Ah, *Bh, *BoH, *qvh, *kvh, *vvh;
    float *qd, *kd, *vd;
    cudaGetSymbolAddress((void**)&Ah,  g_Ah);
    cudaGetSymbolAddress((void**)&Bh,  g_Bh);
    cudaGetSymbolAddress((void**)&BoH, g_BoH);
    cudaGetSymbolAddress((void**)&qvh, g_qvh);
    cudaGetSymbolAddress((void**)&kvh, g_kvh);
    cudaGetSymbolAddress((void**)&vvh, g_vvh);
    cudaGetSymbolAddress((void**)&qd,  g_qd);
    cudaGetSymbolAddress((void**)&kd,  g_kd);
    cudaGetSymbolAddress((void**)&vd,  g_vd);

    cudaFuncSetAttribute(gemm_mma,
                         cudaFuncAttributeMaxDynamicSharedMemorySize, GEMM_SMEM);
    cudaFuncSetAttribute(attn_mma,
                         cudaFuncAttributeMaxDynamicSharedMemorySize, ATTN_SMEM);

    conv_w_qkv<<<768 * KPAD / 256, 256>>>(Wqv, Wkv, Wvv, Bh);
    conv_w_out<<<256 * KPAD / 256, 256>>>(Wout, BoH);
    conv_x_dproj<<<MROWS / 8, 256>>>(x, Wqd, Wkd, Wvd, Ah, qd, kd, vd);

    gemm_mma<<<dim3(6, MROWS / BM), 128, GEMM_SMEM>>>(
        Ah, Bh, qvh, kvh, vvh, SCALE, 1.f, 1.f, DIMV, 1);

    attn_mma<<<NWIN, 128, ATTN_SMEM>>>(qvh, kvh, vvh, qd, kd, vd, Wout, Ah, out);

    gemm_mma<<<dim3(2, MROWS / BM), 128, GEMM_SMEM>>>(
        Ah, BoH, out, out, out, 1.f, 1.f, 1.f, D1, 0);
}

// round 12
// speedup vs baseline: 5.6482x; 1.0010x over previous
#include <cuda_runtime.h>
#include <cuda_fp16.h>
#include <cstdint>
#include <math.h>

#define MROWS 131072        // 2048 windows * 64 tokens
#define NWIN  2048
#define D1    257
#define DIMV  256
#define KPAD  288           // 257 padded to 9 chunks of 32
#define KITERS 9
#define SCALE 0.17677669529663687f   // 32^-0.5

// ======================= scratch (device globals) ===========================
__device__ __align__(256) __half g_Ah[(size_t)MROWS * KPAD];
__device__ __align__(256) __half g_Bh[768 * KPAD];
__device__ __align__(256) __half g_BoH[256 * KPAD];
__device__ __align__(256) __half g_qvh[(size_t)MROWS * DIMV];
__device__ __align__(256) __half g_kvh[(size_t)MROWS * DIMV];
__device__ __align__(256) __half g_vvh[(size_t)MROWS * DIMV];
__device__ float g_qd[MROWS];
__device__ float g_kd[MROWS];
__device__ float g_vd[MROWS];

// ======================= PTX helpers =========================================
__device__ __forceinline__ uint32_t smem_u32(const void* p) {
    uint32_t a;
    asm("{ .reg .u64 t; cvta.to.shared.u64 t, %1; cvt.u32.u64 %0, t; }"
        : "=r"(a) : "l"(p));
    return a;
}
__device__ __forceinline__ void cp16(uint32_t s, const void* g) {
    asm volatile("cp.async.ca.shared.global [%0], [%1], 16;" :: "r"(s), "l"(g));
}
#define CP_COMMIT()  asm volatile("cp.async.commit_group;" ::: "memory")
#define CP_WAIT(n)   asm volatile("cp.async.wait_group %0;" :: "n"(n) : "memory")

#define LDSM4(r, addr) \
    asm volatile("ldmatrix.sync.aligned.m8n8.x4.shared.b16 {%0,%1,%2,%3}, [%4];" \
        : "=r"((r)[0]), "=r"((r)[1]), "=r"((r)[2]), "=r"((r)[3]) : "r"(addr))

#define LDSM2T(r, addr) \
    asm volatile("ldmatrix.sync.aligned.m8n8.x2.trans.shared.b16 {%0,%1}, [%2];" \
        : "=r"((r)[0]), "=r"((r)[1]) : "r"(addr))

#define MMA16816(c, a, b0v, b1v) \
    asm volatile("mma.sync.aligned.m16n8k16.row.col.f32.f16.f16.f32 " \
        "{%0,%1,%2,%3}, {%4,%5,%6,%7}, {%8,%9}, {%0,%1,%2,%3};" \
        : "+f"((c)[0]), "+f"((c)[1]), "+f"((c)[2]), "+f"((c)[3]) \
        : "r"((a)[0]), "r"((a)[1]), "r"((a)[2]), "r"((a)[3]), "r"(b0v), "r"(b1v))

__device__ __forceinline__ uint32_t packh2(float a, float b) {
    __half2 h = __floats2half2_rn(a, b);
    return *reinterpret_cast<uint32_t*>(&h);
}

// ============ conv_x + depth projections (warp per row) =====================
__global__ void __launch_bounds__(256) conv_x_dproj(
    const float* __restrict__ X,
    const float* __restrict__ Wq, const float* __restrict__ Wk,
    const float* __restrict__ Wv,
    __half* __restrict__ Ah,
    float* __restrict__ qd, float* __restrict__ kd, float* __restrict__ vd)
{
    const int warp = threadIdx.x >> 5;
    const int lane = threadIdx.x & 31;
    const size_t r = (size_t)blockIdx.x * 8 + warp;
    const float* xr = X + r * D1;
    float sq = 0.f, sk = 0.f, sv = 0.f;
    #pragma unroll
    for (int i = 0; i < 9; i++) {
        int c = lane + i * 32;
        float v = (c < D1) ? xr[c] : 0.f;
        Ah[r * KPAD + c] = __float2half_rn(v);
        if (c < D1) {
            sq = fmaf(v, Wq[c], sq);
            sk = fmaf(v, Wk[c], sk);
            sv = fmaf(v, Wv[c], sv);
        }
    }
    #pragma unroll
    for (int o = 16; o > 0; o >>= 1) {
        sq += __shfl_down_sync(0xffffffffu, sq, o);
        sk += __shfl_down_sync(0xffffffffu, sk, o);
        sv += __shfl_down_sync(0xffffffffu, sv, o);
    }
    if (lane == 0) { qd[r] = sq * SCALE; kd[r] = sk; vd[r] = sv; }
}

// ============ QKV weight transpose: B[n,k] = fp16(W[k, n%256]) ==============
__global__ void __launch_bounds__(256) conv_w_qkv(
    const float* __restrict__ Wqv, const float* __restrict__ Wkv,
    const float* __restrict__ Wvv, __half* __restrict__ Bh)
{
    int idx = blockIdx.x * 256 + threadIdx.x;   // 768*288 total
    int n = idx / KPAD, k = idx % KPAD;
    const float* W = (n < 256) ? Wqv : (n < 512) ? Wkv : Wvv;
    float v = (k < D1) ? W[(size_t)k * DIMV + (n & 255)] : 0.f;
    Bh[idx] = __float2half_rn(v);
}

// ============ Wout transpose: B[n,k] = fp16(Wout[k, n]) =====================
__global__ void __launch_bounds__(256) conv_w_out(
    const float* __restrict__ Wout, __half* __restrict__ Bh)
{
    int idx = blockIdx.x * 256 + threadIdx.x;   // 256*288 total
    int n = idx / KPAD, k = idx % KPAD;
    float v = (k < D1) ? Wout[(size_t)k * D1 + n] : 0.f;
    Bh[idx] = __float2half_rn(v);
}

// ============ fp16 HMMA GEMM: BM=BN=128 BK=32, 3-stage, 2x2 warps ===========
// 128 threads, 64x64 per warp: 8 LDSM4 per 32 MMAs (was 6 per 16) -> -33% LDS.
#define BM 128
#define BN 128
#define BK 32
#define SPITCH 40
#define MAT_BYTES (BM * SPITCH * 2)        // 10240
#define STAGE_BYTES (2 * MAT_BYTES)        // 20480
#define NSTAGE 3
#define GEMM_SMEM (NSTAGE * STAGE_BYTES)   // 61440

__global__ void __launch_bounds__(128, 2) gemm_mma(
    const __half* __restrict__ A, const __half* __restrict__ B,
    void* __restrict__ o0, void* __restrict__ o1, void* __restrict__ o2,
    float s0, float s1, float s2, int pitch, int half_out)
{
    extern __shared__ char sm[];
    const int tid  = threadIdx.x;
    const int lane = tid & 31;
    const int wid  = tid >> 5;
    const int wm   = wid >> 1;             // 0..1
    const int wn   = wid & 1;              // 0..1
    const int nblk = blockIdx.x;
    const size_t m0 = (size_t)blockIdx.y * BM;
    const int sel = nblk >> 1;
    void* ov = (sel == 0) ? o0 : (sel == 1) ? o1 : o2;
    const float scale = (sel == 0) ? s0 : (sel == 1) ? s1 : s2;
    const int ncol0 = (nblk & 1) * BN;
    const uint32_t sbase = smem_u32(sm);

    const __half* B_b = B + (size_t)nblk * BN * KPAD;

    // per-thread cp.async assignment (8 x 16B chunks / thread / stage)
    auto load_stage = [&](int it, int buf) {
        const int kc = it * BK;
        #pragma unroll
        for (int t = 0; t < 8; t++) {
            int id = tid + t * 128;
            int mat = id >> 9;
            int i = id & 511;
            int row = i >> 2, c = i & 3;
            const __half* g;
            if (mat == 0) g = A   + (m0 + row) * KPAD + kc + c * 8;
            else          g = B_b + (size_t)row * KPAD + kc + c * 8;
            uint32_t s = sbase + buf * STAGE_BYTES + mat * MAT_BYTES
                       + (uint32_t)(row * SPITCH + c * 8) * 2;
            cp16(s, g);
        }
        CP_COMMIT();
    };

    float acc[4][8][4];
    #pragma unroll
    for (int a = 0; a < 4; a++)
        #pragma unroll
        for (int b = 0; b < 8; b++)
            #pragma unroll
            for (int c = 0; c < 4; c++) acc[a][b][c] = 0.f;

    const uint32_t a_off = (uint32_t)((wm * 64 + (lane & 15)) * SPITCH
                                      + ((lane >> 4) << 3)) * 2;
    const uint32_t b_off = (uint32_t)((wn * 64 + ((lane >> 4) << 3) + (lane & 7)) * SPITCH
                                      + (lane & 8)) * 2;

    load_stage(0, 0);
    load_stage(1, 1);

    for (int it = 0; it < KITERS; ++it) {
        CP_WAIT(1);
        __syncthreads();
        if (it + 2 < KITERS) load_stage(it + 2, (it + 2) % NSTAGE);
        else CP_COMMIT();

        const uint32_t st = sbase + (it % NSTAGE) * STAGE_BYTES;
        const int nks = (it == KITERS - 1) ? 1 : 2;
        for (int ks = 0; ks < nks; ks++) {
            const uint32_t ko = ks * 32;
            uint32_t ah[4][4], bh[4][4];
            #pragma unroll
            for (int mi = 0; mi < 4; mi++) {
                uint32_t ao = a_off + (uint32_t)(mi * 16 * SPITCH) * 2 + ko;
                LDSM4(ah[mi], st + 0 * MAT_BYTES + ao);
            }
            #pragma unroll
            for (int nj = 0; nj < 4; nj++) {
                uint32_t bo = b_off + (uint32_t)(nj * 16 * SPITCH) * 2 + ko;
                LDSM4(bh[nj], st + 1 * MAT_BYTES + bo);
            }
            #pragma unroll
            for (int mi = 0; mi < 4; mi++)
                #pragma unroll
                for (int ni = 0; ni < 8; ni++) {
                    uint32_t b0 = bh[ni >> 1][(ni & 1) * 2];
                    uint32_t b1 = bh[ni >> 1][(ni & 1) * 2 + 1];
                    MMA16816(acc[mi][ni], ah[mi], b0, b1);
                }
        }
    }

    // ---- epilogue: warp tile 64x64 ----
    const int r0 = wm * 64 + (lane >> 2);
    const int c0 = ncol0 + wn * 64 + (lane & 3) * 2;
    if (half_out) {
        __half* o = (__half*)ov;
        #pragma unroll
        for (int mi = 0; mi < 4; mi++)
            #pragma unroll
            for (int ni = 0; ni < 8; ni++) {
                size_t row = m0 + r0 + mi * 16;
                int col = c0 + ni * 8;
                *(uint32_t*)&o[row * DIMV + col] =
                    packh2(acc[mi][ni][0] * scale, acc[mi][ni][1] * scale);
                *(uint32_t*)&o[(row + 8) * DIMV + col] =
                    packh2(acc[mi][ni][2] * scale, acc[mi][ni][3] * scale);
            }
    } else {
        float* o = (float*)ov;
        #pragma unroll
        for (int mi = 0; mi < 4; mi++)
            #pragma unroll
            for (int ni = 0; ni < 8; ni++) {
                size_t row = m0 + r0 + mi * 16;
                int col = c0 + ni * 8;
                o[row * (size_t)pitch + col]           = acc[mi][ni][0] * scale;
                o[row * (size_t)pitch + col + 1]       = acc[mi][ni][1] * scale;
                o[(row + 8) * (size_t)pitch + col]     = acc[mi][ni][2] * scale;
                o[(row + 8) * (size_t)pitch + col + 1] = acc[mi][ni][3] * scale;
            }
    }
}

// ============ fused MMA attention: 1 window/CTA, 128 thr, warp = 16 rows ====
#define APITCH 264     // halves per row (256 + 8 pad): conflict-free LDSM
#define ATTN_HALVES (3 * 64 * APITCH + 64 * 66)
#define ATTN_SMEM   (ATTN_HALVES * 2 + (64 * 3 + 260) * 4)

__global__ void __launch_bounds__(128, 2) attn_mma(
    const __half* __restrict__ qv, const __half* __restrict__ kv,
    const __half* __restrict__ vv,
    const float* __restrict__ qd, const float* __restrict__ kd,
    const float* __restrict__ vd, const float* __restrict__ Wout,
    __half* __restrict__ Ah, float* __restrict__ out)
{
    extern __shared__ char sm[];
    __half* sq    = (__half*)sm;                 // [64][APITCH]
    __half* sk    = sq + 64 * APITCH;
    __half* sv    = sk + 64 * APITCH;
    __half* sgate = sv + 64 * APITCH;            // [64][66]
    float*  s_qd  = (float*)(sm + ATTN_HALVES * 2);
    float*  s_kd  = s_qd + 64;
    float*  s_vd  = s_kd + 64;
    float*  s_w   = s_vd + 64;                   // Wout[:,256], 257 floats

    const int tid  = threadIdx.x;
    const int lane = tid & 31;
    const int wid  = tid >> 5;
    const int g    = lane >> 2;
    const int tig  = lane & 3;
    const size_t r0 = (size_t)blockIdx.x * 64;

    const uint32_t sq_u = smem_u32(sq);
    const uint32_t sk_u = smem_u32(sk);
    const uint32_t sv_u = smem_u32(sv);

    // ---- cooperative load via cp.async (fire-and-forget, one wait) ----
    {
        const uint4* gq = (const uint4*)(qv + r0 * DIMV);
        const uint4* gk = (const uint4*)(kv + r0 * DIMV);
        const uint4* gv = (const uint4*)(vv + r0 * DIMV);
        for (int i = tid; i < 2048; i += 128) {
            int row = i >> 5, c = i & 31;            // 32 x 8 halves = 256/row
            uint32_t off = (uint32_t)(row * APITCH * 2 + c * 16);
            cp16(sq_u + off, gq + i);
            cp16(sk_u + off, gk + i);
            cp16(sv_u + off, gv + i);
        }
        CP_COMMIT();
        if (tid < 64) {
            s_qd[tid] = qd[r0 + tid];
            s_kd[tid] = kd[r0 + tid];
            s_vd[tid] = vd[r0 + tid];
        }
        for (int i = tid; i < 257; i += 128)
            s_w[i] = Wout[(size_t)i * D1 + 256];
        CP_WAIT(0);
    }
    __syncthreads();

    // ---- gate table (head-invariant): sigmoid(qd_i * kd_j), fp16 ----
    for (int i = tid; i < 4096; i += 128) {
        int ii = i >> 6, jj = i & 63;
        float z = s_qd[ii] * s_kd[jj];
        sgate[ii * 66 + jj] = __float2half_rn(1.f / (1.f + __expf(-z)));
    }
    __syncthreads();

    const int mrow = wid * 16;

    float ssum[8][4];
    #pragma unroll
    for (int ni = 0; ni < 8; ni++)
        #pragma unroll
        for (int k = 0; k < 4; k++) ssum[ni][k] = 0.f;
    float ds0 = 0.f, ds1 = 0.f;

    const uint32_t a_base = sq_u + (uint32_t)((mrow + (lane & 15)) * APITCH
                                              + ((lane >> 4) << 3)) * 2;
    const uint32_t b_rowoff = (uint32_t)((((lane >> 4) << 3) + (lane & 7)) * APITCH
                                         + (lane & 8)) * 2;
    const uint32_t v_base = sv_u + (uint32_t)((lane & 15) * APITCH) * 2;

    for (int h = 0; h < 8; h++) {
        const int kb = h * 32;
        // ---- S = Q K^T (64 cols, k=32) ----
        float acc[8][4];
        #pragma unroll
        for (int ni = 0; ni < 8; ni++)
            #pragma unroll
            for (int k = 0; k < 4; k++) acc[ni][k] = 0.f;
        #pragma unroll
        for (int ks = 0; ks < 2; ks++) {
            uint32_t a[4];
            LDSM4(a, a_base + (uint32_t)(kb + ks * 16) * 2);
            #pragma unroll
            for (int nt = 0; nt < 4; nt++) {
                uint32_t b[4];
                uint32_t baddr = sk_u + b_rowoff
                               + (uint32_t)(nt * 16 * APITCH + kb + ks * 16) * 2;
                LDSM4(b, baddr);
                MMA16816(acc[nt * 2],     a, b[0], b[1]);
                MMA16816(acc[nt * 2 + 1], a, b[2], b[3]);
            }
        }
        // ---- gate + ssum + row max ----
        float m0 = -1e30f, m1 = -1e30f;
        #pragma unroll
        for (int ni = 0; ni < 8; ni++) {
            int j0 = ni * 8 + tig * 2;
            __half2 gA = *(__half2*)&sgate[(mrow + g) * 66 + j0];
            __half2 gB = *(__half2*)&sgate[(mrow + g + 8) * 66 + j0];
            float2 fA = __half22float2(gA);
            float2 fB = __half22float2(gB);
            acc[ni][0] *= fA.x;  acc[ni][1] *= fA.y;
            acc[ni][2] *= fB.x;  acc[ni][3] *= fB.y;
            ssum[ni][0] += acc[ni][0]; ssum[ni][1] += acc[ni][1];
            ssum[ni][2] += acc[ni][2]; ssum[ni][3] += acc[ni][3];
            m0 = fmaxf(m0, fmaxf(acc[ni][0], acc[ni][1]));
            m1 = fmaxf(m1, fmaxf(acc[ni][2], acc[ni][3]));
        }
        m0 = fmaxf(m0, __shfl_xor_sync(0xffffffffu, m0, 1));
        m0 = fmaxf(m0, __shfl_xor_sync(0xffffffffu, m0, 2));
        m1 = fmaxf(m1, __shfl_xor_sync(0xffffffffu, m1, 1));
        m1 = fmaxf(m1, __shfl_xor_sync(0xffffffffu, m1, 2));
        // ---- exp + row sums ----
        float sum0 = 0.f, sum1 = 0.f;
        #pragma unroll
        for (int ni = 0; ni < 8; ni++) {
            acc[ni][0] = __expf(acc[ni][0] - m0);
            acc[ni][1] = __expf(acc[ni][1] - m0);
            acc[ni][2] = __expf(acc[ni][2] - m1);
            acc[ni][3] = __expf(acc[ni][3] - m1);
            sum0 += acc[ni][0] + acc[ni][1];
            sum1 += acc[ni][2] + acc[ni][3];
        }
        sum0 += __shfl_xor_sync(0xffffffffu, sum0, 1);
        sum0 += __shfl_xor_sync(0xffffffffu, sum0, 2);
        sum1 += __shfl_xor_sync(0xffffffffu, sum1, 1);
        sum1 += __shfl_xor_sync(0xffffffffu, sum1, 2);
        const float inv0 = 1.f / sum0, inv1 = 1.f / sum1;
        // ---- P fragments directly from accumulators (FA2 identity) ----
        uint32_t pa[4][4];
        #pragma unroll
        for (int t = 0; t < 4; t++) {
            pa[t][0] = packh2(acc[2*t][0]   * inv0, acc[2*t][1]   * inv0);
            pa[t][1] = packh2(acc[2*t][2]   * inv1, acc[2*t][3]   * inv1);
            pa[t][2] = packh2(acc[2*t+1][0] * inv0, acc[2*t+1][1] * inv0);
            pa[t][3] = packh2(acc[2*t+1][2] * inv1, acc[2*t+1][3] * inv1);
        }
        // ---- out = P @ V (k=64 tokens, n=32 dims) ----
        float oacc[4][4];
        #pragma unroll
        for (int nb = 0; nb < 4; nb++)
            #pragma unroll
            for (int k = 0; k < 4; k++) oacc[nb][k] = 0.f;
        #pragma unroll
        for (int t = 0; t < 4; t++) {
            #pragma unroll
            for (int nb = 0; nb < 4; nb++) {
                uint32_t b2[2];
                uint32_t vaddr = v_base
                               + (uint32_t)(t * 16 * APITCH + kb + nb * 8) * 2;
                LDSM2T(b2, vaddr);
                MMA16816(oacc[nb], pa[t], b2[0], b2[1]);
            }
        }
        // ---- write ov (fp16 into A matrix) + out[:,256] dot partials ----
        #pragma unroll
        for (int nb = 0; nb < 4; nb++) {
            int c0 = kb + nb * 8 + tig * 2;
            float w0 = s_w[c0], w1 = s_w[c0 + 1];
            ds0 += oacc[nb][0] * w0 + oacc[nb][1] * w1;
            ds1 += oacc[nb][2] * w0 + oacc[nb][3] * w1;
            *(uint32_t*)&Ah[(r0 + mrow + g) * KPAD + c0] =
                packh2(oacc[nb][0], oacc[nb][1]);
            *(uint32_t*)&Ah[(r0 + mrow + g + 8) * KPAD + c0] =
                packh2(oacc[nb][2], oacc[nb][3]);
        }
    }

    // ---- depth attention: softmax(ssum) . vd  (all in registers) ----
    float m0 = -1e30f, m1 = -1e30f;
    #pragma unroll
    for (int ni = 0; ni < 8; ni++) {
        m0 = fmaxf(m0, fmaxf(ssum[ni][0], ssum[ni][1]));
        m1 = fmaxf(m1, fmaxf(ssum[ni][2], ssum[ni][3]));
    }
    m0 = fmaxf(m0, __shfl_xor_sync(0xffffffffu, m0, 1));
    m0 = fmaxf(m0, __shfl_xor_sync(0xffffffffu, m0, 2));
    m1 = fmaxf(m1, __shfl_xor_sync(0xffffffffu, m1, 1));
    m1 = fmaxf(m1, __shfl_xor_sync(0xffffffffu, m1, 2));
    float se0 = 0.f, se1 = 0.f, av0 = 0.f, av1 = 0.f;
    #pragma unroll
    for (int ni = 0; ni < 8; ni++) {
        int j0 = ni * 8 + tig * 2;
        float v0 = s_vd[j0], v1 = s_vd[j0 + 1];
        float e0 = __expf(ssum[ni][0] - m0);
        float e1 = __expf(ssum[ni][1] - m0);
        float e2 = __expf(ssum[ni][2] - m1);
        float e3 = __expf(ssum[ni][3] - m1);
        se0 += e0 + e1;  av0 += e0 * v0 + e1 * v1;
        se1 += e2 + e3;  av1 += e2 * v0 + e3 * v1;
    }
    se0 += __shfl_xor_sync(0xffffffffu, se0, 1);
    se0 += __shfl_xor_sync(0xffffffffu, se0, 2);
    av0 += __shfl_xor_sync(0xffffffffu, av0, 1);
    av0 += __shfl_xor_sync(0xffffffffu, av0, 2);
    se1 += __shfl_xor_sync(0xffffffffu, se1, 1);
    se1 += __shfl_xor_sync(0xffffffffu, se1, 2);
    av1 += __shfl_xor_sync(0xffffffffu, av1, 1);
    av1 += __shfl_xor_sync(0xffffffffu, av1, 2);
    ds0 += __shfl_xor_sync(0xffffffffu, ds0, 1);
    ds0 += __shfl_xor_sync(0xffffffffu, ds0, 2);
    ds1 += __shfl_xor_sync(0xffffffffu, ds1, 1);
    ds1 += __shfl_xor_sync(0xffffffffu, ds1, 2);

    if (tig == 0) {
        float od0 = av0 / se0, od1 = av1 / se1;
        size_t ra = r0 + mrow + g, rb = ra + 8;
        Ah[ra * KPAD + 256] = __float2half_rn(od0);
        Ah[rb * KPAD + 256] = __float2half_rn(od1);
        out[ra * D1 + 256] = ds0 + od0 * s_w[256];
        out[rb * D1 + 256] = ds1 + od1 * s_w[256];
    }
}

// ---------------- launch -----------------------------------------------------
extern "C" void kernel_launch(void* const* d_in, const int* in_sizes, int n_in,
                              void* d_out, int out_size)
{
    const float* x    = (const float*)d_in[0];
    const float* Wqv  = (const float*)d_in[1];
    const float* Wkv  = (const float*)d_in[2];
    const float* Wvv  = (const float*)d_in[3];
    const float* Wqd  = (const float*)d_in[4];
    const float* Wkd  = (const float*)d_in[5];
    const float* Wvd  = (const float*)d_in[6];
    const float* Wout = (const float*)d_in[7];
    float* out = (float*)d_out;

    __half *Ah, *Bh, *BoH, *qvh, *kvh, *vvh;
    float *qd, *kd, *vd;
    cudaGetSymbolAddress((void**)&Ah,  g_Ah);
    cudaGetSymbolAddress((void**)&Bh,  g_Bh);
    cudaGetSymbolAddress((void**)&BoH, g_BoH);
    cudaGetSymbolAddress((void**)&qvh, g_qvh);
    cudaGetSymbolAddress((void**)&kvh, g_kvh);
    cudaGetSymbolAddress((void**)&vvh, g_vvh);
    cudaGetSymbolAddress((void**)&qd,  g_qd);
    cudaGetSymbolAddress((void**)&kd,  g_kd);
    cudaGetSymbolAddress((void**)&vd,  g_vd);

    cudaFuncSetAttribute(gemm_mma,
                         cudaFuncAttributeMaxDynamicSharedMemorySize, GEMM_SMEM);
    cudaFuncSetAttribute(attn_mma,
                         cudaFuncAttributeMaxDynamicSharedMemorySize, ATTN_SMEM);

    conv_w_qkv<<<768 * KPAD / 256, 256>>>(Wqv, Wkv, Wvv, Bh);
    conv_w_out<<<256 * KPAD / 256, 256>>>(Wout, BoH);
    conv_x_dproj<<<MROWS / 8, 256>>>(x, Wqd, Wkd, Wvd, Ah, qd, kd, vd);

    gemm_mma<<<dim3(6, MROWS / BM), 128, GEMM_SMEM>>>(
        Ah, Bh, qvh, kvh, vvh, SCALE, 1.f, 1.f, DIMV, 1);

    attn_mma<<<NWIN, 128, ATTN_SMEM>>>(qvh, kvh, vvh, qd, kd, vd, Wout, Ah, out);

    gemm_mma<<<dim3(2, MROWS / BM), 128, GEMM_SMEM>>>(
        Ah, BoH, out, out, out, 1.f, 1.f, 1.f, D1, 0);
}

// round 13
// speedup vs baseline: 5.6489x; 1.0001x over previous
#include <cuda_runtime.h>
#include <cuda_fp16.h>
#include <cstdint>
#include <math.h>

#define MROWS 131072        // 2048 windows * 64 tokens
#define NWIN  2048
#define D1    257
#define DIMV  256
#define KPAD  288           // 257 padded to 9 chunks of 32
#define KITERS 9
#define SCALE 0.17677669529663687f   // 32^-0.5

// ======================= scratch (device globals) ===========================
__device__ __align__(256) __half g_Ah[(size_t)MROWS * KPAD];
__device__ __align__(256) __half g_Bh[768 * KPAD];
__device__ __align__(256) __half g_BoH[256 * KPAD];
__device__ __align__(256) __half g_qvh[(size_t)MROWS * DIMV];
__device__ __align__(256) __half g_kvh[(size_t)MROWS * DIMV];
__device__ __align__(256) __half g_vvh[(size_t)MROWS * DIMV];
__device__ float g_qd[MROWS];
__device__ float g_kd[MROWS];
__device__ float g_vd[MROWS];

// ======================= PTX helpers =========================================
__device__ __forceinline__ uint32_t smem_u32(const void* p) {
    uint32_t a;
    asm("{ .reg .u64 t; cvta.to.shared.u64 t, %1; cvt.u32.u64 %0, t; }"
        : "=r"(a) : "l"(p));
    return a;
}
__device__ __forceinline__ void cp16(uint32_t s, const void* g) {
    asm volatile("cp.async.ca.shared.global [%0], [%1], 16;" :: "r"(s), "l"(g));
}
#define CP_COMMIT()  asm volatile("cp.async.commit_group;" ::: "memory")
#define CP_WAIT(n)   asm volatile("cp.async.wait_group %0;" :: "n"(n) : "memory")

#define LDSM4(r, addr) \
    asm volatile("ldmatrix.sync.aligned.m8n8.x4.shared.b16 {%0,%1,%2,%3}, [%4];" \
        : "=r"((r)[0]), "=r"((r)[1]), "=r"((r)[2]), "=r"((r)[3]) : "r"(addr))

#define LDSM2T(r, addr) \
    asm volatile("ldmatrix.sync.aligned.m8n8.x2.trans.shared.b16 {%0,%1}, [%2];" \
        : "=r"((r)[0]), "=r"((r)[1]) : "r"(addr))

#define MMA16816(c, a, b0v, b1v) \
    asm volatile("mma.sync.aligned.m16n8k16.row.col.f32.f16.f16.f32 " \
        "{%0,%1,%2,%3}, {%4,%5,%6,%7}, {%8,%9}, {%0,%1,%2,%3};" \
        : "+f"((c)[0]), "+f"((c)[1]), "+f"((c)[2]), "+f"((c)[3]) \
        : "r"((a)[0]), "r"((a)[1]), "r"((a)[2]), "r"((a)[3]), "r"(b0v), "r"(b1v))

__device__ __forceinline__ uint32_t packh2(float a, float b) {
    __half2 h = __floats2half2_rn(a, b);
    return *reinterpret_cast<uint32_t*>(&h);
}

// ============ conv_x + depth projections (warp per row) =====================
__global__ void __launch_bounds__(256) conv_x_dproj(
    const float* __restrict__ X,
    const float* __restrict__ Wq, const float* __restrict__ Wk,
    const float* __restrict__ Wv,
    __half* __restrict__ Ah,
    float* __restrict__ qd, float* __restrict__ kd, float* __restrict__ vd)
{
    const int warp = threadIdx.x >> 5;
    const int lane = threadIdx.x & 31;
    const size_t r = (size_t)blockIdx.x * 8 + warp;
    const float* xr = X + r * D1;
    float sq = 0.f, sk = 0.f, sv = 0.f;
    #pragma unroll
    for (int i = 0; i < 9; i++) {
        int c = lane + i * 32;
        float v = (c < D1) ? xr[c] : 0.f;
        Ah[r * KPAD + c] = __float2half_rn(v);
        if (c < D1) {
            sq = fmaf(v, Wq[c], sq);
            sk = fmaf(v, Wk[c], sk);
            sv = fmaf(v, Wv[c], sv);
        }
    }
    #pragma unroll
    for (int o = 16; o > 0; o >>= 1) {
        sq += __shfl_down_sync(0xffffffffu, sq, o);
        sk += __shfl_down_sync(0xffffffffu, sk, o);
        sv += __shfl_down_sync(0xffffffffu, sv, o);
    }
    if (lane == 0) { qd[r] = sq * SCALE; kd[r] = sk; vd[r] = sv; }
}

// ============ QKV weight transpose: B[n,k] = fp16(W[k, n%256]) ==============
__global__ void __launch_bounds__(256) conv_w_qkv(
    const float* __restrict__ Wqv, const float* __restrict__ Wkv,
    const float* __restrict__ Wvv, __half* __restrict__ Bh)
{
    int idx = blockIdx.x * 256 + threadIdx.x;   // 768*288 total
    int n = idx / KPAD, k = idx % KPAD;
    const float* W = (n < 256) ? Wqv : (n < 512) ? Wkv : Wvv;
    float v = (k < D1) ? W[(size_t)k * DIMV + (n & 255)] : 0.f;
    Bh[idx] = __float2half_rn(v);
}

// ============ Wout transpose: B[n,k] = fp16(Wout[k, n]) =====================
__global__ void __launch_bounds__(256) conv_w_out(
    const float* __restrict__ Wout, __half* __restrict__ Bh)
{
    int idx = blockIdx.x * 256 + threadIdx.x;   // 256*288 total
    int n = idx / KPAD, k = idx % KPAD;
    float v = (k < D1) ? Wout[(size_t)k * D1 + n] : 0.f;
    Bh[idx] = __float2half_rn(v);
}

// ============ fp16 HMMA GEMM: BM=BN=128 BK=32, 3-stage, 2x2 warps ===========
// 128 threads, 64x64 per warp: 8 LDSM4 per 32 MMAs (was 6 per 16) -> -33% LDS.
#define BM 128
#define BN 128
#define BK 32
#define SPITCH 40
#define MAT_BYTES (BM * SPITCH * 2)        // 10240
#define STAGE_BYTES (2 * MAT_BYTES)        // 20480
#define NSTAGE 3
#define GEMM_SMEM (NSTAGE * STAGE_BYTES)   // 61440

__global__ void __launch_bounds__(128, 2) gemm_mma(
    const __half* __restrict__ A, const __half* __restrict__ B,
    void* __restrict__ o0, void* __restrict__ o1, void* __restrict__ o2,
    float s0, float s1, float s2, int pitch, int half_out)
{
    extern __shared__ char sm[];
    const int tid  = threadIdx.x;
    const int lane = tid & 31;
    const int wid  = tid >> 5;
    const int wm   = wid >> 1;             // 0..1
    const int wn   = wid & 1;              // 0..1
    const int nblk = blockIdx.x;
    const size_t m0 = (size_t)blockIdx.y * BM;
    const int sel = nblk >> 1;
    void* ov = (sel == 0) ? o0 : (sel == 1) ? o1 : o2;
    const float scale = (sel == 0) ? s0 : (sel == 1) ? s1 : s2;
    const int ncol0 = (nblk & 1) * BN;
    const uint32_t sbase = smem_u32(sm);

    const __half* B_b = B + (size_t)nblk * BN * KPAD;

    // per-thread cp.async assignment (8 x 16B chunks / thread / stage)
    auto load_stage = [&](int it, int buf) {
        const int kc = it * BK;
        #pragma unroll
        for (int t = 0; t < 8; t++) {
            int id = tid + t * 128;
            int mat = id >> 9;
            int i = id & 511;
            int row = i >> 2, c = i & 3;
            const __half* g;
            if (mat == 0) g = A   + (m0 + row) * KPAD + kc + c * 8;
            else          g = B_b + (size_t)row * KPAD + kc + c * 8;
            uint32_t s = sbase + buf * STAGE_BYTES + mat * MAT_BYTES
                       + (uint32_t)(row * SPITCH + c * 8) * 2;
            cp16(s, g);
        }
        CP_COMMIT();
    };

    float acc[4][8][4];
    #pragma unroll
    for (int a = 0; a < 4; a++)
        #pragma unroll
        for (int b = 0; b < 8; b++)
            #pragma unroll
            for (int c = 0; c < 4; c++) acc[a][b][c] = 0.f;

    const uint32_t a_off = (uint32_t)((wm * 64 + (lane & 15)) * SPITCH
                                      + ((lane >> 4) << 3)) * 2;
    const uint32_t b_off = (uint32_t)((wn * 64 + ((lane >> 4) << 3) + (lane & 7)) * SPITCH
                                      + (lane & 8)) * 2;

    load_stage(0, 0);
    load_stage(1, 1);

    for (int it = 0; it < KITERS; ++it) {
        CP_WAIT(1);
        __syncthreads();
        if (it + 2 < KITERS) load_stage(it + 2, (it + 2) % NSTAGE);
        else CP_COMMIT();

        const uint32_t st = sbase + (it % NSTAGE) * STAGE_BYTES;
        const int nks = (it == KITERS - 1) ? 1 : 2;
        for (int ks = 0; ks < nks; ks++) {
            const uint32_t ko = ks * 32;
            uint32_t ah[4][4], bh[4][4];
            #pragma unroll
            for (int mi = 0; mi < 4; mi++) {
                uint32_t ao = a_off + (uint32_t)(mi * 16 * SPITCH) * 2 + ko;
                LDSM4(ah[mi], st + 0 * MAT_BYTES + ao);
            }
            #pragma unroll
            for (int nj = 0; nj < 4; nj++) {
                uint32_t bo = b_off + (uint32_t)(nj * 16 * SPITCH) * 2 + ko;
                LDSM4(bh[nj], st + 1 * MAT_BYTES + bo);
            }
            #pragma unroll
            for (int mi = 0; mi < 4; mi++)
                #pragma unroll
                for (int ni = 0; ni < 8; ni++) {
                    uint32_t b0 = bh[ni >> 1][(ni & 1) * 2];
                    uint32_t b1 = bh[ni >> 1][(ni & 1) * 2 + 1];
                    MMA16816(acc[mi][ni], ah[mi], b0, b1);
                }
        }
    }

    // ---- epilogue: warp tile 64x64 ----
    const int r0 = wm * 64 + (lane >> 2);
    const int c0 = ncol0 + wn * 64 + (lane & 3) * 2;
    if (half_out) {
        __half* o = (__half*)ov;
        #pragma unroll
        for (int mi = 0; mi < 4; mi++)
            #pragma unroll
            for (int ni = 0; ni < 8; ni++) {
                size_t row = m0 + r0 + mi * 16;
                int col = c0 + ni * 8;
                *(uint32_t*)&o[row * DIMV + col] =
                    packh2(acc[mi][ni][0] * scale, acc[mi][ni][1] * scale);
                *(uint32_t*)&o[(row + 8) * DIMV + col] =
                    packh2(acc[mi][ni][2] * scale, acc[mi][ni][3] * scale);
            }
    } else {
        float* o = (float*)ov;
        #pragma unroll
        for (int mi = 0; mi < 4; mi++)
            #pragma unroll
            for (int ni = 0; ni < 8; ni++) {
                size_t row = m0 + r0 + mi * 16;
                int col = c0 + ni * 8;
                o[row * (size_t)pitch + col]           = acc[mi][ni][0] * scale;
                o[row * (size_t)pitch + col + 1]       = acc[mi][ni][1] * scale;
                o[(row + 8) * (size_t)pitch + col]     = acc[mi][ni][2] * scale;
                o[(row + 8) * (size_t)pitch + col + 1] = acc[mi][ni][3] * scale;
            }
    }
}

// ============ fused MMA attention: 1 window/CTA, 128 thr, warp = 16 rows ====
#define APITCH 264     // halves per row (256 + 8 pad): conflict-free LDSM
#define ATTN_HALVES (3 * 64 * APITCH + 64 * 66)
#define ATTN_SMEM   (ATTN_HALVES * 2 + (64 * 3 + 260) * 4)

__global__ void __launch_bounds__(128, 2) attn_mma(
    const __half* __restrict__ qv, const __half* __restrict__ kv,
    const __half* __restrict__ vv,
    const float* __restrict__ qd, const float* __restrict__ kd,
    const float* __restrict__ vd, const float* __restrict__ Wout,
    __half* __restrict__ Ah, float* __restrict__ out)
{
    extern __shared__ char sm[];
    __half* sq    = (__half*)sm;                 // [64][APITCH]
    __half* sk    = sq + 64 * APITCH;
    __half* sv    = sk + 64 * APITCH;
    __half* sgate = sv + 64 * APITCH;            // [64][66]
    float*  s_qd  = (float*)(sm + ATTN_HALVES * 2);
    float*  s_kd  = s_qd + 64;
    float*  s_vd  = s_kd + 64;
    float*  s_w   = s_vd + 64;                   // Wout[:,256], 257 floats

    const int tid  = threadIdx.x;
    const int lane = tid & 31;
    const int wid  = tid >> 5;
    const int g    = lane >> 2;
    const int tig  = lane & 3;
    const size_t r0 = (size_t)blockIdx.x * 64;

    const uint32_t sq_u = smem_u32(sq);
    const uint32_t sk_u = smem_u32(sk);
    const uint32_t sv_u = smem_u32(sv);

    // ---- cooperative load via cp.async (fire-and-forget, one wait) ----
    {
        const uint4* gq = (const uint4*)(qv + r0 * DIMV);
        const uint4* gk = (const uint4*)(kv + r0 * DIMV);
        const uint4* gv = (const uint4*)(vv + r0 * DIMV);
        for (int i = tid; i < 2048; i += 128) {
            int row = i >> 5, c = i & 31;            // 32 x 8 halves = 256/row
            uint32_t off = (uint32_t)(row * APITCH * 2 + c * 16);
            cp16(sq_u + off, gq + i);
            cp16(sk_u + off, gk + i);
            cp16(sv_u + off, gv + i);
        }
        CP_COMMIT();
        if (tid < 64) {
            s_qd[tid] = qd[r0 + tid];
            s_kd[tid] = kd[r0 + tid];
            s_vd[tid] = vd[r0 + tid];
        }
        for (int i = tid; i < 257; i += 128)
            s_w[i] = Wout[(size_t)i * D1 + 256];
        CP_WAIT(0);
    }
    __syncthreads();

    // ---- gate table (head-invariant): sigmoid(qd_i * kd_j), fp16 ----
    for (int i = tid; i < 4096; i += 128) {
        int ii = i >> 6, jj = i & 63;
        float z = s_qd[ii] * s_kd[jj];
        sgate[ii * 66 + jj] = __float2half_rn(1.f / (1.f + __expf(-z)));
    }
    __syncthreads();

    const int mrow = wid * 16;

    float ssum[8][4];
    #pragma unroll
    for (int ni = 0; ni < 8; ni++)
        #pragma unroll
        for (int k = 0; k < 4; k++) ssum[ni][k] = 0.f;
    float ds0 = 0.f, ds1 = 0.f;

    const uint32_t a_base = sq_u + (uint32_t)((mrow + (lane & 15)) * APITCH
                                              + ((lane >> 4) << 3)) * 2;
    const uint32_t b_rowoff = (uint32_t)((((lane >> 4) << 3) + (lane & 7)) * APITCH
                                         + (lane & 8)) * 2;
    const uint32_t v_base = sv_u + (uint32_t)((lane & 15) * APITCH) * 2;

    for (int h = 0; h < 8; h++) {
        const int kb = h * 32;
        // ---- S = Q K^T (64 cols, k=32) ----
        float acc[8][4];
        #pragma unroll
        for (int ni = 0; ni < 8; ni++)
            #pragma unroll
            for (int k = 0; k < 4; k++) acc[ni][k] = 0.f;
        #pragma unroll
        for (int ks = 0; ks < 2; ks++) {
            uint32_t a[4];
            LDSM4(a, a_base + (uint32_t)(kb + ks * 16) * 2);
            #pragma unroll
            for (int nt = 0; nt < 4; nt++) {
                uint32_t b[4];
                uint32_t baddr = sk_u + b_rowoff
                               + (uint32_t)(nt * 16 * APITCH + kb + ks * 16) * 2;
                LDSM4(b, baddr);
                MMA16816(acc[nt * 2],     a, b[0], b[1]);
                MMA16816(acc[nt * 2 + 1], a, b[2], b[3]);
            }
        }
        // ---- gate + ssum + row max ----
        float m0 = -1e30f, m1 = -1e30f;
        #pragma unroll
        for (int ni = 0; ni < 8; ni++) {
            int j0 = ni * 8 + tig * 2;
            __half2 gA = *(__half2*)&sgate[(mrow + g) * 66 + j0];
            __half2 gB = *(__half2*)&sgate[(mrow + g + 8) * 66 + j0];
            float2 fA = __half22float2(gA);
            float2 fB = __half22float2(gB);
            acc[ni][0] *= fA.x;  acc[ni][1] *= fA.y;
            acc[ni][2] *= fB.x;  acc[ni][3] *= fB.y;
            ssum[ni][0] += acc[ni][0]; ssum[ni][1] += acc[ni][1];
            ssum[ni][2] += acc[ni][2]; ssum[ni][3] += acc[ni][3];
            m0 = fmaxf(m0, fmaxf(acc[ni][0], acc[ni][1]));
            m1 = fmaxf(m1, fmaxf(acc[ni][2], acc[ni][3]));
        }
        m0 = fmaxf(m0, __shfl_xor_sync(0xffffffffu, m0, 1));
        m0 = fmaxf(m0, __shfl_xor_sync(0xffffffffu, m0, 2));
        m1 = fmaxf(m1, __shfl_xor_sync(0xffffffffu, m1, 1));
        m1 = fmaxf(m1, __shfl_xor_sync(0xffffffffu, m1, 2));
        // ---- exp + row sums ----
        float sum0 = 0.f, sum1 = 0.f;
        #pragma unroll
        for (int ni = 0; ni < 8; ni++) {
            acc[ni][0] = __expf(acc[ni][0] - m0);
            acc[ni][1] = __expf(acc[ni][1] - m0);
            acc[ni][2] = __expf(acc[ni][2] - m1);
            acc[ni][3] = __expf(acc[ni][3] - m1);
            sum0 += acc[ni][0] + acc[ni][1];
            sum1 += acc[ni][2] + acc[ni][3];
        }
        sum0 += __shfl_xor_sync(0xffffffffu, sum0, 1);
        sum0 += __shfl_xor_sync(0xffffffffu, sum0, 2);
        sum1 += __shfl_xor_sync(0xffffffffu, sum1, 1);
        sum1 += __shfl_xor_sync(0xffffffffu, sum1, 2);
        const float inv0 = 1.f / sum0, inv1 = 1.f / sum1;
        // ---- P fragments directly from accumulators (FA2 identity) ----
        uint32_t pa[4][4];
        #pragma unroll
        for (int t = 0; t < 4; t++) {
            pa[t][0] = packh2(acc[2*t][0]   * inv0, acc[2*t][1]   * inv0);
            pa[t][1] = packh2(acc[2*t][2]   * inv1, acc[2*t][3]   * inv1);
            pa[t][2] = packh2(acc[2*t+1][0] * inv0, acc[2*t+1][1] * inv0);
            pa[t][3] = packh2(acc[2*t+1][2] * inv1, acc[2*t+1][3] * inv1);
        }
        // ---- out = P @ V (k=64 tokens, n=32 dims) ----
        float oacc[4][4];
        #pragma unroll
        for (int nb = 0; nb < 4; nb++)
            #pragma unroll
            for (int k = 0; k < 4; k++) oacc[nb][k] = 0.f;
        #pragma unroll
        for (int t = 0; t < 4; t++) {
            #pragma unroll
            for (int nb = 0; nb < 4; nb++) {
                uint32_t b2[2];
                uint32_t vaddr = v_base
                               + (uint32_t)(t * 16 * APITCH + kb + nb * 8) * 2;
                LDSM2T(b2, vaddr);
                MMA16816(oacc[nb], pa[t], b2[0], b2[1]);
            }
        }
        // ---- write ov (fp16 into A matrix) + out[:,256] dot partials ----
        #pragma unroll
        for (int nb = 0; nb < 4; nb++) {
            int c0 = kb + nb * 8 + tig * 2;
            float w0 = s_w[c0], w1 = s_w[c0 + 1];
            ds0 += oacc[nb][0] * w0 + oacc[nb][1] * w1;
            ds1 += oacc[nb][2] * w0 + oacc[nb][3] * w1;
            *(uint32_t*)&Ah[(r0 + mrow + g) * KPAD + c0] =
                packh2(oacc[nb][0], oacc[nb][1]);
            *(uint32_t*)&Ah[(r0 + mrow + g + 8) * KPAD + c0] =
                packh2(oacc[nb][2], oacc[nb][3]);
        }
    }

    // ---- depth attention: softmax(ssum) . vd  (all in registers) ----
    float m0 = -1e30f, m1 = -1e30f;
    #pragma unroll
    for (int ni = 0; ni < 8; ni++) {
        m0 = fmaxf(m0, fmaxf(ssum[ni][0], ssum[ni][1]));
        m1 = fmaxf(m1, fmaxf(ssum[ni][2], ssum[ni][3]));
    }
    m0 = fmaxf(m0, __shfl_xor_sync(0xffffffffu, m0, 1));
    m0 = fmaxf(m0, __shfl_xor_sync(0xffffffffu, m0, 2));
    m1 = fmaxf(m1, __shfl_xor_sync(0xffffffffu, m1, 1));
    m1 = fmaxf(m1, __shfl_xor_sync(0xffffffffu, m1, 2));
    float se0 = 0.f, se1 = 0.f, av0 = 0.f, av1 = 0.f;
    #pragma unroll
    for (int ni = 0; ni < 8; ni++) {
        int j0 = ni * 8 + tig * 2;
        float v0 = s_vd[j0], v1 = s_vd[j0 + 1];
        float e0 = __expf(ssum[ni][0] - m0);
        float e1 = __expf(ssum[ni][1] - m0);
        float e2 = __expf(ssum[ni][2] - m1);
        float e3 = __expf(ssum[ni][3] - m1);
        se0 += e0 + e1;  av0 += e0 * v0 + e1 * v1;
        se1 += e2 + e3;  av1 += e2 * v0 + e3 * v1;
    }
    se0 += __shfl_xor_sync(0xffffffffu, se0, 1);
    se0 += __shfl_xor_sync(0xffffffffu, se0, 2);
    av0 += __shfl_xor_sync(0xffffffffu, av0, 1);
    av0 += __shfl_xor_sync(0xffffffffu, av0, 2);
    se1 += __shfl_xor_sync(0xffffffffu, se1, 1);
    se1 += __shfl_xor_sync(0xffffffffu, se1, 2);
    av1 += __shfl_xor_sync(0xffffffffu, av1, 1);
    av1 += __shfl_xor_sync(0xffffffffu, av1, 2);
    ds0 += __shfl_xor_sync(0xffffffffu, ds0, 1);
    ds0 += __shfl_xor_sync(0xffffffffu, ds0, 2);
    ds1 += __shfl_xor_sync(0xffffffffu, ds1, 1);
    ds1 += __shfl_xor_sync(0xffffffffu, ds1, 2);

    if (tig == 0) {
        float od0 = av0 / se0, od1 = av1 / se1;
        size_t ra = r0 + mrow + g, rb = ra + 8;
        Ah[ra * KPAD + 256] = __float2half_rn(od0);
        Ah[rb * KPAD + 256] = __float2half_rn(od1);
        out[ra * D1 + 256] = ds0 + od0 * s_w[256];
        out[rb * D1 + 256] = ds1 + od1 * s_w[256];
    }
}

// ---------------- launch -----------------------------------------------------
extern "C" void kernel_launch(void* const* d_in, const int* in_sizes, int n_in,
                              void* d_out, int out_size)
{
    const float* x    = (const float*)d_in[0];
    const float* Wqv  = (const float*)d_in[1];
    const float* Wkv  = (const float*)d_in[2];
    const float* Wvv  = (const float*)d_in[3];
    const float* Wqd  = (const float*)d_in[4];
    const float* Wkd  = (const float*)d_in[5];
    const float* Wvd  = (const float*)d_in[6];
    const float* Wout = (const float*)d_in[7];
    float* out = (float*)d_out;

    __half *Ah, *Bh, *BoH, *qvh, *kvh, *vvh;
    float *qd, *kd, *vd;
    cudaGetSymbolAddress((void**)&Ah,  g_Ah);
    cudaGetSymbolAddress((void**)&Bh,  g_Bh);
    cudaGetSymbolAddress((void**)&BoH, g_BoH);
    cudaGetSymbolAddress((void**)&qvh, g_qvh);
    cudaGetSymbolAddress((void**)&kvh, g_kvh);
    cudaGetSymbolAddress((void**)&vvh, g_vvh);
    cudaGetSymbolAddress((void**)&qd,  g_qd);
    cudaGetSymbolAddress((void**)&kd,  g_kd);
    cudaGetSymbolAddress((void**)&vd,  g_vd);

    cudaFuncSetAttribute(gemm_mma,
                         cudaFuncAttributeMaxDynamicSharedMemorySize, GEMM_SMEM);
    cudaFuncSetAttribute(attn_mma,
                         cudaFuncAttributeMaxDynamicSharedMemorySize, ATTN_SMEM);

    conv_w_qkv<<<768 * KPAD / 256, 256>>>(Wqv, Wkv, Wvv, Bh);
    conv_w_out<<<256 * KPAD / 256, 256>>>(Wout, BoH);
    conv_x_dproj<<<MROWS / 8, 256>>>(x, Wqd, Wkd, Wvd, Ah, qd, kd, vd);

    gemm_mma<<<dim3(6, MROWS / BM), 128, GEMM_SMEM>>>(
        Ah, Bh, qvh, kvh, vvh, SCALE, 1.f, 1.f, DIMV, 1);

    attn_mma<<<NWIN, 128, ATTN_SMEM>>>(qvh, kvh, vvh, qd, kd, vd, Wout, Ah, out);

    gemm_mma<<<dim3(2, MROWS / BM), 128, GEMM_SMEM>>>(
        Ah, BoH, out, out, out, 1.f, 1.f, 1.f, D1, 0);
}